// round 1
// baseline (speedup 1.0000x reference)
#include <cuda_runtime.h>
#include <cuda_bf16.h>
#include <math.h>

#define IN_DIM 164
#define HID    512
#define G4H    2048
#define BATCH  1024
#define MAXLEN 128
#define MAXT   (BATCH * (MAXLEN - 1))   // 130048 max ragged tokens

// ---------------- scratch (static device globals; no allocation) ------------
__device__ float g_x1[(long)MAXT * HID];     // encoder layer1 out
__device__ float g_x2[(long)MAXT * HID];     // encoder layer2 out
__device__ float g_xp[(long)MAXT * G4H];     // input projection x@Wih^T (ragged)
__device__ float g_G [(long)BATCH * G4H];    // per-step h@Whh^T
__device__ float g_h [(long)BATCH * HID];
__device__ float g_c [(long)BATCH * HID];
__device__ float g_r0[(long)BATCH * HID];
__device__ float g_r1[(long)BATCH * HID];
__device__ int   g_starts[BATCH];

// ---------------- exclusive prefix sum of segment sizes --------------------
__global__ void scan_starts_kernel(const int* __restrict__ sizes, int* __restrict__ starts) {
    __shared__ int s[BATCH];
    int t = threadIdx.x;
    s[t] = sizes[t];
    __syncthreads();
    for (int off = 1; off < BATCH; off <<= 1) {
        int v = (t >= off) ? s[t - off] : 0;
        __syncthreads();
        s[t] += v;
        __syncthreads();
    }
    starts[t] = s[t] - sizes[t];
}

// ---------------- zero h, c -------------------------------------------------
__global__ void init_hc_kernel(float* __restrict__ h, float* __restrict__ c) {
    int i = blockIdx.x * blockDim.x + threadIdx.x;
    if (i < BATCH * HID) { h[i] = 0.f; c[i] = 0.f; }
}

// ---------------- generic SGEMM: C = act(A[M,K] @ W[N,K]^T + bias) (+resid) -
// BM=BN=64, BK=16, 256 threads, 4x4 per thread.
template<bool RELU, bool RESID, bool BIAS>
__global__ __launch_bounds__(256)
void sgemm_nt(const float* __restrict__ A, const float* __restrict__ W,
              const float* __restrict__ bias, const float* __restrict__ R,
              float* __restrict__ C, int M, int N, int K)
{
    constexpr int BM = 64, BN = 64, BK = 16;
    __shared__ float As[BK][BM];
    __shared__ float Bs[BK][BN];

    const int tid  = threadIdx.x;
    const int brow = blockIdx.y * BM;
    const int bcol = blockIdx.x * BN;
    const int tr = (tid / 16) * 4;     // row in tile
    const int tc = (tid % 16) * 4;     // col in tile
    const int lr = tid / 4;            // loader row 0..63
    const int lc = (tid % 4) * 4;      // loader k-offset 0,4,8,12

    float acc[4][4] = {};

    for (int k0 = 0; k0 < K; k0 += BK) {
        // ---- load A tile ----
        {
            int ar = brow + lr;
            if (ar < M && (k0 + lc + 3) < K) {
                float4 v = *reinterpret_cast<const float4*>(&A[(long)ar * K + k0 + lc]);
                As[lc + 0][lr] = v.x; As[lc + 1][lr] = v.y;
                As[lc + 2][lr] = v.z; As[lc + 3][lr] = v.w;
            } else {
                #pragma unroll
                for (int i = 0; i < 4; i++) {
                    int kk = k0 + lc + i;
                    As[lc + i][lr] = (ar < M && kk < K) ? A[(long)ar * K + kk] : 0.f;
                }
            }
        }
        // ---- load W tile ----
        {
            int wr = bcol + lr;
            if (wr < N && (k0 + lc + 3) < K) {
                float4 v = *reinterpret_cast<const float4*>(&W[(long)wr * K + k0 + lc]);
                Bs[lc + 0][lr] = v.x; Bs[lc + 1][lr] = v.y;
                Bs[lc + 2][lr] = v.z; Bs[lc + 3][lr] = v.w;
            } else {
                #pragma unroll
                for (int i = 0; i < 4; i++) {
                    int kk = k0 + lc + i;
                    Bs[lc + i][lr] = (wr < N && kk < K) ? W[(long)wr * K + kk] : 0.f;
                }
            }
        }
        __syncthreads();

        #pragma unroll
        for (int kk = 0; kk < BK; kk++) {
            float a[4], b[4];
            #pragma unroll
            for (int i = 0; i < 4; i++) a[i] = As[kk][tr + i];
            #pragma unroll
            for (int j = 0; j < 4; j++) b[j] = Bs[kk][tc + j];
            #pragma unroll
            for (int i = 0; i < 4; i++)
                #pragma unroll
                for (int j = 0; j < 4; j++)
                    acc[i][j] = fmaf(a[i], b[j], acc[i][j]);
        }
        __syncthreads();
    }

    #pragma unroll
    for (int i = 0; i < 4; i++) {
        int r = brow + tr + i;
        if (r >= M) continue;
        #pragma unroll
        for (int j = 0; j < 4; j++) {
            int cidx = bcol + tc + j;
            if (cidx >= N) continue;
            float v = acc[i][j];
            if (BIAS)  v += bias[cidx];
            if (RELU)  v = fmaxf(v, 0.f);
            if (RESID) v += R[(long)r * N + cidx];
            C[(long)r * N + cidx] = v;
        }
    }
}

// ---------------- LSTM gate update ------------------------------------------
__device__ __forceinline__ float sigf(float x) { return 1.f / (1.f + expf(-x)); }

__global__ __launch_bounds__(HID)
void lstm_gates_kernel(const float* __restrict__ G, const float* __restrict__ Xp,
                       const int* __restrict__ sizes, const int* __restrict__ starts,
                       const float* __restrict__ bih, const float* __restrict__ bhh,
                       float* __restrict__ h, float* __restrict__ c, int t)
{
    const int b = blockIdx.x;
    const int j = threadIdx.x;
    const long gb = (long)b * G4H;

    float gi = G[gb +            j] + bih[j]            + bhh[j];
    float gf = G[gb + HID      + j] + bih[HID + j]      + bhh[HID + j];
    float gg = G[gb + 2 * HID  + j] + bih[2 * HID + j]  + bhh[2 * HID + j];
    float go = G[gb + 3 * HID  + j] + bih[3 * HID + j]  + bhh[3 * HID + j];

    if (t < sizes[b]) {
        const long xr = (long)(starts[b] + t) * G4H;
        gi += Xp[xr + j];
        gf += Xp[xr + HID + j];
        gg += Xp[xr + 2 * HID + j];
        go += Xp[xr + 3 * HID + j];
    }

    const long hi = (long)b * HID + j;
    float cc = sigf(gf) * c[hi] + sigf(gi) * tanhf(gg);
    c[hi] = cc;
    h[hi] = sigf(go) * tanhf(cc);
}

// ---------------- decoder: out[b] = dot(X[b,:], Wd) + bd --------------------
__global__ __launch_bounds__(128)
void decoder_kernel(const float* __restrict__ X, const float* __restrict__ Wd,
                    const float* __restrict__ bd, float* __restrict__ out)
{
    const int b = blockIdx.x;
    const int t = threadIdx.x;
    float s = 0.f;
    #pragma unroll
    for (int j = t; j < HID; j += 128) s += X[(long)b * HID + j] * Wd[j];
    s += __shfl_down_sync(0xffffffffu, s, 16);
    s += __shfl_down_sync(0xffffffffu, s, 8);
    s += __shfl_down_sync(0xffffffffu, s, 4);
    s += __shfl_down_sync(0xffffffffu, s, 2);
    s += __shfl_down_sync(0xffffffffu, s, 1);
    __shared__ float sh[4];
    if ((t & 31) == 0) sh[t >> 5] = s;
    __syncthreads();
    if (t == 0) out[b] = sh[0] + sh[1] + sh[2] + sh[3] + bd[0];
}

// ---------------- host launcher ---------------------------------------------
static inline dim3 gemm_grid(int M, int N) {
    return dim3((N + 63) / 64, (M + 63) / 64);
}

extern "C" void kernel_launch(void* const* d_in, const int* in_sizes, int n_in,
                              void* d_out, int out_size)
{
    const int*   sizes = (const int*)  d_in[0];
    const float* feat  = (const float*)d_in[1];
    const float* We0   = (const float*)d_in[2];
    const float* be0   = (const float*)d_in[3];
    const float* We1   = (const float*)d_in[4];
    const float* be1   = (const float*)d_in[5];
    const float* Wih   = (const float*)d_in[6];
    const float* bih   = (const float*)d_in[7];
    const float* Whh   = (const float*)d_in[8];
    const float* bhh   = (const float*)d_in[9];
    const float* Wl0   = (const float*)d_in[10];
    const float* bl0   = (const float*)d_in[11];
    const float* Wl1   = (const float*)d_in[12];
    const float* bl1   = (const float*)d_in[13];
    const float* Wd    = (const float*)d_in[14];
    const float* bd    = (const float*)d_in[15];
    float* out = (float*)d_out;

    const int T = in_sizes[1] / IN_DIM;

    float *x1, *x2, *xp, *G, *h, *c, *r0, *r1;
    int* starts;
    cudaGetSymbolAddress((void**)&x1, g_x1);
    cudaGetSymbolAddress((void**)&x2, g_x2);
    cudaGetSymbolAddress((void**)&xp, g_xp);
    cudaGetSymbolAddress((void**)&G,  g_G);
    cudaGetSymbolAddress((void**)&h,  g_h);
    cudaGetSymbolAddress((void**)&c,  g_c);
    cudaGetSymbolAddress((void**)&r0, g_r0);
    cudaGetSymbolAddress((void**)&r1, g_r1);
    cudaGetSymbolAddress((void**)&starts, g_starts);

    scan_starts_kernel<<<1, BATCH>>>(sizes, starts);
    init_hc_kernel<<<(BATCH * HID + 255) / 256, 256>>>(h, c);

    // encoder MLP
    sgemm_nt<true, false, true><<<gemm_grid(T, HID), 256>>>(feat, We0, be0, nullptr, x1, T, HID, IN_DIM);
    sgemm_nt<true, false, true><<<gemm_grid(T, HID), 256>>>(x1,   We1, be1, nullptr, x2, T, HID, HID);

    // input projection for all ragged tokens: xp = x2 @ Wih^T (no bias)
    sgemm_nt<false, false, false><<<gemm_grid(T, G4H), 256>>>(x2, Wih, nullptr, nullptr, xp, T, G4H, HID);

    // LSTM recurrence over MAX_LEN steps
    for (int t = 0; t < MAXLEN; t++) {
        sgemm_nt<false, false, false><<<gemm_grid(BATCH, G4H), 256>>>(h, Whh, nullptr, nullptr, G, BATCH, G4H, HID);
        lstm_gates_kernel<<<BATCH, HID>>>(G, xp, sizes, starts, bih, bhh, h, c, t);
    }

    // residual MLPs
    sgemm_nt<true, true, true><<<gemm_grid(BATCH, HID), 256>>>(h,  Wl0, bl0, h,  r0, BATCH, HID, HID);
    sgemm_nt<true, true, true><<<gemm_grid(BATCH, HID), 256>>>(r0, Wl1, bl1, r0, r1, BATCH, HID, HID);

    // decoder
    decoder_kernel<<<BATCH, 128>>>(r1, Wd, bd, out);

    (void)n_in; (void)out_size;
}

// round 3
// speedup vs baseline: 2.8960x; 2.8960x over previous
#include <cuda_runtime.h>
#include <cuda_bf16.h>
#include <math.h>
#include <stdint.h>

#define IN_DIM 164
#define KP0    192          // IN_DIM zero-padded to multiple of 64
#define HID    512
#define G4H    2048
#define BATCH  1024
#define MAXLEN 128
#define MAXT   (BATCH * (MAXLEN - 1))   // 130048 max ragged tokens

// ===================== scratch (static device globals) ======================
__device__ __nv_bfloat16 g_fhi[(long)MAXT * KP0];
__device__ __nv_bfloat16 g_flo[(long)MAXT * KP0];
__device__ __nv_bfloat16 g_x1hi[(long)MAXT * HID];
__device__ __nv_bfloat16 g_x1lo[(long)MAXT * HID];
__device__ __nv_bfloat16 g_x2hi[(long)MAXT * HID];
__device__ __nv_bfloat16 g_x2lo[(long)MAXT * HID];
__device__ float         g_xp[(long)MAXT * G4H];
__device__ __nv_bfloat16 g_we0hi[HID * KP0], g_we0lo[HID * KP0];
__device__ __nv_bfloat16 g_we1hi[HID * HID], g_we1lo[HID * HID];
__device__ __nv_bfloat16 g_wihhi[G4H * HID], g_wihlo[G4H * HID];
__device__ __nv_bfloat16 g_whhhi[G4H * HID], g_whhlo[G4H * HID];
__device__ float         g_G[(long)BATCH * G4H];
__device__ float         g_h[(long)BATCH * HID];
__device__ float         g_c[(long)BATCH * HID];
__device__ __nv_bfloat16 g_hhi[BATCH * HID], g_hlo[BATCH * HID];
__device__ float         g_r0[(long)BATCH * HID];
__device__ float         g_r1[(long)BATCH * HID];
__device__ int           g_starts[BATCH];

// ===================== PTX helpers ==========================================
__device__ __forceinline__ uint32_t smem_u32(const void* p) {
    uint32_t a;
    asm("{ .reg .u64 t; cvta.to.shared.u64 t, %1; cvt.u32.u64 %0, t; }" : "=r"(a) : "l"(p));
    return a;
}
__device__ __forceinline__ void cp16(uint32_t dst, const void* src, int sz) {
    asm volatile("cp.async.cg.shared.global [%0], [%1], 16, %2;"
                 :: "r"(dst), "l"(src), "r"(sz));
}
__device__ __forceinline__ void cp_commit() {
    asm volatile("cp.async.commit_group;" ::: "memory");
}
#define CP_WAIT(n) asm volatile("cp.async.wait_group %0;" :: "n"(n) : "memory")

#define LDSM_X4(r, addr) \
    asm volatile("ldmatrix.sync.aligned.m8n8.x4.shared.b16 {%0,%1,%2,%3}, [%4];" \
        : "=r"((r)[0]), "=r"((r)[1]), "=r"((r)[2]), "=r"((r)[3]) : "r"(addr))

#define MMA16816(d, a, b0, b1) \
    asm volatile("mma.sync.aligned.m16n8k16.row.col.f32.bf16.bf16.f32 " \
        "{%0,%1,%2,%3}, {%4,%5,%6,%7}, {%8,%9}, {%0,%1,%2,%3};" \
        : "+f"((d)[0]), "+f"((d)[1]), "+f"((d)[2]), "+f"((d)[3]) \
        : "r"((a)[0]), "r"((a)[1]), "r"((a)[2]), "r"((a)[3]), "r"(b0), "r"(b1))

#define SWZ128(b) ((b) ^ (((b) >> 3) & 0x70))

// ===================== small kernels ========================================
__global__ void scan_starts_kernel(const int* __restrict__ sizes, int* __restrict__ starts) {
    __shared__ int s[BATCH];
    int t = threadIdx.x;
    s[t] = sizes[t];
    __syncthreads();
    for (int off = 1; off < BATCH; off <<= 1) {
        int v = (t >= off) ? s[t - off] : 0;
        __syncthreads();
        s[t] += v;
        __syncthreads();
    }
    starts[t] = s[t] - sizes[t];
}

__global__ void init_hc_kernel(float* __restrict__ h, float* __restrict__ c,
                               __nv_bfloat16* __restrict__ hhi, __nv_bfloat16* __restrict__ hlo) {
    int i = blockIdx.x * blockDim.x + threadIdx.x;
    if (i < BATCH * HID) {
        h[i] = 0.f; c[i] = 0.f;
        hhi[i] = __float2bfloat16(0.f); hlo[i] = __float2bfloat16(0.f);
    }
}

// fp32 [M,K] -> bf16 hi/lo [M,Kp] with zero padding for c >= K
__global__ void convert_pad_kernel(const float* __restrict__ X,
                                   __nv_bfloat16* __restrict__ hi, __nv_bfloat16* __restrict__ lo,
                                   int M, int K, int Kp) {
    long i = (long)blockIdx.x * blockDim.x + threadIdx.x;
    if (i >= (long)M * Kp) return;
    int r = (int)(i / Kp), cidx = (int)(i % Kp);
    float v = (cidx < K) ? X[(long)r * K + cidx] : 0.f;
    __nv_bfloat16 h = __float2bfloat16(v);
    hi[i] = h;
    lo[i] = __float2bfloat16(v - __bfloat162float(h));
}

// ===================== bf16-split tensor GEMM (mma.sync) ====================
// C[M,N] = epi( (Ahi+Alo)[M,K] @ (Bhi+Blo)[N,K]^T ), dropping Alo*Blo.
// CTA tile 128x128, BK=64, double-buffered cp.async, 8 warps (warp tile 32x64).
// EPI 0: fp32 C. EPI 1: bias+relu -> bf16 hi/lo.
#define STAGE_BYTES 65536
#define OFF_AHI 0
#define OFF_ALO 16384
#define OFF_BHI 32768
#define OFF_BLO 49152
#define MM_SMEM (2 * STAGE_BYTES)

template<int EPI>
__global__ __launch_bounds__(256, 1)
void mm_mma(const __nv_bfloat16* __restrict__ Ahi, const __nv_bfloat16* __restrict__ Alo,
            const __nv_bfloat16* __restrict__ Bhi, const __nv_bfloat16* __restrict__ Blo,
            const float* __restrict__ bias,
            float* __restrict__ Cf, __nv_bfloat16* __restrict__ Chi, __nv_bfloat16* __restrict__ Clo,
            int M, int N, int K)
{
    extern __shared__ char smem[];
    const uint32_t sb = smem_u32(smem);

    const int tid  = threadIdx.x;
    const int wid  = tid >> 5;
    const int lane = tid & 31;
    const int warp_m = wid & 3;    // 4 warps along M (32 rows each)
    const int warp_n = wid >> 2;   // 2 warps along N (64 cols each)

    const int m0 = blockIdx.y * 128;
    const int n0 = blockIdx.x * 128;
    const int nk = K >> 6;

    // ---- loader mapping: thread t -> row t/2, 4 consecutive 16B chunks ----
    const int lrow = tid >> 1;
    const int qb = (tid & 1) * 4;
    const int arow = m0 + lrow;
    const int asz = (arow < M) ? 16 : 0;
    const long abase = (long)((arow < M) ? arow : (M - 1)) * K;
    const long bbase = (long)(n0 + lrow) * K;

    uint32_t sw_dst[4];
    #pragma unroll
    for (int i = 0; i < 4; i++)
        sw_dst[i] = (uint32_t)SWZ128(lrow * 128 + (qb + i) * 16);

    // ---- prefetch stage 0 ----
    {
        const long ka = abase, kb = bbase;
        #pragma unroll
        for (int i = 0; i < 4; i++) {
            const int q = qb + i;
            const uint32_t d = sb + sw_dst[i];
            cp16(d + OFF_AHI, Ahi + ka + q * 8, asz);
            cp16(d + OFF_ALO, Alo + ka + q * 8, asz);
            cp16(d + OFF_BHI, Bhi + kb + q * 8, 16);
            cp16(d + OFF_BLO, Blo + kb + q * 8, 16);
        }
        cp_commit();
    }

    float acc[2][8][4];
    #pragma unroll
    for (int a = 0; a < 2; a++)
        #pragma unroll
        for (int b = 0; b < 8; b++)
            #pragma unroll
            for (int cidx = 0; cidx < 4; cidx++) acc[a][b][cidx] = 0.f;

    // ---- precomputed ldmatrix lane address components ----
    const int a_row = warp_m * 32 + (lane & 15);       // + mf*16
    const int a_kq  = (lane >> 4) * 16;                 // k-byte half select
    const int b_row = warp_n * 64 + (lane & 7) + ((lane >> 4) << 3); // + p*16
    const int b_kq  = ((lane >> 3) & 1) * 16;

    for (int it = 0; it < nk; ++it) {
        const uint32_t cur = sb + (uint32_t)((it & 1) * STAGE_BYTES);

        if (it + 1 < nk) {
            const uint32_t nxt = sb + (uint32_t)(((it + 1) & 1) * STAGE_BYTES);
            const long ka = abase + (long)(it + 1) * 64;
            const long kb = bbase + (long)(it + 1) * 64;
            #pragma unroll
            for (int i = 0; i < 4; i++) {
                const int q = qb + i;
                const uint32_t d = nxt + sw_dst[i];
                cp16(d + OFF_AHI, Ahi + ka + q * 8, asz);
                cp16(d + OFF_ALO, Alo + ka + q * 8, asz);
                cp16(d + OFF_BHI, Bhi + kb + q * 8, 16);
                cp16(d + OFF_BLO, Blo + kb + q * 8, 16);
            }
            cp_commit();
            CP_WAIT(1);
        } else {
            CP_WAIT(0);
        }
        __syncthreads();

        #pragma unroll
        for (int ks = 0; ks < 4; ks++) {
            const int kbyte = ks * 32;
            uint32_t ah[2][4], al[2][4], bh[4][4], bl[4][4];

            #pragma unroll
            for (int mf = 0; mf < 2; mf++) {
                const uint32_t ab = (uint32_t)SWZ128((a_row + mf * 16) * 128 + kbyte + a_kq);
                LDSM_X4(ah[mf], cur + OFF_AHI + ab);
                LDSM_X4(al[mf], cur + OFF_ALO + ab);
            }
            #pragma unroll
            for (int p = 0; p < 4; p++) {
                const uint32_t bb = (uint32_t)SWZ128((b_row + p * 16) * 128 + kbyte + b_kq);
                LDSM_X4(bh[p], cur + OFF_BHI + bb);
                LDSM_X4(bl[p], cur + OFF_BLO + bb);
            }

            #pragma unroll
            for (int mf = 0; mf < 2; mf++) {
                #pragma unroll
                for (int p = 0; p < 4; p++) {
                    MMA16816(acc[mf][2 * p],     ah[mf], bh[p][0], bh[p][1]);
                    MMA16816(acc[mf][2 * p + 1], ah[mf], bh[p][2], bh[p][3]);
                    MMA16816(acc[mf][2 * p],     ah[mf], bl[p][0], bl[p][1]);
                    MMA16816(acc[mf][2 * p + 1], ah[mf], bl[p][2], bl[p][3]);
                    MMA16816(acc[mf][2 * p],     al[mf], bh[p][0], bh[p][1]);
                    MMA16816(acc[mf][2 * p + 1], al[mf], bh[p][2], bh[p][3]);
                }
            }
        }
        __syncthreads();
    }

    // ---- epilogue ----
    const int g  = lane >> 2;
    const int tg = lane & 3;
    #pragma unroll
    for (int mf = 0; mf < 2; mf++) {
        const int r_base = m0 + warp_m * 32 + mf * 16 + g;
        #pragma unroll
        for (int ng = 0; ng < 8; ng++) {
            const int col = n0 + warp_n * 64 + ng * 8 + tg * 2;
            if (EPI == 0) {
                if (r_base < M) {
                    float2 v0 = make_float2(acc[mf][ng][0], acc[mf][ng][1]);
                    *(float2*)(Cf + (long)r_base * N + col) = v0;
                }
                if (r_base + 8 < M) {
                    float2 v1 = make_float2(acc[mf][ng][2], acc[mf][ng][3]);
                    *(float2*)(Cf + (long)(r_base + 8) * N + col) = v1;
                }
            } else {
                const float b0 = bias[col], b1 = bias[col + 1];
                #pragma unroll
                for (int half = 0; half < 2; half++) {
                    const int r = r_base + half * 8;
                    if (r >= M) continue;
                    float v0 = fmaxf(acc[mf][ng][2 * half]     + b0, 0.f);
                    float v1 = fmaxf(acc[mf][ng][2 * half + 1] + b1, 0.f);
                    __nv_bfloat162 h2 = __floats2bfloat162_rn(v0, v1);
                    float r0 = v0 - __bfloat162float(h2.x);
                    float r1 = v1 - __bfloat162float(h2.y);
                    __nv_bfloat162 l2 = __floats2bfloat162_rn(r0, r1);
                    *(uint32_t*)(Chi + (long)r * N + col) = *(uint32_t*)&h2;
                    *(uint32_t*)(Clo + (long)r * N + col) = *(uint32_t*)&l2;
                }
            }
        }
    }
}

// ===================== fp32 SGEMM (small tail layers) =======================
template<bool RELU, bool RESID, bool BIAS>
__global__ __launch_bounds__(256)
void sgemm_nt(const float* __restrict__ A, const float* __restrict__ W,
              const float* __restrict__ bias, const float* __restrict__ R,
              float* __restrict__ C, int M, int N, int K)
{
    constexpr int BM = 64, BN = 64, BK = 16;
    __shared__ float As[BK][BM];
    __shared__ float Bs[BK][BN];
    const int tid = threadIdx.x;
    const int brow = blockIdx.y * BM;
    const int bcol = blockIdx.x * BN;
    const int tr = (tid / 16) * 4;
    const int tc = (tid % 16) * 4;
    const int lr = tid / 4;
    const int lc = (tid % 4) * 4;
    float acc[4][4] = {};
    for (int k0 = 0; k0 < K; k0 += BK) {
        {
            int ar = brow + lr;
            if (ar < M && (k0 + lc + 3) < K) {
                float4 v = *reinterpret_cast<const float4*>(&A[(long)ar * K + k0 + lc]);
                As[lc + 0][lr] = v.x; As[lc + 1][lr] = v.y; As[lc + 2][lr] = v.z; As[lc + 3][lr] = v.w;
            } else {
                #pragma unroll
                for (int i = 0; i < 4; i++) {
                    int kk = k0 + lc + i;
                    As[lc + i][lr] = (ar < M && kk < K) ? A[(long)ar * K + kk] : 0.f;
                }
            }
        }
        {
            int wr = bcol + lr;
            if (wr < N && (k0 + lc + 3) < K) {
                float4 v = *reinterpret_cast<const float4*>(&W[(long)wr * K + k0 + lc]);
                Bs[lc + 0][lr] = v.x; Bs[lc + 1][lr] = v.y; Bs[lc + 2][lr] = v.z; Bs[lc + 3][lr] = v.w;
            } else {
                #pragma unroll
                for (int i = 0; i < 4; i++) {
                    int kk = k0 + lc + i;
                    Bs[lc + i][lr] = (wr < N && kk < K) ? W[(long)wr * K + kk] : 0.f;
                }
            }
        }
        __syncthreads();
        #pragma unroll
        for (int kk = 0; kk < BK; kk++) {
            float a[4], b[4];
            #pragma unroll
            for (int i = 0; i < 4; i++) a[i] = As[kk][tr + i];
            #pragma unroll
            for (int j = 0; j < 4; j++) b[j] = Bs[kk][tc + j];
            #pragma unroll
            for (int i = 0; i < 4; i++)
                #pragma unroll
                for (int j = 0; j < 4; j++)
                    acc[i][j] = fmaf(a[i], b[j], acc[i][j]);
        }
        __syncthreads();
    }
    #pragma unroll
    for (int i = 0; i < 4; i++) {
        int r = brow + tr + i;
        if (r >= M) continue;
        #pragma unroll
        for (int j = 0; j < 4; j++) {
            int cidx = bcol + tc + j;
            if (cidx >= N) continue;
            float v = acc[i][j];
            if (BIAS)  v += bias[cidx];
            if (RELU)  v = fmaxf(v, 0.f);
            if (RESID) v += R[(long)r * N + cidx];
            C[(long)r * N + cidx] = v;
        }
    }
}

// ===================== LSTM gates ===========================================
__device__ __forceinline__ float sigf(float x) { return 1.f / (1.f + expf(-x)); }

__global__ __launch_bounds__(HID)
void lstm_gates_kernel(const float* __restrict__ G, const float* __restrict__ Xp,
                       const int* __restrict__ sizes, const int* __restrict__ starts,
                       const float* __restrict__ bih, const float* __restrict__ bhh,
                       float* __restrict__ h, float* __restrict__ c,
                       __nv_bfloat16* __restrict__ hhi, __nv_bfloat16* __restrict__ hlo, int t)
{
    const int b = blockIdx.x;
    const int j = threadIdx.x;
    const long gb = (long)b * G4H;

    float gi = G[gb +           j] + bih[j]           + bhh[j];
    float gf = G[gb + HID     + j] + bih[HID + j]     + bhh[HID + j];
    float gg = G[gb + 2 * HID + j] + bih[2 * HID + j] + bhh[2 * HID + j];
    float go = G[gb + 3 * HID + j] + bih[3 * HID + j] + bhh[3 * HID + j];

    if (t < sizes[b]) {
        const long xr = (long)(starts[b] + t) * G4H;
        gi += Xp[xr + j];
        gf += Xp[xr + HID + j];
        gg += Xp[xr + 2 * HID + j];
        go += Xp[xr + 3 * HID + j];
    }

    const long hix = (long)b * HID + j;
    float cc = sigf(gf) * c[hix] + sigf(gi) * tanhf(gg);
    c[hix] = cc;
    float hv = sigf(go) * tanhf(cc);
    h[hix] = hv;
    __nv_bfloat16 hh = __float2bfloat16(hv);
    hhi[hix] = hh;
    hlo[hix] = __float2bfloat16(hv - __bfloat162float(hh));
}

// ===================== decoder ==============================================
__global__ __launch_bounds__(128)
void decoder_kernel(const float* __restrict__ X, const float* __restrict__ Wd,
                    const float* __restrict__ bd, float* __restrict__ out)
{
    const int b = blockIdx.x;
    const int t = threadIdx.x;
    float s = 0.f;
    #pragma unroll
    for (int j = t; j < HID; j += 128) s += X[(long)b * HID + j] * Wd[j];
    s += __shfl_down_sync(0xffffffffu, s, 16);
    s += __shfl_down_sync(0xffffffffu, s, 8);
    s += __shfl_down_sync(0xffffffffu, s, 4);
    s += __shfl_down_sync(0xffffffffu, s, 2);
    s += __shfl_down_sync(0xffffffffu, s, 1);
    __shared__ float sh[4];
    if ((t & 31) == 0) sh[t >> 5] = s;
    __syncthreads();
    if (t == 0) out[b] = sh[0] + sh[1] + sh[2] + sh[3] + bd[0];
}

// ===================== host launcher ========================================
extern "C" void kernel_launch(void* const* d_in, const int* in_sizes, int n_in,
                              void* d_out, int out_size)
{
    const int*   sizes = (const int*)  d_in[0];
    const float* feat  = (const float*)d_in[1];
    const float* We0   = (const float*)d_in[2];
    const float* be0   = (const float*)d_in[3];
    const float* We1   = (const float*)d_in[4];
    const float* be1   = (const float*)d_in[5];
    const float* Wih   = (const float*)d_in[6];
    const float* bih   = (const float*)d_in[7];
    const float* Whh   = (const float*)d_in[8];
    const float* bhh   = (const float*)d_in[9];
    const float* Wl0   = (const float*)d_in[10];
    const float* bl0   = (const float*)d_in[11];
    const float* Wl1   = (const float*)d_in[12];
    const float* bl1   = (const float*)d_in[13];
    const float* Wd    = (const float*)d_in[14];
    const float* bd    = (const float*)d_in[15];
    float* out = (float*)d_out;

    const int T = in_sizes[1] / IN_DIM;
    const int mt = (T + 127) / 128;

    __nv_bfloat16 *fhi, *flo, *x1hi, *x1lo, *x2hi, *x2lo;
    __nv_bfloat16 *we0hi, *we0lo, *we1hi, *we1lo, *wihhi, *wihlo, *whhhi, *whhlo, *hhi, *hlo;
    float *xp, *G, *h, *c, *r0, *r1;
    int* starts;
    cudaGetSymbolAddress((void**)&fhi, g_fhi);     cudaGetSymbolAddress((void**)&flo, g_flo);
    cudaGetSymbolAddress((void**)&x1hi, g_x1hi);   cudaGetSymbolAddress((void**)&x1lo, g_x1lo);
    cudaGetSymbolAddress((void**)&x2hi, g_x2hi);   cudaGetSymbolAddress((void**)&x2lo, g_x2lo);
    cudaGetSymbolAddress((void**)&we0hi, g_we0hi); cudaGetSymbolAddress((void**)&we0lo, g_we0lo);
    cudaGetSymbolAddress((void**)&we1hi, g_we1hi); cudaGetSymbolAddress((void**)&we1lo, g_we1lo);
    cudaGetSymbolAddress((void**)&wihhi, g_wihhi); cudaGetSymbolAddress((void**)&wihlo, g_wihlo);
    cudaGetSymbolAddress((void**)&whhhi, g_whhhi); cudaGetSymbolAddress((void**)&whhlo, g_whhlo);
    cudaGetSymbolAddress((void**)&hhi, g_hhi);     cudaGetSymbolAddress((void**)&hlo, g_hlo);
    cudaGetSymbolAddress((void**)&xp, g_xp);
    cudaGetSymbolAddress((void**)&G, g_G);
    cudaGetSymbolAddress((void**)&h, g_h);
    cudaGetSymbolAddress((void**)&c, g_c);
    cudaGetSymbolAddress((void**)&r0, g_r0);
    cudaGetSymbolAddress((void**)&r1, g_r1);
    cudaGetSymbolAddress((void**)&starts, g_starts);

    cudaFuncSetAttribute(mm_mma<0>, cudaFuncAttributeMaxDynamicSharedMemorySize, MM_SMEM);
    cudaFuncSetAttribute(mm_mma<1>, cudaFuncAttributeMaxDynamicSharedMemorySize, MM_SMEM);

    scan_starts_kernel<<<1, BATCH>>>(sizes, starts);
    init_hc_kernel<<<(BATCH * HID + 255) / 256, 256>>>(h, c, hhi, hlo);

    // ---- convert inputs/weights to bf16 hi/lo (pad K where needed) ----
    auto cvt = [](const float* src, __nv_bfloat16* hi, __nv_bfloat16* lo, int M, int K, int Kp) {
        long n = (long)M * Kp;
        convert_pad_kernel<<<(int)((n + 255) / 256), 256>>>(src, hi, lo, M, K, Kp);
    };
    cvt(feat, fhi, flo, T, IN_DIM, KP0);
    cvt(We0, we0hi, we0lo, HID, IN_DIM, KP0);
    cvt(We1, we1hi, we1lo, HID, HID, HID);
    cvt(Wih, wihhi, wihlo, G4H, HID, HID);
    cvt(Whh, whhhi, whhlo, G4H, HID, HID);

    // ---- encoder MLP (tensor cores, bf16-split) ----
    mm_mma<1><<<dim3(HID / 128, mt), 256, MM_SMEM>>>(fhi, flo, we0hi, we0lo, be0,
                                                     nullptr, x1hi, x1lo, T, HID, KP0);
    mm_mma<1><<<dim3(HID / 128, mt), 256, MM_SMEM>>>(x1hi, x1lo, we1hi, we1lo, be1,
                                                     nullptr, x2hi, x2lo, T, HID, HID);
    // ---- input projection xp = x2 @ Wih^T ----
    mm_mma<0><<<dim3(G4H / 128, mt), 256, MM_SMEM>>>(x2hi, x2lo, wihhi, wihlo, nullptr,
                                                     xp, nullptr, nullptr, T, G4H, HID);

    // ---- LSTM recurrence ----
    for (int t = 0; t < MAXLEN; t++) {
        mm_mma<0><<<dim3(G4H / 128, BATCH / 128), 256, MM_SMEM>>>(hhi, hlo, whhhi, whhlo, nullptr,
                                                                  G, nullptr, nullptr, BATCH, G4H, HID);
        lstm_gates_kernel<<<BATCH, HID>>>(G, xp, sizes, starts, bih, bhh, h, c, hhi, hlo, t);
    }

    // ---- residual MLPs + decoder (fp32, tiny) ----
    sgemm_nt<true, true, true><<<dim3(HID / 64, BATCH / 64), 256>>>(h,  Wl0, bl0, h,  r0, BATCH, HID, HID);
    sgemm_nt<true, true, true><<<dim3(HID / 64, BATCH / 64), 256>>>(r0, Wl1, bl1, r0, r1, BATCH, HID, HID);
    decoder_kernel<<<BATCH, 128>>>(r1, Wd, bd, out);

    (void)n_in; (void)out_size;
}

// round 4
// speedup vs baseline: 3.0410x; 1.0501x over previous
#include <cuda_runtime.h>
#include <cuda_bf16.h>
#include <math.h>
#include <stdint.h>

#define IN_DIM 164
#define KP0    192
#define HID    512
#define G4H    2048
#define BATCH  1024
#define MAXLEN 128
#define MAXT   (BATCH * (MAXLEN - 1))
#define RCTAS  128

// ===================== scratch (static device globals) ======================
__device__ __nv_bfloat16 g_fhi[(long)MAXT * KP0];
__device__ __nv_bfloat16 g_x1hi[(long)MAXT * HID];
__device__ __nv_bfloat16 g_x2hi[(long)MAXT * HID];
__device__ __nv_bfloat16 g_xp[(long)MAXT * G4H];          // permuted gate layout, bf16
__device__ __nv_bfloat16 g_we0hi[HID * KP0], g_we0lo[HID * KP0];
__device__ __nv_bfloat16 g_we1hi[HID * HID], g_we1lo[HID * HID];
__device__ __nv_bfloat16 g_wihp_hi[G4H * HID], g_wihp_lo[G4H * HID];  // row-permuted
__device__ __nv_bfloat16 g_whhp_hi[G4H * HID], g_whhp_lo[G4H * HID];  // row-permuted
__device__ float         g_bsum[G4H];                      // bih+bhh, permuted
__device__ __nv_bfloat16 g_hbuf[2][BATCH * HID];
__device__ float         g_hf32[BATCH * HID];
__device__ float         g_r0[BATCH * HID];
__device__ float         g_r1[BATCH * HID];
__device__ int           g_starts[BATCH];
__device__ unsigned      g_bar;

// ===================== PTX helpers ==========================================
__device__ __forceinline__ uint32_t smem_u32(const void* p) {
    uint32_t a;
    asm("{ .reg .u64 t; cvta.to.shared.u64 t, %1; cvt.u32.u64 %0, t; }" : "=r"(a) : "l"(p));
    return a;
}
__device__ __forceinline__ void cp16(uint32_t dst, const void* src, int sz) {
    asm volatile("cp.async.cg.shared.global [%0], [%1], 16, %2;"
                 :: "r"(dst), "l"(src), "r"(sz));
}
__device__ __forceinline__ void cp_commit() {
    asm volatile("cp.async.commit_group;" ::: "memory");
}
#define CP_WAIT(n) asm volatile("cp.async.wait_group %0;" :: "n"(n) : "memory")

#define LDSM_X4(r, addr) \
    asm volatile("ldmatrix.sync.aligned.m8n8.x4.shared.b16 {%0,%1,%2,%3}, [%4];" \
        : "=r"((r)[0]), "=r"((r)[1]), "=r"((r)[2]), "=r"((r)[3]) : "r"(addr))

#define MMA16816(d, a, b0, b1) \
    asm volatile("mma.sync.aligned.m16n8k16.row.col.f32.bf16.bf16.f32 " \
        "{%0,%1,%2,%3}, {%4,%5,%6,%7}, {%8,%9}, {%0,%1,%2,%3};" \
        : "+f"((d)[0]), "+f"((d)[1]), "+f"((d)[2]), "+f"((d)[3]) \
        : "r"((a)[0]), "r"((a)[1]), "r"((a)[2]), "r"((a)[3]), "r"(b0), "r"(b1))

#define SWZ128(b) ((b) ^ (((b) >> 3) & 0x70))

__device__ __forceinline__ float sigf(float x) { return 1.f / (1.f + expf(-x)); }

// ===================== setup kernels ========================================
__global__ void scan_starts_kernel(const int* __restrict__ sizes, int* __restrict__ starts) {
    __shared__ int s[BATCH];
    int t = threadIdx.x;
    s[t] = sizes[t];
    __syncthreads();
    for (int off = 1; off < BATCH; off <<= 1) {
        int v = (t >= off) ? s[t - off] : 0;
        __syncthreads();
        s[t] += v;
        __syncthreads();
    }
    starts[t] = s[t] - sizes[t];
    if (t == 0) g_bar = 0u;
}

__global__ void prep_bsum_kernel(const float* __restrict__ bih, const float* __restrict__ bhh,
                                 float* __restrict__ bsum) {
    int n = blockIdx.x * blockDim.x + threadIdx.x;
    if (n < G4H) {
        int orig = (n & 3) * HID + (n >> 2);
        bsum[n] = bih[orig] + bhh[orig];
    }
}

// fp32 [M,K] -> bf16 hi [M,Kp], zero-padded
__global__ void cvt_act_kernel(const float* __restrict__ X, __nv_bfloat16* __restrict__ hi,
                               int M, int K, int Kp) {
    long i = (long)blockIdx.x * blockDim.x + threadIdx.x;
    if (i >= (long)M * Kp) return;
    int r = (int)(i / Kp), cidx = (int)(i % Kp);
    float v = (cidx < K) ? X[(long)r * K + cidx] : 0.f;
    hi[i] = __float2bfloat16(v);
}

// fp32 [M,K] -> bf16 hi/lo [M,Kp], zero-padded
__global__ void cvt_w_kernel(const float* __restrict__ X,
                             __nv_bfloat16* __restrict__ hi, __nv_bfloat16* __restrict__ lo,
                             int M, int K, int Kp) {
    long i = (long)blockIdx.x * blockDim.x + threadIdx.x;
    if (i >= (long)M * Kp) return;
    int r = (int)(i / Kp), cidx = (int)(i % Kp);
    float v = (cidx < K) ? X[(long)r * K + cidx] : 0.f;
    __nv_bfloat16 h = __float2bfloat16(v);
    hi[i] = h;
    lo[i] = __float2bfloat16(v - __bfloat162float(h));
}

// fp32 [2048,512] -> gate-permuted bf16 hi/lo: out row n = in row (n&3)*512 + (n>>2)
__global__ void cvt_wperm_kernel(const float* __restrict__ W,
                                 __nv_bfloat16* __restrict__ hi, __nv_bfloat16* __restrict__ lo) {
    long i = (long)blockIdx.x * blockDim.x + threadIdx.x;
    if (i >= (long)G4H * HID) return;
    int n = (int)(i >> 9), k = (int)(i & 511);
    int orig = (n & 3) * HID + (n >> 2);
    float v = W[(long)orig * HID + k];
    __nv_bfloat16 h = __float2bfloat16(v);
    hi[i] = h;
    lo[i] = __float2bfloat16(v - __bfloat162float(h));
}

// ===================== 2-term tensor GEMM (parallel section) ================
// C = epi( Ahi[M,K] @ (Bhi+Blo)[N,K]^T ).  CTA 128x128, BK=64, double-buffered.
// EPI 1: bias+relu -> bf16.  EPI 2: plain -> bf16.
#define P_OFF_A  0
#define P_OFF_BH 16384
#define P_OFF_BL 32768
#define P_STAGE  49152
#define P_SMEM   (2 * P_STAGE)

template<int EPI>
__global__ __launch_bounds__(256, 1)
void mm2(const __nv_bfloat16* __restrict__ Ahi,
         const __nv_bfloat16* __restrict__ Bhi, const __nv_bfloat16* __restrict__ Blo,
         const float* __restrict__ bias, __nv_bfloat16* __restrict__ C,
         int M, int N, int K)
{
    extern __shared__ char smem[];
    const uint32_t sb = smem_u32(smem);
    const int tid  = threadIdx.x;
    const int wid  = tid >> 5;
    const int lane = tid & 31;
    const int warp_m = wid & 3;
    const int warp_n = wid >> 2;

    const int m0 = blockIdx.y * 128;
    const int n0 = blockIdx.x * 128;
    const int nk = K >> 6;

    const int lrow = tid >> 1;
    const int qb = (tid & 1) * 4;
    const int arow = m0 + lrow;
    const int asz = (arow < M) ? 16 : 0;
    const long abase = (long)((arow < M) ? arow : (M - 1)) * K;
    const long bbase = (long)(n0 + lrow) * K;

    uint32_t sw_dst[4];
    #pragma unroll
    for (int i = 0; i < 4; i++)
        sw_dst[i] = (uint32_t)SWZ128(lrow * 128 + (qb + i) * 16);

    {
        #pragma unroll
        for (int i = 0; i < 4; i++) {
            const int q = qb + i;
            const uint32_t d = sb + sw_dst[i];
            cp16(d + P_OFF_A,  Ahi + abase + q * 8, asz);
            cp16(d + P_OFF_BH, Bhi + bbase + q * 8, 16);
            cp16(d + P_OFF_BL, Blo + bbase + q * 8, 16);
        }
        cp_commit();
    }

    float acc[2][8][4];
    #pragma unroll
    for (int a = 0; a < 2; a++)
        #pragma unroll
        for (int b = 0; b < 8; b++)
            #pragma unroll
            for (int v = 0; v < 4; v++) acc[a][b][v] = 0.f;

    const int a_row = warp_m * 32 + (lane & 15);
    const int a_kq  = (lane >> 4) * 16;
    const int b_row = warp_n * 64 + (lane & 7) + ((lane >> 4) << 3);
    const int b_kq  = ((lane >> 3) & 1) * 16;

    for (int it = 0; it < nk; ++it) {
        const uint32_t cur = sb + (uint32_t)((it & 1) * P_STAGE);
        if (it + 1 < nk) {
            const uint32_t nxt = sb + (uint32_t)(((it + 1) & 1) * P_STAGE);
            const long ka = abase + (long)(it + 1) * 64;
            const long kb = bbase + (long)(it + 1) * 64;
            #pragma unroll
            for (int i = 0; i < 4; i++) {
                const int q = qb + i;
                const uint32_t d = nxt + sw_dst[i];
                cp16(d + P_OFF_A,  Ahi + ka + q * 8, asz);
                cp16(d + P_OFF_BH, Bhi + kb + q * 8, 16);
                cp16(d + P_OFF_BL, Blo + kb + q * 8, 16);
            }
            cp_commit();
            CP_WAIT(1);
        } else {
            CP_WAIT(0);
        }
        __syncthreads();

        #pragma unroll
        for (int ks = 0; ks < 4; ks++) {
            const int kbyte = ks * 32;
            uint32_t ah[2][4], bh[4][4], bl[4][4];
            #pragma unroll
            for (int mf = 0; mf < 2; mf++) {
                const uint32_t ab = (uint32_t)SWZ128((a_row + mf * 16) * 128 + kbyte + a_kq);
                LDSM_X4(ah[mf], cur + P_OFF_A + ab);
            }
            #pragma unroll
            for (int p = 0; p < 4; p++) {
                const uint32_t bb = (uint32_t)SWZ128((b_row + p * 16) * 128 + kbyte + b_kq);
                LDSM_X4(bh[p], cur + P_OFF_BH + bb);
                LDSM_X4(bl[p], cur + P_OFF_BL + bb);
            }
            #pragma unroll
            for (int mf = 0; mf < 2; mf++) {
                #pragma unroll
                for (int p = 0; p < 4; p++) {
                    MMA16816(acc[mf][2 * p],     ah[mf], bh[p][0], bh[p][1]);
                    MMA16816(acc[mf][2 * p + 1], ah[mf], bh[p][2], bh[p][3]);
                    MMA16816(acc[mf][2 * p],     ah[mf], bl[p][0], bl[p][1]);
                    MMA16816(acc[mf][2 * p + 1], ah[mf], bl[p][2], bl[p][3]);
                }
            }
        }
        __syncthreads();
    }

    const int g  = lane >> 2;
    const int tg = lane & 3;
    #pragma unroll
    for (int mf = 0; mf < 2; mf++) {
        const int r_base = m0 + warp_m * 32 + mf * 16 + g;
        #pragma unroll
        for (int ng = 0; ng < 8; ng++) {
            const int col = n0 + warp_n * 64 + ng * 8 + tg * 2;
            float b0 = 0.f, b1 = 0.f;
            if (EPI == 1) { b0 = bias[col]; b1 = bias[col + 1]; }
            #pragma unroll
            for (int half = 0; half < 2; half++) {
                const int r = r_base + half * 8;
                if (r >= M) continue;
                float v0 = acc[mf][ng][2 * half]     + b0;
                float v1 = acc[mf][ng][2 * half + 1] + b1;
                if (EPI == 1) { v0 = fmaxf(v0, 0.f); v1 = fmaxf(v1, 0.f); }
                __nv_bfloat162 h2 = __floats2bfloat162_rn(v0, v1);
                *(uint32_t*)(C + (long)r * N + col) = *(uint32_t*)&h2;
            }
        }
    }
}

// ===================== persistent fused LSTM recurrence =====================
// 128 CTAs: mi = bid/16 (batch tile), ni = bid%16 (gate-col tile).
// Each step: acc = h(t-1) @ Whh'^T (2-term split), epilogue adds xp'+bias,
// computes gates via adjacent-lane shuffle; c stays in registers.
#define R_OFF_A  0
#define R_OFF_BH 16384
#define R_OFF_BL 32768
#define R_STAGE  49152
#define R_SMEM   (2 * R_STAGE)

__global__ __launch_bounds__(256, 1)
void lstm_persist(const __nv_bfloat16* __restrict__ xp,
                  const int* __restrict__ sizes, const int* __restrict__ starts,
                  const float* __restrict__ bsum,
                  const __nv_bfloat16* __restrict__ Whi, const __nv_bfloat16* __restrict__ Wlo,
                  __nv_bfloat16* __restrict__ hbuf0, __nv_bfloat16* __restrict__ hbuf1,
                  float* __restrict__ hf32)
{
    extern __shared__ char smem[];
    const uint32_t sb = smem_u32(smem);
    const int tid  = threadIdx.x;
    const int wid  = tid >> 5;
    const int lane = tid & 31;
    const int warp_m = wid & 3;
    const int warp_n = wid >> 2;
    const int mi = blockIdx.x >> 4;
    const int ni = blockIdx.x & 15;
    const int m0 = mi * 128;
    const int n0 = ni * 128;

    const int lrow = tid >> 1;
    const int qb = (tid & 1) * 4;
    const long abase = (long)(m0 + lrow) * HID;
    const long bbase = (long)(n0 + lrow) * HID;

    uint32_t sw_dst[4];
    #pragma unroll
    for (int i = 0; i < 4; i++)
        sw_dst[i] = (uint32_t)SWZ128(lrow * 128 + (qb + i) * 16);

    const int a_row = warp_m * 32 + (lane & 15);
    const int a_kq  = (lane >> 4) * 16;
    const int b_row = warp_n * 64 + (lane & 7) + ((lane >> 4) << 3);
    const int b_kq  = ((lane >> 3) & 1) * 16;

    const int g  = lane >> 2;
    const int tg = lane & 3;
    const int col_base = n0 + warp_n * 64 + tg * 2;

    // per-lane static row info
    int rr[2][2], sz_r[2][2], st_r[2][2];
    #pragma unroll
    for (int mf = 0; mf < 2; mf++)
        #pragma unroll
        for (int half = 0; half < 2; half++) {
            int r = m0 + warp_m * 32 + mf * 16 + g + 8 * half;
            rr[mf][half] = r;
            sz_r[mf][half] = sizes[r];
            st_r[mf][half] = starts[r];
        }

    float c_reg[2][8][2];
    #pragma unroll
    for (int mf = 0; mf < 2; mf++)
        #pragma unroll
        for (int ng = 0; ng < 8; ng++)
            #pragma unroll
            for (int half = 0; half < 2; half++) c_reg[mf][ng][half] = 0.f;

    __nv_bfloat16* bufs[2] = { hbuf0, hbuf1 };

    for (int t = 0; t < MAXLEN; t++) {
        float acc[2][8][4];
        #pragma unroll
        for (int a = 0; a < 2; a++)
            #pragma unroll
            for (int b = 0; b < 8; b++)
                #pragma unroll
                for (int v = 0; v < 4; v++) acc[a][b][v] = 0.f;

        if (t > 0) {
            const __nv_bfloat16* hr = bufs[(t + 1) & 1];   // written at step t-1
            // prefetch stage 0
            #pragma unroll
            for (int i = 0; i < 4; i++) {
                const int q = qb + i;
                const uint32_t d = sb + sw_dst[i];
                cp16(d + R_OFF_A,  hr  + abase + q * 8, 16);
                cp16(d + R_OFF_BH, Whi + bbase + q * 8, 16);
                cp16(d + R_OFF_BL, Wlo + bbase + q * 8, 16);
            }
            cp_commit();

            for (int it = 0; it < 8; ++it) {
                const uint32_t cur = sb + (uint32_t)((it & 1) * R_STAGE);
                if (it + 1 < 8) {
                    const uint32_t nxt = sb + (uint32_t)(((it + 1) & 1) * R_STAGE);
                    const long ka = abase + (long)(it + 1) * 64;
                    const long kb = bbase + (long)(it + 1) * 64;
                    #pragma unroll
                    for (int i = 0; i < 4; i++) {
                        const int q = qb + i;
                        const uint32_t d = nxt + sw_dst[i];
                        cp16(d + R_OFF_A,  hr  + ka + q * 8, 16);
                        cp16(d + R_OFF_BH, Whi + kb + q * 8, 16);
                        cp16(d + R_OFF_BL, Wlo + kb + q * 8, 16);
                    }
                    cp_commit();
                    CP_WAIT(1);
                } else {
                    CP_WAIT(0);
                }
                __syncthreads();

                #pragma unroll
                for (int ks = 0; ks < 4; ks++) {
                    const int kbyte = ks * 32;
                    uint32_t ah[2][4], bh[4][4], bl[4][4];
                    #pragma unroll
                    for (int mf = 0; mf < 2; mf++) {
                        const uint32_t ab = (uint32_t)SWZ128((a_row + mf * 16) * 128 + kbyte + a_kq);
                        LDSM_X4(ah[mf], cur + R_OFF_A + ab);
                    }
                    #pragma unroll
                    for (int p = 0; p < 4; p++) {
                        const uint32_t bb = (uint32_t)SWZ128((b_row + p * 16) * 128 + kbyte + b_kq);
                        LDSM_X4(bh[p], cur + R_OFF_BH + bb);
                        LDSM_X4(bl[p], cur + R_OFF_BL + bb);
                    }
                    #pragma unroll
                    for (int mf = 0; mf < 2; mf++) {
                        #pragma unroll
                        for (int p = 0; p < 4; p++) {
                            MMA16816(acc[mf][2 * p],     ah[mf], bh[p][0], bh[p][1]);
                            MMA16816(acc[mf][2 * p + 1], ah[mf], bh[p][2], bh[p][3]);
                            MMA16816(acc[mf][2 * p],     ah[mf], bl[p][0], bl[p][1]);
                            MMA16816(acc[mf][2 * p + 1], ah[mf], bl[p][2], bl[p][3]);
                        }
                    }
                }
                __syncthreads();
            }
        }

        // ---- fused gate epilogue ----
        __nv_bfloat16* hw = bufs[t & 1];
        #pragma unroll
        for (int mf = 0; mf < 2; mf++) {
            #pragma unroll
            for (int half = 0; half < 2; half++) {
                const int r = rr[mf][half];
                const bool act = (t < sz_r[mf][half]);
                const __nv_bfloat16* xrow = xp + (long)(st_r[mf][half] + t) * G4H;
                #pragma unroll
                for (int ng = 0; ng < 8; ng++) {
                    const int col = col_base + ng * 8;
                    float p0 = acc[mf][ng][2 * half]     + bsum[col];
                    float p1 = acc[mf][ng][2 * half + 1] + bsum[col + 1];
                    if (act) {
                        __nv_bfloat162 x2 = *(const __nv_bfloat162*)(xrow + col);
                        p0 += __bfloat162float(x2.x);
                        p1 += __bfloat162float(x2.y);
                    }
                    const float q0 = __shfl_xor_sync(0xffffffffu, p0, 1);
                    const float q1 = __shfl_xor_sync(0xffffffffu, p1, 1);
                    if ((tg & 1) == 0) {
                        // p0=i, p1=f, q0=g, q1=o
                        float cc = sigf(p1) * c_reg[mf][ng][half] + sigf(p0) * tanhf(q0);
                        c_reg[mf][ng][half] = cc;
                        float hv = sigf(q1) * tanhf(cc);
                        const int j = col >> 2;
                        hw[(long)r * HID + j] = __float2bfloat16(hv);
                        if (t == MAXLEN - 1) hf32[(long)r * HID + j] = hv;
                    }
                }
            }
        }

        // ---- grid barrier ----
        if (t < MAXLEN - 1) {
            __syncthreads();
            if (tid == 0) {
                __threadfence();
                atomicAdd(&g_bar, 1u);
                const unsigned target = (unsigned)RCTAS * (unsigned)(t + 1);
                while (*(volatile unsigned*)&g_bar < target) { __nanosleep(64); }
                __threadfence();
            }
            __syncthreads();
        }
    }
}

// ===================== fp32 SGEMM (tail) ====================================
template<bool RELU, bool RESID, bool BIAS>
__global__ __launch_bounds__(256)
void sgemm_nt(const float* __restrict__ A, const float* __restrict__ W,
              const float* __restrict__ bias, const float* __restrict__ R,
              float* __restrict__ C, int M, int N, int K)
{
    constexpr int BM = 64, BN = 64, BK = 16;
    __shared__ float As[BK][BM];
    __shared__ float Bs[BK][BN];
    const int tid = threadIdx.x;
    const int brow = blockIdx.y * BM;
    const int bcol = blockIdx.x * BN;
    const int tr = (tid / 16) * 4;
    const int tc = (tid % 16) * 4;
    const int lr = tid / 4;
    const int lc = (tid % 4) * 4;
    float acc[4][4] = {};
    for (int k0 = 0; k0 < K; k0 += BK) {
        {
            int ar = brow + lr;
            float4 v = *reinterpret_cast<const float4*>(&A[(long)ar * K + k0 + lc]);
            As[lc + 0][lr] = v.x; As[lc + 1][lr] = v.y; As[lc + 2][lr] = v.z; As[lc + 3][lr] = v.w;
        }
        {
            int wr = bcol + lr;
            float4 v = *reinterpret_cast<const float4*>(&W[(long)wr * K + k0 + lc]);
            Bs[lc + 0][lr] = v.x; Bs[lc + 1][lr] = v.y; Bs[lc + 2][lr] = v.z; Bs[lc + 3][lr] = v.w;
        }
        __syncthreads();
        #pragma unroll
        for (int kk = 0; kk < BK; kk++) {
            float a[4], b[4];
            #pragma unroll
            for (int i = 0; i < 4; i++) a[i] = As[kk][tr + i];
            #pragma unroll
            for (int j = 0; j < 4; j++) b[j] = Bs[kk][tc + j];
            #pragma unroll
            for (int i = 0; i < 4; i++)
                #pragma unroll
                for (int j = 0; j < 4; j++)
                    acc[i][j] = fmaf(a[i], b[j], acc[i][j]);
        }
        __syncthreads();
    }
    #pragma unroll
    for (int i = 0; i < 4; i++) {
        int r = brow + tr + i;
        #pragma unroll
        for (int j = 0; j < 4; j++) {
            int cidx = bcol + tc + j;
            float v = acc[i][j];
            if (BIAS)  v += bias[cidx];
            if (RELU)  v = fmaxf(v, 0.f);
            if (RESID) v += R[(long)r * N + cidx];
            C[(long)r * N + cidx] = v;
        }
    }
}

// ===================== decoder ==============================================
__global__ __launch_bounds__(128)
void decoder_kernel(const float* __restrict__ X, const float* __restrict__ Wd,
                    const float* __restrict__ bd, float* __restrict__ out)
{
    const int b = blockIdx.x;
    const int t = threadIdx.x;
    float s = 0.f;
    #pragma unroll
    for (int j = t; j < HID; j += 128) s += X[(long)b * HID + j] * Wd[j];
    s += __shfl_down_sync(0xffffffffu, s, 16);
    s += __shfl_down_sync(0xffffffffu, s, 8);
    s += __shfl_down_sync(0xffffffffu, s, 4);
    s += __shfl_down_sync(0xffffffffu, s, 2);
    s += __shfl_down_sync(0xffffffffu, s, 1);
    __shared__ float sh[4];
    if ((t & 31) == 0) sh[t >> 5] = s;
    __syncthreads();
    if (t == 0) out[b] = sh[0] + sh[1] + sh[2] + sh[3] + bd[0];
}

// ===================== host launcher ========================================
extern "C" void kernel_launch(void* const* d_in, const int* in_sizes, int n_in,
                              void* d_out, int out_size)
{
    const int*   sizes = (const int*)  d_in[0];
    const float* feat  = (const float*)d_in[1];
    const float* We0   = (const float*)d_in[2];
    const float* be0   = (const float*)d_in[3];
    const float* We1   = (const float*)d_in[4];
    const float* be1   = (const float*)d_in[5];
    const float* Wih   = (const float*)d_in[6];
    const float* bih   = (const float*)d_in[7];
    const float* Whh   = (const float*)d_in[8];
    const float* bhh   = (const float*)d_in[9];
    const float* Wl0   = (const float*)d_in[10];
    const float* bl0   = (const float*)d_in[11];
    const float* Wl1   = (const float*)d_in[12];
    const float* bl1   = (const float*)d_in[13];
    const float* Wd    = (const float*)d_in[14];
    const float* bd    = (const float*)d_in[15];
    float* out = (float*)d_out;

    const int T = in_sizes[1] / IN_DIM;
    const int mt = (T + 127) / 128;

    __nv_bfloat16 *fhi, *x1hi, *x2hi, *xp;
    __nv_bfloat16 *we0hi, *we0lo, *we1hi, *we1lo, *wihphi, *wihplo, *whhphi, *whhplo;
    __nv_bfloat16 *hb0, *hb1;
    float *bsum, *hf32, *r0, *r1;
    int* starts;
    cudaGetSymbolAddress((void**)&fhi, g_fhi);
    cudaGetSymbolAddress((void**)&x1hi, g_x1hi);
    cudaGetSymbolAddress((void**)&x2hi, g_x2hi);
    cudaGetSymbolAddress((void**)&xp, g_xp);
    cudaGetSymbolAddress((void**)&we0hi, g_we0hi); cudaGetSymbolAddress((void**)&we0lo, g_we0lo);
    cudaGetSymbolAddress((void**)&we1hi, g_we1hi); cudaGetSymbolAddress((void**)&we1lo, g_we1lo);
    cudaGetSymbolAddress((void**)&wihphi, g_wihp_hi); cudaGetSymbolAddress((void**)&wihplo, g_wihp_lo);
    cudaGetSymbolAddress((void**)&whhphi, g_whhp_hi); cudaGetSymbolAddress((void**)&whhplo, g_whhp_lo);
    cudaGetSymbolAddress((void**)&bsum, g_bsum);
    {
        __nv_bfloat16* hb;
        cudaGetSymbolAddress((void**)&hb, g_hbuf);
        hb0 = hb;
        hb1 = hb + (long)BATCH * HID;
    }
    cudaGetSymbolAddress((void**)&hf32, g_hf32);
    cudaGetSymbolAddress((void**)&r0, g_r0);
    cudaGetSymbolAddress((void**)&r1, g_r1);
    cudaGetSymbolAddress((void**)&starts, g_starts);

    cudaFuncSetAttribute(mm2<1>, cudaFuncAttributeMaxDynamicSharedMemorySize, P_SMEM);
    cudaFuncSetAttribute(mm2<2>, cudaFuncAttributeMaxDynamicSharedMemorySize, P_SMEM);
    cudaFuncSetAttribute(lstm_persist, cudaFuncAttributeMaxDynamicSharedMemorySize, R_SMEM);

    scan_starts_kernel<<<1, BATCH>>>(sizes, starts);
    prep_bsum_kernel<<<(G4H + 255) / 256, 256>>>(bih, bhh, bsum);

    // converts
    {
        long n;
        n = (long)T * KP0;
        cvt_act_kernel<<<(int)((n + 255) / 256), 256>>>(feat, fhi, T, IN_DIM, KP0);
        n = (long)HID * KP0;
        cvt_w_kernel<<<(int)((n + 255) / 256), 256>>>(We0, we0hi, we0lo, HID, IN_DIM, KP0);
        n = (long)HID * HID;
        cvt_w_kernel<<<(int)((n + 255) / 256), 256>>>(We1, we1hi, we1lo, HID, HID, HID);
        n = (long)G4H * HID;
        cvt_wperm_kernel<<<(int)((n + 255) / 256), 256>>>(Wih, wihphi, wihplo);
        cvt_wperm_kernel<<<(int)((n + 255) / 256), 256>>>(Whh, whhphi, whhplo);
    }

    // encoder MLP + input projection (gate-permuted)
    mm2<1><<<dim3(HID / 128, mt), 256, P_SMEM>>>(fhi, we0hi, we0lo, be0, x1hi, T, HID, KP0);
    mm2<1><<<dim3(HID / 128, mt), 256, P_SMEM>>>(x1hi, we1hi, we1lo, be1, x2hi, T, HID, HID);
    mm2<2><<<dim3(G4H / 128, mt), 256, P_SMEM>>>(x2hi, wihphi, wihplo, nullptr, xp, T, G4H, HID);

    // persistent fused recurrence (one kernel, 128 steps)
    lstm_persist<<<RCTAS, 256, R_SMEM>>>(xp, sizes, starts, bsum, whhphi, whhplo,
                                         hb0, hb1, hf32);

    // tail
    sgemm_nt<true, true, true><<<dim3(HID / 64, BATCH / 64), 256>>>(hf32, Wl0, bl0, hf32, r0, BATCH, HID, HID);
    sgemm_nt<true, true, true><<<dim3(HID / 64, BATCH / 64), 256>>>(r0,   Wl1, bl1, r0,   r1, BATCH, HID, HID);
    decoder_kernel<<<BATCH, 128>>>(r1, Wd, bd, out);

    (void)n_in; (void)out_size;
}

// round 5
// speedup vs baseline: 4.2987x; 1.4136x over previous
#include <cuda_runtime.h>
#include <cuda_fp16.h>
#include <math.h>
#include <stdint.h>

#define IN_DIM 164
#define KP0    192
#define HID    512
#define G4H    2048
#define BATCH  1024
#define MAXLEN 128
#define MAXT   (BATCH * (MAXLEN - 1))
#define RCTAS  128

// ===================== scratch (static device globals) ======================
__device__ __half g_fh[(long)MAXT * KP0];
__device__ __half g_x1[(long)MAXT * HID];
__device__ __half g_x2[(long)MAXT * HID];
__device__ __half g_xp[(long)MAXT * G4H];            // gate-permuted, fp16
__device__ __half g_we0[HID * KP0];
__device__ __half g_we1[HID * HID];
__device__ __half g_wihp[G4H * HID];                 // row-permuted
__device__ __half g_whhp[G4H * HID];                 // row-permuted
__device__ float  g_bsum[G4H];                       // bih+bhh, permuted
__device__ __half g_hbuf[2][BATCH * HID];
__device__ float  g_hf32[BATCH * HID];
__device__ float  g_r0[BATCH * HID];
__device__ float  g_r1[BATCH * HID];
__device__ int    g_starts[BATCH];
__device__ unsigned g_bar;

// ===================== PTX helpers ==========================================
__device__ __forceinline__ uint32_t smem_u32(const void* p) {
    uint32_t a;
    asm("{ .reg .u64 t; cvta.to.shared.u64 t, %1; cvt.u32.u64 %0, t; }" : "=r"(a) : "l"(p));
    return a;
}
__device__ __forceinline__ void cp16(uint32_t dst, const void* src, int sz) {
    asm volatile("cp.async.cg.shared.global [%0], [%1], 16, %2;"
                 :: "r"(dst), "l"(src), "r"(sz));
}
__device__ __forceinline__ void cp_commit() {
    asm volatile("cp.async.commit_group;" ::: "memory");
}
#define CP_WAIT(n) asm volatile("cp.async.wait_group %0;" :: "n"(n) : "memory")

#define LDSM_X4(r, addr) \
    asm volatile("ldmatrix.sync.aligned.m8n8.x4.shared.b16 {%0,%1,%2,%3}, [%4];" \
        : "=r"((r)[0]), "=r"((r)[1]), "=r"((r)[2]), "=r"((r)[3]) : "r"(addr))

#define MMA16816(d, a, b0, b1) \
    asm volatile("mma.sync.aligned.m16n8k16.row.col.f32.f16.f16.f32 " \
        "{%0,%1,%2,%3}, {%4,%5,%6,%7}, {%8,%9}, {%0,%1,%2,%3};" \
        : "+f"((d)[0]), "+f"((d)[1]), "+f"((d)[2]), "+f"((d)[3]) \
        : "r"((a)[0]), "r"((a)[1]), "r"((a)[2]), "r"((a)[3]), "r"(b0), "r"(b1))

#define SWZ128(b) ((b) ^ (((b) >> 3) & 0x70))

__device__ __forceinline__ float sigf(float x) { return 1.f / (1.f + expf(-x)); }

// ===================== setup kernels ========================================
__global__ void scan_starts_kernel(const int* __restrict__ sizes, int* __restrict__ starts) {
    __shared__ int s[BATCH];
    int t = threadIdx.x;
    s[t] = sizes[t];
    __syncthreads();
    for (int off = 1; off < BATCH; off <<= 1) {
        int v = (t >= off) ? s[t - off] : 0;
        __syncthreads();
        s[t] += v;
        __syncthreads();
    }
    starts[t] = s[t] - sizes[t];
    if (t == 0) g_bar = 0u;
}

__global__ void prep_bsum_kernel(const float* __restrict__ bih, const float* __restrict__ bhh,
                                 float* __restrict__ bsum) {
    int n = blockIdx.x * blockDim.x + threadIdx.x;
    if (n < G4H) {
        int orig = (n & 3) * HID + (n >> 2);
        bsum[n] = bih[orig] + bhh[orig];
    }
}

// fp32 [M,K] -> fp16 [M,Kp], zero-padded
__global__ void cvt_kernel(const float* __restrict__ X, __half* __restrict__ out,
                           int M, int K, int Kp) {
    long i = (long)blockIdx.x * blockDim.x + threadIdx.x;
    if (i >= (long)M * Kp) return;
    int r = (int)(i / Kp), cidx = (int)(i % Kp);
    float v = (cidx < K) ? X[(long)r * K + cidx] : 0.f;
    out[i] = __float2half(v);
}

// fp32 [2048,512] -> gate-permuted fp16: out row n = in row (n&3)*512 + (n>>2)
__global__ void cvt_wperm_kernel(const float* __restrict__ W, __half* __restrict__ out) {
    long i = (long)blockIdx.x * blockDim.x + threadIdx.x;
    if (i >= (long)G4H * HID) return;
    int n = (int)(i >> 9), k = (int)(i & 511);
    int orig = (n & 3) * HID + (n >> 2);
    out[i] = __float2half(W[(long)orig * HID + k]);
}

// ===================== fp16 tensor GEMM (parallel section) ==================
// C = epi( A[M,K] @ B[N,K]^T ).  CTA 128x128, BK=64, double-buffered cp.async.
// EPI 1: bias+relu -> fp16.  EPI 2: plain -> fp16.
#define P_OFF_A  0
#define P_OFF_B  16384
#define P_STAGE  32768
#define P_SMEM   (2 * P_STAGE)

template<int EPI>
__global__ __launch_bounds__(256)
void mm2(const __half* __restrict__ A, const __half* __restrict__ B,
         const float* __restrict__ bias, __half* __restrict__ C,
         int M, int N, int K)
{
    extern __shared__ char smem[];
    const uint32_t sb = smem_u32(smem);
    const int tid  = threadIdx.x;
    const int wid  = tid >> 5;
    const int lane = tid & 31;
    const int warp_m = wid & 3;
    const int warp_n = wid >> 2;

    const int m0 = blockIdx.y * 128;
    const int n0 = blockIdx.x * 128;
    const int nk = K >> 6;

    const int lrow = tid >> 1;
    const int qb = (tid & 1) * 4;
    const int arow = m0 + lrow;
    const int asz = (arow < M) ? 16 : 0;
    const long abase = (long)((arow < M) ? arow : (M - 1)) * K;
    const long bbase = (long)(n0 + lrow) * K;

    uint32_t sw_dst[4];
    #pragma unroll
    for (int i = 0; i < 4; i++)
        sw_dst[i] = (uint32_t)SWZ128(lrow * 128 + (qb + i) * 16);

    {
        #pragma unroll
        for (int i = 0; i < 4; i++) {
            const int q = qb + i;
            const uint32_t d = sb + sw_dst[i];
            cp16(d + P_OFF_A, A + abase + q * 8, asz);
            cp16(d + P_OFF_B, B + bbase + q * 8, 16);
        }
        cp_commit();
    }

    float acc[2][8][4];
    #pragma unroll
    for (int a = 0; a < 2; a++)
        #pragma unroll
        for (int b = 0; b < 8; b++)
            #pragma unroll
            for (int v = 0; v < 4; v++) acc[a][b][v] = 0.f;

    const int a_row = warp_m * 32 + (lane & 15);
    const int a_kq  = (lane >> 4) * 16;
    const int b_row = warp_n * 64 + (lane & 7) + ((lane >> 4) << 3);
    const int b_kq  = ((lane >> 3) & 1) * 16;

    for (int it = 0; it < nk; ++it) {
        const uint32_t cur = sb + (uint32_t)((it & 1) * P_STAGE);
        if (it + 1 < nk) {
            const uint32_t nxt = sb + (uint32_t)(((it + 1) & 1) * P_STAGE);
            const long ka = abase + (long)(it + 1) * 64;
            const long kb = bbase + (long)(it + 1) * 64;
            #pragma unroll
            for (int i = 0; i < 4; i++) {
                const int q = qb + i;
                const uint32_t d = nxt + sw_dst[i];
                cp16(d + P_OFF_A, A + ka + q * 8, asz);
                cp16(d + P_OFF_B, B + kb + q * 8, 16);
            }
            cp_commit();
            CP_WAIT(1);
        } else {
            CP_WAIT(0);
        }
        __syncthreads();

        #pragma unroll
        for (int ks = 0; ks < 4; ks++) {
            const int kbyte = ks * 32;
            uint32_t ah[2][4], bh[4][4];
            #pragma unroll
            for (int mf = 0; mf < 2; mf++) {
                const uint32_t ab = (uint32_t)SWZ128((a_row + mf * 16) * 128 + kbyte + a_kq);
                LDSM_X4(ah[mf], cur + P_OFF_A + ab);
            }
            #pragma unroll
            for (int p = 0; p < 4; p++) {
                const uint32_t bb = (uint32_t)SWZ128((b_row + p * 16) * 128 + kbyte + b_kq);
                LDSM_X4(bh[p], cur + P_OFF_B + bb);
            }
            #pragma unroll
            for (int mf = 0; mf < 2; mf++) {
                #pragma unroll
                for (int p = 0; p < 4; p++) {
                    MMA16816(acc[mf][2 * p],     ah[mf], bh[p][0], bh[p][1]);
                    MMA16816(acc[mf][2 * p + 1], ah[mf], bh[p][2], bh[p][3]);
                }
            }
        }
        __syncthreads();
    }

    const int g  = lane >> 2;
    const int tg = lane & 3;
    #pragma unroll
    for (int mf = 0; mf < 2; mf++) {
        const int r_base = m0 + warp_m * 32 + mf * 16 + g;
        #pragma unroll
        for (int ng = 0; ng < 8; ng++) {
            const int col = n0 + warp_n * 64 + ng * 8 + tg * 2;
            float b0 = 0.f, b1 = 0.f;
            if (EPI == 1) { b0 = bias[col]; b1 = bias[col + 1]; }
            #pragma unroll
            for (int half_i = 0; half_i < 2; half_i++) {
                const int r = r_base + half_i * 8;
                if (r >= M) continue;
                float v0 = acc[mf][ng][2 * half_i]     + b0;
                float v1 = acc[mf][ng][2 * half_i + 1] + b1;
                if (EPI == 1) { v0 = fmaxf(v0, 0.f); v1 = fmaxf(v1, 0.f); }
                __half2 h2 = __floats2half2_rn(v0, v1);
                *(uint32_t*)(C + (long)r * N + col) = *(uint32_t*)&h2;
            }
        }
    }
}

// ===================== persistent fused LSTM recurrence =====================
// 128 CTAs: mi = bid/16 (128-row batch tile), ni = bid%16 (128-col gate tile).
// Whh slice (128x512 fp16 = 128KB) resident in smem for all 128 steps.
// Per step: stream h(t-1) (A), single-term fp16 MMA, fused gate epilogue,
// c in registers, grid barrier.
#define R_SM_B   0                      // 8 chunks of 16KB (K-major, 64-K each)
#define R_SM_A   131072                 // 2 stages of 16KB
#define R_STAGE  16384
#define R_SMEM   (131072 + 2 * R_STAGE)

__global__ __launch_bounds__(256, 1)
void lstm_persist(const __half* __restrict__ xp,
                  const int* __restrict__ sizes, const int* __restrict__ starts,
                  const float* __restrict__ bsum,
                  const __half* __restrict__ Whh,
                  __half* __restrict__ hbuf0, __half* __restrict__ hbuf1,
                  float* __restrict__ hf32)
{
    extern __shared__ char smem[];
    const uint32_t sb = smem_u32(smem);
    const int tid  = threadIdx.x;
    const int wid  = tid >> 5;
    const int lane = tid & 31;
    const int warp_m = wid & 3;
    const int warp_n = wid >> 2;
    const int mi = blockIdx.x >> 4;
    const int ni = blockIdx.x & 15;
    const int m0 = mi * 128;
    const int n0 = ni * 128;

    const int lrow = tid >> 1;
    const int qb = (tid & 1) * 4;
    const long abase = (long)(m0 + lrow) * HID;
    const long bbase = (long)(n0 + lrow) * HID;

    uint32_t sw_dst[4];
    #pragma unroll
    for (int i = 0; i < 4; i++)
        sw_dst[i] = (uint32_t)SWZ128(lrow * 128 + (qb + i) * 16);

    // ---- preload resident Whh slice: 8 K-chunks x 16KB ----
    #pragma unroll
    for (int it = 0; it < 8; it++) {
        #pragma unroll
        for (int i = 0; i < 4; i++) {
            const int q = qb + i;
            cp16(sb + R_SM_B + it * 16384 + sw_dst[i], Whh + bbase + it * 64 + q * 8, 16);
        }
    }
    cp_commit();
    CP_WAIT(0);
    __syncthreads();

    const int a_row = warp_m * 32 + (lane & 15);
    const int a_kq  = (lane >> 4) * 16;
    const int b_row = warp_n * 64 + (lane & 7) + ((lane >> 4) << 3);
    const int b_kq  = ((lane >> 3) & 1) * 16;

    const int g  = lane >> 2;
    const int tg = lane & 3;
    const int col_base = n0 + warp_n * 64 + tg * 2;

    int rr[2][2], sz_r[2][2], st_r[2][2];
    #pragma unroll
    for (int mf = 0; mf < 2; mf++)
        #pragma unroll
        for (int hf = 0; hf < 2; hf++) {
            int r = m0 + warp_m * 32 + mf * 16 + g + 8 * hf;
            rr[mf][hf] = r;
            sz_r[mf][hf] = sizes[r];
            st_r[mf][hf] = starts[r];
        }

    float c_reg[2][8][2];
    #pragma unroll
    for (int mf = 0; mf < 2; mf++)
        #pragma unroll
        for (int ng = 0; ng < 8; ng++)
            #pragma unroll
            for (int hf = 0; hf < 2; hf++) c_reg[mf][ng][hf] = 0.f;

    __half* bufs[2] = { hbuf0, hbuf1 };

    for (int t = 0; t < MAXLEN; t++) {
        float acc[2][8][4];
        #pragma unroll
        for (int a = 0; a < 2; a++)
            #pragma unroll
            for (int b = 0; b < 8; b++)
                #pragma unroll
                for (int v = 0; v < 4; v++) acc[a][b][v] = 0.f;

        if (t > 0) {
            const __half* hr = bufs[(t + 1) & 1];   // written at step t-1
            // prefetch A stage 0
            #pragma unroll
            for (int i = 0; i < 4; i++) {
                const int q = qb + i;
                cp16(sb + R_SM_A + sw_dst[i], hr + abase + q * 8, 16);
            }
            cp_commit();

            for (int it = 0; it < 8; ++it) {
                const uint32_t curA = sb + R_SM_A + (uint32_t)((it & 1) * R_STAGE);
                if (it + 1 < 8) {
                    const uint32_t nxtA = sb + R_SM_A + (uint32_t)(((it + 1) & 1) * R_STAGE);
                    const long ka = abase + (long)(it + 1) * 64;
                    #pragma unroll
                    for (int i = 0; i < 4; i++) {
                        const int q = qb + i;
                        cp16(nxtA + sw_dst[i], hr + ka + q * 8, 16);
                    }
                    cp_commit();
                    CP_WAIT(1);
                } else {
                    CP_WAIT(0);
                }
                __syncthreads();

                const uint32_t curB = sb + R_SM_B + (uint32_t)(it * 16384);
                #pragma unroll
                for (int ks = 0; ks < 4; ks++) {
                    const int kbyte = ks * 32;
                    uint32_t ah[2][4], bh[4][4];
                    #pragma unroll
                    for (int mf = 0; mf < 2; mf++) {
                        const uint32_t ab = (uint32_t)SWZ128((a_row + mf * 16) * 128 + kbyte + a_kq);
                        LDSM_X4(ah[mf], curA + ab);
                    }
                    #pragma unroll
                    for (int p = 0; p < 4; p++) {
                        const uint32_t bb = (uint32_t)SWZ128((b_row + p * 16) * 128 + kbyte + b_kq);
                        LDSM_X4(bh[p], curB + bb);
                    }
                    #pragma unroll
                    for (int mf = 0; mf < 2; mf++) {
                        #pragma unroll
                        for (int p = 0; p < 4; p++) {
                            MMA16816(acc[mf][2 * p],     ah[mf], bh[p][0], bh[p][1]);
                            MMA16816(acc[mf][2 * p + 1], ah[mf], bh[p][2], bh[p][3]);
                        }
                    }
                }
                __syncthreads();
            }
        }

        // ---- fused gate epilogue ----
        __half* hw = bufs[t & 1];
        #pragma unroll
        for (int mf = 0; mf < 2; mf++) {
            #pragma unroll
            for (int hf = 0; hf < 2; hf++) {
                const int r = rr[mf][hf];
                const bool act = (t < sz_r[mf][hf]);
                const __half* xrow = xp + (long)(st_r[mf][hf] + t) * G4H;
                #pragma unroll
                for (int ng = 0; ng < 8; ng++) {
                    const int col = col_base + ng * 8;
                    float p0 = acc[mf][ng][2 * hf]     + bsum[col];
                    float p1 = acc[mf][ng][2 * hf + 1] + bsum[col + 1];
                    if (act) {
                        __half2 x2 = *(const __half2*)(xrow + col);
                        float2 xf = __half22float2(x2);
                        p0 += xf.x;
                        p1 += xf.y;
                    }
                    const float q0 = __shfl_xor_sync(0xffffffffu, p0, 1);
                    const float q1 = __shfl_xor_sync(0xffffffffu, p1, 1);
                    if ((tg & 1) == 0) {
                        // p0=i, p1=f, q0=g, q1=o
                        float cc = sigf(p1) * c_reg[mf][ng][hf] + sigf(p0) * tanhf(q0);
                        c_reg[mf][ng][hf] = cc;
                        float hv = sigf(q1) * tanhf(cc);
                        const int j = col >> 2;
                        hw[(long)r * HID + j] = __float2half(hv);
                        if (t == MAXLEN - 1) hf32[(long)r * HID + j] = hv;
                    }
                }
            }
        }

        // ---- grid barrier ----
        if (t < MAXLEN - 1) {
            __syncthreads();
            if (tid == 0) {
                __threadfence();
                atomicAdd(&g_bar, 1u);
                const unsigned target = (unsigned)RCTAS * (unsigned)(t + 1);
                while (*(volatile unsigned*)&g_bar < target) { __nanosleep(64); }
                __threadfence();
            }
            __syncthreads();
        }
    }
}

// ===================== fp32 SGEMM (tail) ====================================
template<bool RELU, bool RESID, bool BIAS>
__global__ __launch_bounds__(256)
void sgemm_nt(const float* __restrict__ A, const float* __restrict__ W,
              const float* __restrict__ bias, const float* __restrict__ R,
              float* __restrict__ C, int M, int N, int K)
{
    constexpr int BM = 64, BN = 64, BK = 16;
    __shared__ float As[BK][BM];
    __shared__ float Bs[BK][BN];
    const int tid = threadIdx.x;
    const int brow = blockIdx.y * BM;
    const int bcol = blockIdx.x * BN;
    const int tr = (tid / 16) * 4;
    const int tc = (tid % 16) * 4;
    const int lr = tid / 4;
    const int lc = (tid % 4) * 4;
    float acc[4][4] = {};
    for (int k0 = 0; k0 < K; k0 += BK) {
        {
            int ar = brow + lr;
            float4 v = *reinterpret_cast<const float4*>(&A[(long)ar * K + k0 + lc]);
            As[lc + 0][lr] = v.x; As[lc + 1][lr] = v.y; As[lc + 2][lr] = v.z; As[lc + 3][lr] = v.w;
        }
        {
            int wr = bcol + lr;
            float4 v = *reinterpret_cast<const float4*>(&W[(long)wr * K + k0 + lc]);
            Bs[lc + 0][lr] = v.x; Bs[lc + 1][lr] = v.y; Bs[lc + 2][lr] = v.z; Bs[lc + 3][lr] = v.w;
        }
        __syncthreads();
        #pragma unroll
        for (int kk = 0; kk < BK; kk++) {
            float a[4], b[4];
            #pragma unroll
            for (int i = 0; i < 4; i++) a[i] = As[kk][tr + i];
            #pragma unroll
            for (int j = 0; j < 4; j++) b[j] = Bs[kk][tc + j];
            #pragma unroll
            for (int i = 0; i < 4; i++)
                #pragma unroll
                for (int j = 0; j < 4; j++)
                    acc[i][j] = fmaf(a[i], b[j], acc[i][j]);
        }
        __syncthreads();
    }
    #pragma unroll
    for (int i = 0; i < 4; i++) {
        int r = brow + tr + i;
        #pragma unroll
        for (int j = 0; j < 4; j++) {
            int cidx = bcol + tc + j;
            float v = acc[i][j];
            if (BIAS)  v += bias[cidx];
            if (RELU)  v = fmaxf(v, 0.f);
            if (RESID) v += R[(long)r * N + cidx];
            C[(long)r * N + cidx] = v;
        }
    }
}

// ===================== decoder ==============================================
__global__ __launch_bounds__(128)
void decoder_kernel(const float* __restrict__ X, const float* __restrict__ Wd,
                    const float* __restrict__ bd, float* __restrict__ out)
{
    const int b = blockIdx.x;
    const int t = threadIdx.x;
    float s = 0.f;
    #pragma unroll
    for (int j = t; j < HID; j += 128) s += X[(long)b * HID + j] * Wd[j];
    s += __shfl_down_sync(0xffffffffu, s, 16);
    s += __shfl_down_sync(0xffffffffu, s, 8);
    s += __shfl_down_sync(0xffffffffu, s, 4);
    s += __shfl_down_sync(0xffffffffu, s, 2);
    s += __shfl_down_sync(0xffffffffu, s, 1);
    __shared__ float sh[4];
    if ((t & 31) == 0) sh[t >> 5] = s;
    __syncthreads();
    if (t == 0) out[b] = sh[0] + sh[1] + sh[2] + sh[3] + bd[0];
}

// ===================== host launcher ========================================
extern "C" void kernel_launch(void* const* d_in, const int* in_sizes, int n_in,
                              void* d_out, int out_size)
{
    const int*   sizes = (const int*)  d_in[0];
    const float* feat  = (const float*)d_in[1];
    const float* We0   = (const float*)d_in[2];
    const float* be0   = (const float*)d_in[3];
    const float* We1   = (const float*)d_in[4];
    const float* be1   = (const float*)d_in[5];
    const float* Wih   = (const float*)d_in[6];
    const float* bih   = (const float*)d_in[7];
    const float* Whh   = (const float*)d_in[8];
    const float* bhh   = (const float*)d_in[9];
    const float* Wl0   = (const float*)d_in[10];
    const float* bl0   = (const float*)d_in[11];
    const float* Wl1   = (const float*)d_in[12];
    const float* bl1   = (const float*)d_in[13];
    const float* Wd    = (const float*)d_in[14];
    const float* bd    = (const float*)d_in[15];
    float* out = (float*)d_out;

    const int T = in_sizes[1] / IN_DIM;
    const int mt = (T + 127) / 128;

    __half *fh, *x1, *x2, *xp, *we0, *we1, *wihp, *whhp, *hb0, *hb1;
    float *bsum, *hf32, *r0, *r1;
    int* starts;
    cudaGetSymbolAddress((void**)&fh, g_fh);
    cudaGetSymbolAddress((void**)&x1, g_x1);
    cudaGetSymbolAddress((void**)&x2, g_x2);
    cudaGetSymbolAddress((void**)&xp, g_xp);
    cudaGetSymbolAddress((void**)&we0, g_we0);
    cudaGetSymbolAddress((void**)&we1, g_we1);
    cudaGetSymbolAddress((void**)&wihp, g_wihp);
    cudaGetSymbolAddress((void**)&whhp, g_whhp);
    cudaGetSymbolAddress((void**)&bsum, g_bsum);
    {
        __half* hb;
        cudaGetSymbolAddress((void**)&hb, g_hbuf);
        hb0 = hb;
        hb1 = hb + (long)BATCH * HID;
    }
    cudaGetSymbolAddress((void**)&hf32, g_hf32);
    cudaGetSymbolAddress((void**)&r0, g_r0);
    cudaGetSymbolAddress((void**)&r1, g_r1);
    cudaGetSymbolAddress((void**)&starts, g_starts);

    cudaFuncSetAttribute(mm2<1>, cudaFuncAttributeMaxDynamicSharedMemorySize, P_SMEM);
    cudaFuncSetAttribute(mm2<2>, cudaFuncAttributeMaxDynamicSharedMemorySize, P_SMEM);
    cudaFuncSetAttribute(lstm_persist, cudaFuncAttributeMaxDynamicSharedMemorySize, R_SMEM);

    scan_starts_kernel<<<1, BATCH>>>(sizes, starts);
    prep_bsum_kernel<<<(G4H + 255) / 256, 256>>>(bih, bhh, bsum);

    // converts (fp16, single term)
    {
        long n;
        n = (long)T * KP0;
        cvt_kernel<<<(int)((n + 255) / 256), 256>>>(feat, fh, T, IN_DIM, KP0);
        n = (long)HID * KP0;
        cvt_kernel<<<(int)((n + 255) / 256), 256>>>(We0, we0, HID, IN_DIM, KP0);
        n = (long)HID * HID;
        cvt_kernel<<<(int)((n + 255) / 256), 256>>>(We1, we1, HID, HID, HID);
        n = (long)G4H * HID;
        cvt_wperm_kernel<<<(int)((n + 255) / 256), 256>>>(Wih, wihp);
        cvt_wperm_kernel<<<(int)((n + 255) / 256), 256>>>(Whh, whhp);
    }

    // encoder MLP + input projection (gate-permuted)
    mm2<1><<<dim3(HID / 128, mt), 256, P_SMEM>>>(fh, we0, be0, x1, T, HID, KP0);
    mm2<1><<<dim3(HID / 128, mt), 256, P_SMEM>>>(x1, we1, be1, x2, T, HID, HID);
    mm2<2><<<dim3(G4H / 128, mt), 256, P_SMEM>>>(x2, wihp, nullptr, xp, T, G4H, HID);

    // persistent fused recurrence (one kernel, 128 steps, Whh resident in smem)
    lstm_persist<<<RCTAS, 256, R_SMEM>>>(xp, sizes, starts, bsum, whhp, hb0, hb1, hf32);

    // tail
    sgemm_nt<true, true, true><<<dim3(HID / 64, BATCH / 64), 256>>>(hf32, Wl0, bl0, hf32, r0, BATCH, HID, HID);
    sgemm_nt<true, true, true><<<dim3(HID / 64, BATCH / 64), 256>>>(r0,   Wl1, bl1, r0,   r1, BATCH, HID, HID);
    decoder_kernel<<<BATCH, 128>>>(r1, Wd, bd, out);

    (void)n_in; (void)out_size;
}

// round 6
// speedup vs baseline: 4.9339x; 1.1478x over previous
#include <cuda_runtime.h>
#include <cuda_fp16.h>
#include <math.h>
#include <stdint.h>

#define IN_DIM 164
#define KP0    192
#define HID    512
#define G4H    2048
#define BATCH  1024
#define MAXLEN 128
#define MAXT   (BATCH * (MAXLEN - 1))
#define RCTAS  128

// ===================== scratch (static device globals) ======================
__device__ __half g_fh[(long)MAXT * KP0];
__device__ __half g_x1[(long)MAXT * HID];
__device__ __half g_x2[(long)MAXT * HID];
__device__ __half g_xp[(long)MAXT * G4H];            // gate-permuted, fp16
__device__ __half g_we0[HID * KP0];
__device__ __half g_we1[HID * HID];
__device__ __half g_wihp[G4H * HID];                 // row-permuted
__device__ __half g_whhp[G4H * HID];                 // row-permuted
__device__ float  g_bsum[G4H];                       // bih+bhh, permuted
__device__ __half g_hbuf[2][BATCH * HID];
__device__ float  g_hf32[BATCH * HID];
__device__ float  g_r0[BATCH * HID];
__device__ float  g_r1[BATCH * HID];
__device__ int    g_starts[BATCH];
__device__ unsigned g_barg[8];                       // per-mi-group barriers

// ===================== PTX helpers ==========================================
__device__ __forceinline__ uint32_t smem_u32(const void* p) {
    uint32_t a;
    asm("{ .reg .u64 t; cvta.to.shared.u64 t, %1; cvt.u32.u64 %0, t; }" : "=r"(a) : "l"(p));
    return a;
}
__device__ __forceinline__ void cp16(uint32_t dst, const void* src, int sz) {
    asm volatile("cp.async.cg.shared.global [%0], [%1], 16, %2;"
                 :: "r"(dst), "l"(src), "r"(sz));
}
__device__ __forceinline__ void cp_commit() {
    asm volatile("cp.async.commit_group;" ::: "memory");
}
#define CP_WAIT(n) asm volatile("cp.async.wait_group %0;" :: "n"(n) : "memory")

#define LDSM_X4(r, addr) \
    asm volatile("ldmatrix.sync.aligned.m8n8.x4.shared.b16 {%0,%1,%2,%3}, [%4];" \
        : "=r"((r)[0]), "=r"((r)[1]), "=r"((r)[2]), "=r"((r)[3]) : "r"(addr))

#define MMA16816(d, a, b0, b1) \
    asm volatile("mma.sync.aligned.m16n8k16.row.col.f32.f16.f16.f32 " \
        "{%0,%1,%2,%3}, {%4,%5,%6,%7}, {%8,%9}, {%0,%1,%2,%3};" \
        : "+f"((d)[0]), "+f"((d)[1]), "+f"((d)[2]), "+f"((d)[3]) \
        : "r"((a)[0]), "r"((a)[1]), "r"((a)[2]), "r"((a)[3]), "r"(b0), "r"(b1))

#define SWZ128(b) ((b) ^ (((b) >> 3) & 0x70))

__device__ __forceinline__ float rcpa(float x) {
    float y;
    asm("rcp.approx.f32 %0, %1;" : "=f"(y) : "f"(x));
    return y;
}
// fast sigmoid / tanh: MUFU.EX2 + MUFU.RCP, rel err ~1e-6
__device__ __forceinline__ float sigfast(float x)  { return rcpa(1.f + __expf(-x)); }
__device__ __forceinline__ float tanhfast(float x) { return fmaf(2.f, rcpa(1.f + __expf(-2.f * x)), -1.f); }

__device__ __forceinline__ float sigf(float x) { return 1.f / (1.f + expf(-x)); }

// ===================== setup kernels ========================================
__global__ void scan_starts_kernel(const int* __restrict__ sizes, int* __restrict__ starts) {
    __shared__ int s[BATCH];
    int t = threadIdx.x;
    s[t] = sizes[t];
    __syncthreads();
    for (int off = 1; off < BATCH; off <<= 1) {
        int v = (t >= off) ? s[t - off] : 0;
        __syncthreads();
        s[t] += v;
        __syncthreads();
    }
    starts[t] = s[t] - sizes[t];
    if (t < 8) g_barg[t] = 0u;
}

__global__ void prep_bsum_kernel(const float* __restrict__ bih, const float* __restrict__ bhh,
                                 float* __restrict__ bsum) {
    int n = blockIdx.x * blockDim.x + threadIdx.x;
    if (n < G4H) {
        int orig = (n & 3) * HID + (n >> 2);
        bsum[n] = bih[orig] + bhh[orig];
    }
}

__global__ void cvt_kernel(const float* __restrict__ X, __half* __restrict__ out,
                           int M, int K, int Kp) {
    long i = (long)blockIdx.x * blockDim.x + threadIdx.x;
    if (i >= (long)M * Kp) return;
    int r = (int)(i / Kp), cidx = (int)(i % Kp);
    float v = (cidx < K) ? X[(long)r * K + cidx] : 0.f;
    out[i] = __float2half(v);
}

__global__ void cvt_wperm_kernel(const float* __restrict__ W, __half* __restrict__ out) {
    long i = (long)blockIdx.x * blockDim.x + threadIdx.x;
    if (i >= (long)G4H * HID) return;
    int n = (int)(i >> 9), k = (int)(i & 511);
    int orig = (n & 3) * HID + (n >> 2);
    out[i] = __float2half(W[(long)orig * HID + k]);
}

// ===================== fp16 tensor GEMM (parallel section) ==================
#define P_OFF_A  0
#define P_OFF_B  16384
#define P_STAGE  32768
#define P_SMEM   (2 * P_STAGE)

template<int EPI>
__global__ __launch_bounds__(256)
void mm2(const __half* __restrict__ A, const __half* __restrict__ B,
         const float* __restrict__ bias, __half* __restrict__ C,
         int M, int N, int K)
{
    extern __shared__ char smem[];
    const uint32_t sb = smem_u32(smem);
    const int tid  = threadIdx.x;
    const int wid  = tid >> 5;
    const int lane = tid & 31;
    const int warp_m = wid & 3;
    const int warp_n = wid >> 2;

    const int m0 = blockIdx.y * 128;
    const int n0 = blockIdx.x * 128;
    const int nk = K >> 6;

    const int lrow = tid >> 1;
    const int qb = (tid & 1) * 4;
    const int arow = m0 + lrow;
    const int asz = (arow < M) ? 16 : 0;
    const long abase = (long)((arow < M) ? arow : (M - 1)) * K;
    const long bbase = (long)(n0 + lrow) * K;

    uint32_t sw_dst[4];
    #pragma unroll
    for (int i = 0; i < 4; i++)
        sw_dst[i] = (uint32_t)SWZ128(lrow * 128 + (qb + i) * 16);

    {
        #pragma unroll
        for (int i = 0; i < 4; i++) {
            const int q = qb + i;
            const uint32_t d = sb + sw_dst[i];
            cp16(d + P_OFF_A, A + abase + q * 8, asz);
            cp16(d + P_OFF_B, B + bbase + q * 8, 16);
        }
        cp_commit();
    }

    float acc[2][8][4];
    #pragma unroll
    for (int a = 0; a < 2; a++)
        #pragma unroll
        for (int b = 0; b < 8; b++)
            #pragma unroll
            for (int v = 0; v < 4; v++) acc[a][b][v] = 0.f;

    const int a_row = warp_m * 32 + (lane & 15);
    const int a_kq  = (lane >> 4) * 16;
    const int b_row = warp_n * 64 + (lane & 7) + ((lane >> 4) << 3);
    const int b_kq  = ((lane >> 3) & 1) * 16;

    for (int it = 0; it < nk; ++it) {
        const uint32_t cur = sb + (uint32_t)((it & 1) * P_STAGE);
        if (it + 1 < nk) {
            const uint32_t nxt = sb + (uint32_t)(((it + 1) & 1) * P_STAGE);
            const long ka = abase + (long)(it + 1) * 64;
            const long kb = bbase + (long)(it + 1) * 64;
            #pragma unroll
            for (int i = 0; i < 4; i++) {
                const int q = qb + i;
                const uint32_t d = nxt + sw_dst[i];
                cp16(d + P_OFF_A, A + ka + q * 8, asz);
                cp16(d + P_OFF_B, B + kb + q * 8, 16);
            }
            cp_commit();
            CP_WAIT(1);
        } else {
            CP_WAIT(0);
        }
        __syncthreads();

        #pragma unroll
        for (int ks = 0; ks < 4; ks++) {
            const int kbyte = ks * 32;
            uint32_t ah[2][4], bh[4][4];
            #pragma unroll
            for (int mf = 0; mf < 2; mf++) {
                const uint32_t ab = (uint32_t)SWZ128((a_row + mf * 16) * 128 + kbyte + a_kq);
                LDSM_X4(ah[mf], cur + P_OFF_A + ab);
            }
            #pragma unroll
            for (int p = 0; p < 4; p++) {
                const uint32_t bb = (uint32_t)SWZ128((b_row + p * 16) * 128 + kbyte + b_kq);
                LDSM_X4(bh[p], cur + P_OFF_B + bb);
            }
            #pragma unroll
            for (int mf = 0; mf < 2; mf++) {
                #pragma unroll
                for (int p = 0; p < 4; p++) {
                    MMA16816(acc[mf][2 * p],     ah[mf], bh[p][0], bh[p][1]);
                    MMA16816(acc[mf][2 * p + 1], ah[mf], bh[p][2], bh[p][3]);
                }
            }
        }
        __syncthreads();
    }

    const int g  = lane >> 2;
    const int tg = lane & 3;
    #pragma unroll
    for (int mf = 0; mf < 2; mf++) {
        const int r_base = m0 + warp_m * 32 + mf * 16 + g;
        #pragma unroll
        for (int ng = 0; ng < 8; ng++) {
            const int col = n0 + warp_n * 64 + ng * 8 + tg * 2;
            float b0 = 0.f, b1 = 0.f;
            if (EPI == 1) { b0 = bias[col]; b1 = bias[col + 1]; }
            #pragma unroll
            for (int half_i = 0; half_i < 2; half_i++) {
                const int r = r_base + half_i * 8;
                if (r >= M) continue;
                float v0 = acc[mf][ng][2 * half_i]     + b0;
                float v1 = acc[mf][ng][2 * half_i + 1] + b1;
                if (EPI == 1) { v0 = fmaxf(v0, 0.f); v1 = fmaxf(v1, 0.f); }
                __half2 h2 = __floats2half2_rn(v0, v1);
                *(uint32_t*)(C + (long)r * N + col) = *(uint32_t*)&h2;
            }
        }
    }
}

// ===================== persistent fused LSTM recurrence =====================
// 128 CTAs: mi = bid/16 (128-row batch tile), ni = bid%16 (128-col gate tile).
// Whh slice resident in smem; 3-stage A pipeline (1 sync/chunk); per-mi-group
// barrier (16 CTAs); fast MUFU gates; h staged in smem -> coalesced stores.
#define R_SM_B   0
#define R_SM_A   131072
#define R_STAGE  16384
#define R_SM_H   (R_SM_A + 3 * R_STAGE)       // 180224
#define R_SMEM   (R_SM_H + 8192)              // 188416

__global__ __launch_bounds__(256, 1)
void lstm_persist(const __half* __restrict__ xp,
                  const int* __restrict__ sizes, const int* __restrict__ starts,
                  const float* __restrict__ bsum,
                  const __half* __restrict__ Whh,
                  __half* __restrict__ hbuf0, __half* __restrict__ hbuf1,
                  float* __restrict__ hf32)
{
    extern __shared__ char smem[];
    const uint32_t sb = smem_u32(smem);
    const int tid  = threadIdx.x;
    const int wid  = tid >> 5;
    const int lane = tid & 31;
    const int warp_m = wid & 3;
    const int warp_n = wid >> 2;
    const int mi = blockIdx.x >> 4;
    const int ni = blockIdx.x & 15;
    const int m0 = mi * 128;
    const int n0 = ni * 128;

    const int lrow = tid >> 1;
    const int qb = (tid & 1) * 4;
    const long abase = (long)(m0 + lrow) * HID;
    const long bbase = (long)(n0 + lrow) * HID;

    uint32_t sw_dst[4];
    #pragma unroll
    for (int i = 0; i < 4; i++)
        sw_dst[i] = (uint32_t)SWZ128(lrow * 128 + (qb + i) * 16);

    // ---- preload resident Whh slice: 8 K-chunks x 16KB (1 commit group) ----
    #pragma unroll
    for (int it = 0; it < 8; it++) {
        #pragma unroll
        for (int i = 0; i < 4; i++) {
            const int q = qb + i;
            cp16(sb + R_SM_B + it * 16384 + sw_dst[i], Whh + bbase + it * 64 + q * 8, 16);
        }
    }
    cp_commit();

    const int a_row = warp_m * 32 + (lane & 15);
    const int a_kq  = (lane >> 4) * 16;
    const int b_row = warp_n * 64 + (lane & 7) + ((lane >> 4) << 3);
    const int b_kq  = ((lane >> 3) & 1) * 16;

    const int g  = lane >> 2;
    const int tg = lane & 3;
    const int col_base = n0 + warp_n * 64 + tg * 2;

    int rr[2][2], sz_r[2][2], st_r[2][2];
    #pragma unroll
    for (int mf = 0; mf < 2; mf++)
        #pragma unroll
        for (int hf = 0; hf < 2; hf++) {
            int r = m0 + warp_m * 32 + mf * 16 + g + 8 * hf;
            rr[mf][hf] = r;
            sz_r[mf][hf] = sizes[r];
            st_r[mf][hf] = starts[r];
        }

    // bias pairs preloaded to registers
    float bs0[8], bs1[8];
    #pragma unroll
    for (int ng = 0; ng < 8; ng++) {
        bs0[ng] = bsum[col_base + ng * 8];
        bs1[ng] = bsum[col_base + ng * 8 + 1];
    }

    float c_reg[2][8][2];
    #pragma unroll
    for (int mf = 0; mf < 2; mf++)
        #pragma unroll
        for (int ng = 0; ng < 8; ng++)
            #pragma unroll
            for (int hf = 0; hf < 2; hf++) c_reg[mf][ng][hf] = 0.f;

    __half* bufs[2] = { hbuf0, hbuf1 };
    __half* hstage = (__half*)(smem + R_SM_H);

    for (int t = 0; t < MAXLEN; t++) {
        float acc[2][8][4];
        #pragma unroll
        for (int a = 0; a < 2; a++)
            #pragma unroll
            for (int b = 0; b < 8; b++)
                #pragma unroll
                for (int v = 0; v < 4; v++) acc[a][b][v] = 0.f;

        if (t > 0) {
            const __half* hr = bufs[(t + 1) & 1];   // written at step t-1
            // issue chunks 0,1 into stages 0,1
            #pragma unroll
            for (int c = 0; c < 2; c++) {
                const long ka = abase + (long)c * 64;
                #pragma unroll
                for (int i = 0; i < 4; i++) {
                    const int q = qb + i;
                    cp16(sb + R_SM_A + (uint32_t)(c * R_STAGE) + sw_dst[i], hr + ka + q * 8, 16);
                }
                cp_commit();
            }

            int s_cur = 0, s_pf = 2;
            for (int it = 0; it < 8; ++it) {
                if (it < 7) { CP_WAIT(1); } else { CP_WAIT(0); }
                __syncthreads();
                if (it + 2 < 8) {
                    const long ka = abase + (long)(it + 2) * 64;
                    const uint32_t dstb = sb + R_SM_A + (uint32_t)(s_pf * R_STAGE);
                    #pragma unroll
                    for (int i = 0; i < 4; i++) {
                        const int q = qb + i;
                        cp16(dstb + sw_dst[i], hr + ka + q * 8, 16);
                    }
                    cp_commit();
                    s_pf = (s_pf == 2) ? 0 : s_pf + 1;
                }

                const uint32_t curA = sb + R_SM_A + (uint32_t)(s_cur * R_STAGE);
                const uint32_t curB = sb + R_SM_B + (uint32_t)(it * 16384);
                #pragma unroll
                for (int ks = 0; ks < 4; ks++) {
                    const int kbyte = ks * 32;
                    uint32_t ah[2][4], bh[4][4];
                    #pragma unroll
                    for (int mf = 0; mf < 2; mf++) {
                        const uint32_t ab = (uint32_t)SWZ128((a_row + mf * 16) * 128 + kbyte + a_kq);
                        LDSM_X4(ah[mf], curA + ab);
                    }
                    #pragma unroll
                    for (int p = 0; p < 4; p++) {
                        const uint32_t bb = (uint32_t)SWZ128((b_row + p * 16) * 128 + kbyte + b_kq);
                        LDSM_X4(bh[p], curB + bb);
                    }
                    #pragma unroll
                    for (int mf = 0; mf < 2; mf++) {
                        #pragma unroll
                        for (int p = 0; p < 4; p++) {
                            MMA16816(acc[mf][2 * p],     ah[mf], bh[p][0], bh[p][1]);
                            MMA16816(acc[mf][2 * p + 1], ah[mf], bh[p][2], bh[p][3]);
                        }
                    }
                }
                s_cur = (s_cur == 2) ? 0 : s_cur + 1;
            }
        }

        // ---- fused gate epilogue -> smem stage ----
        #pragma unroll
        for (int mf = 0; mf < 2; mf++) {
            #pragma unroll
            for (int hf = 0; hf < 2; hf++) {
                const bool act = (t < sz_r[mf][hf]);
                const __half* xrow = xp + (long)(st_r[mf][hf] + t) * G4H;
                #pragma unroll
                for (int ng = 0; ng < 8; ng++) {
                    const int col = col_base + ng * 8;
                    float p0 = acc[mf][ng][2 * hf]     + bs0[ng];
                    float p1 = acc[mf][ng][2 * hf + 1] + bs1[ng];
                    if (act) {
                        __half2 x2 = *(const __half2*)(xrow + col);
                        float2 xf = __half22float2(x2);
                        p0 += xf.x;
                        p1 += xf.y;
                    }
                    const float q0 = __shfl_xor_sync(0xffffffffu, p0, 1);
                    const float q1 = __shfl_xor_sync(0xffffffffu, p1, 1);
                    if ((tg & 1) == 0) {
                        // p0=i, p1=f, q0=g, q1=o
                        float cc = sigfast(p1) * c_reg[mf][ng][hf] + sigfast(p0) * tanhfast(q0);
                        c_reg[mf][ng][hf] = cc;
                        float hv = sigfast(q1) * tanhfast(cc);
                        const int rloc = warp_m * 32 + mf * 16 + g + 8 * hf;
                        const int jloc = warp_n * 16 + (tg >> 1) + ng * 2;
                        hstage[rloc * 32 + jloc] = __float2half(hv);
                    }
                }
            }
        }
        __syncthreads();

        // ---- coalesced h store from stage ----
        {
            __half* hw = bufs[t & 1];
            const int row = tid >> 1;
            const int off = (tid & 1) * 16;
            const __half* sp = hstage + row * 32 + off;
            uint4 v0 = *(const uint4*)(sp);
            uint4 v1 = *(const uint4*)(sp + 8);
            __half* dst = hw + (long)(m0 + row) * HID + ni * 32 + off;
            *(uint4*)dst = v0;
            *(uint4*)(dst + 8) = v1;
            if (t == MAXLEN - 1) {
                float* fd = hf32 + (long)(m0 + row) * HID + ni * 32 + off;
                #pragma unroll
                for (int k2 = 0; k2 < 16; k2++) fd[k2] = __half2float(sp[k2]);
            }
        }

        // ---- per-group barrier (16 CTAs sharing mi) ----
        if (t < MAXLEN - 1) {
            __syncthreads();
            if (tid == 0) {
                __threadfence();
                atomicAdd(&g_barg[mi], 1u);
                const unsigned target = 16u * (unsigned)(t + 1);
                while (*(volatile unsigned*)&g_barg[mi] < target) { __nanosleep(64); }
                __threadfence();
            }
            __syncthreads();
        }
    }
}

// ===================== fp32 SGEMM (tail) ====================================
template<bool RELU, bool RESID, bool BIAS>
__global__ __launch_bounds__(256)
void sgemm_nt(const float* __restrict__ A, const float* __restrict__ W,
              const float* __restrict__ bias, const float* __restrict__ R,
              float* __restrict__ C, int M, int N, int K)
{
    constexpr int BM = 64, BN = 64, BK = 16;
    __shared__ float As[BK][BM];
    __shared__ float Bs[BK][BN];
    const int tid = threadIdx.x;
    const int brow = blockIdx.y * BM;
    const int bcol = blockIdx.x * BN;
    const int tr = (tid / 16) * 4;
    const int tc = (tid % 16) * 4;
    const int lr = tid / 4;
    const int lc = (tid % 4) * 4;
    float acc[4][4] = {};
    for (int k0 = 0; k0 < K; k0 += BK) {
        {
            int ar = brow + lr;
            float4 v = *reinterpret_cast<const float4*>(&A[(long)ar * K + k0 + lc]);
            As[lc + 0][lr] = v.x; As[lc + 1][lr] = v.y; As[lc + 2][lr] = v.z; As[lc + 3][lr] = v.w;
        }
        {
            int wr = bcol + lr;
            float4 v = *reinterpret_cast<const float4*>(&W[(long)wr * K + k0 + lc]);
            Bs[lc + 0][lr] = v.x; Bs[lc + 1][lr] = v.y; Bs[lc + 2][lr] = v.z; Bs[lc + 3][lr] = v.w;
        }
        __syncthreads();
        #pragma unroll
        for (int kk = 0; kk < BK; kk++) {
            float a[4], b[4];
            #pragma unroll
            for (int i = 0; i < 4; i++) a[i] = As[kk][tr + i];
            #pragma unroll
            for (int j = 0; j < 4; j++) b[j] = Bs[kk][tc + j];
            #pragma unroll
            for (int i = 0; i < 4; i++)
                #pragma unroll
                for (int j = 0; j < 4; j++)
                    acc[i][j] = fmaf(a[i], b[j], acc[i][j]);
        }
        __syncthreads();
    }
    #pragma unroll
    for (int i = 0; i < 4; i++) {
        int r = brow + tr + i;
        #pragma unroll
        for (int j = 0; j < 4; j++) {
            int cidx = bcol + tc + j;
            float v = acc[i][j];
            if (BIAS)  v += bias[cidx];
            if (RELU)  v = fmaxf(v, 0.f);
            if (RESID) v += R[(long)r * N + cidx];
            C[(long)r * N + cidx] = v;
        }
    }
}

// ===================== decoder ==============================================
__global__ __launch_bounds__(128)
void decoder_kernel(const float* __restrict__ X, const float* __restrict__ Wd,
                    const float* __restrict__ bd, float* __restrict__ out)
{
    const int b = blockIdx.x;
    const int t = threadIdx.x;
    float s = 0.f;
    #pragma unroll
    for (int j = t; j < HID; j += 128) s += X[(long)b * HID + j] * Wd[j];
    s += __shfl_down_sync(0xffffffffu, s, 16);
    s += __shfl_down_sync(0xffffffffu, s, 8);
    s += __shfl_down_sync(0xffffffffu, s, 4);
    s += __shfl_down_sync(0xffffffffu, s, 2);
    s += __shfl_down_sync(0xffffffffu, s, 1);
    __shared__ float sh[4];
    if ((t & 31) == 0) sh[t >> 5] = s;
    __syncthreads();
    if (t == 0) out[b] = sh[0] + sh[1] + sh[2] + sh[3] + bd[0];
}

// ===================== host launcher ========================================
extern "C" void kernel_launch(void* const* d_in, const int* in_sizes, int n_in,
                              void* d_out, int out_size)
{
    const int*   sizes = (const int*)  d_in[0];
    const float* feat  = (const float*)d_in[1];
    const float* We0   = (const float*)d_in[2];
    const float* be0   = (const float*)d_in[3];
    const float* We1   = (const float*)d_in[4];
    const float* be1   = (const float*)d_in[5];
    const float* Wih   = (const float*)d_in[6];
    const float* bih   = (const float*)d_in[7];
    const float* Whh   = (const float*)d_in[8];
    const float* bhh   = (const float*)d_in[9];
    const float* Wl0   = (const float*)d_in[10];
    const float* bl0   = (const float*)d_in[11];
    const float* Wl1   = (const float*)d_in[12];
    const float* bl1   = (const float*)d_in[13];
    const float* Wd    = (const float*)d_in[14];
    const float* bd    = (const float*)d_in[15];
    float* out = (float*)d_out;

    const int T = in_sizes[1] / IN_DIM;
    const int mt = (T + 127) / 128;

    __half *fh, *x1, *x2, *xp, *we0, *we1, *wihp, *whhp, *hb0, *hb1;
    float *bsum, *hf32, *r0, *r1;
    int* starts;
    cudaGetSymbolAddress((void**)&fh, g_fh);
    cudaGetSymbolAddress((void**)&x1, g_x1);
    cudaGetSymbolAddress((void**)&x2, g_x2);
    cudaGetSymbolAddress((void**)&xp, g_xp);
    cudaGetSymbolAddress((void**)&we0, g_we0);
    cudaGetSymbolAddress((void**)&we1, g_we1);
    cudaGetSymbolAddress((void**)&wihp, g_wihp);
    cudaGetSymbolAddress((void**)&whhp, g_whhp);
    cudaGetSymbolAddress((void**)&bsum, g_bsum);
    {
        __half* hb;
        cudaGetSymbolAddress((void**)&hb, g_hbuf);
        hb0 = hb;
        hb1 = hb + (long)BATCH * HID;
    }
    cudaGetSymbolAddress((void**)&hf32, g_hf32);
    cudaGetSymbolAddress((void**)&r0, g_r0);
    cudaGetSymbolAddress((void**)&r1, g_r1);
    cudaGetSymbolAddress((void**)&starts, g_starts);

    cudaFuncSetAttribute(mm2<1>, cudaFuncAttributeMaxDynamicSharedMemorySize, P_SMEM);
    cudaFuncSetAttribute(mm2<2>, cudaFuncAttributeMaxDynamicSharedMemorySize, P_SMEM);
    cudaFuncSetAttribute(lstm_persist, cudaFuncAttributeMaxDynamicSharedMemorySize, R_SMEM);

    scan_starts_kernel<<<1, BATCH>>>(sizes, starts);
    prep_bsum_kernel<<<(G4H + 255) / 256, 256>>>(bih, bhh, bsum);

    // converts (fp16)
    {
        long n;
        n = (long)T * KP0;
        cvt_kernel<<<(int)((n + 255) / 256), 256>>>(feat, fh, T, IN_DIM, KP0);
        n = (long)HID * KP0;
        cvt_kernel<<<(int)((n + 255) / 256), 256>>>(We0, we0, HID, IN_DIM, KP0);
        n = (long)HID * HID;
        cvt_kernel<<<(int)((n + 255) / 256), 256>>>(We1, we1, HID, HID, HID);
        n = (long)G4H * HID;
        cvt_wperm_kernel<<<(int)((n + 255) / 256), 256>>>(Wih, wihp);
        cvt_wperm_kernel<<<(int)((n + 255) / 256), 256>>>(Whh, whhp);
    }

    // encoder MLP + input projection (gate-permuted)
    mm2<1><<<dim3(HID / 128, mt), 256, P_SMEM>>>(fh, we0, be0, x1, T, HID, KP0);
    mm2<1><<<dim3(HID / 128, mt), 256, P_SMEM>>>(x1, we1, be1, x2, T, HID, HID);
    mm2<2><<<dim3(G4H / 128, mt), 256, P_SMEM>>>(x2, wihp, nullptr, xp, T, G4H, HID);

    // persistent fused recurrence
    lstm_persist<<<RCTAS, 256, R_SMEM>>>(xp, sizes, starts, bsum, whhp, hb0, hb1, hf32);

    // tail
    sgemm_nt<true, true, true><<<dim3(HID / 64, BATCH / 64), 256>>>(hf32, Wl0, bl0, hf32, r0, BATCH, HID, HID);
    sgemm_nt<true, true, true><<<dim3(HID / 64, BATCH / 64), 256>>>(r0,   Wl1, bl1, r0,   r1, BATCH, HID, HID);
    decoder_kernel<<<BATCH, 128>>>(r1, Wd, bd, out);

    (void)n_in; (void)out_size;
}

// round 7
// speedup vs baseline: 6.8646x; 1.3913x over previous
#include <cuda_runtime.h>
#include <cuda_fp16.h>
#include <math.h>
#include <stdint.h>

#define IN_DIM 164
#define KP0    192
#define HID    512
#define G4H    2048
#define BATCH  1024
#define MAXLEN 128
#define MAXT   (BATCH * (MAXLEN - 1))
#define RCTAS  128

// ===================== scratch (static device globals) ======================
__device__ __half g_fh[(long)MAXT * KP0];
__device__ __half g_x1[(long)MAXT * HID];
__device__ __half g_x2[(long)MAXT * HID];
__device__ __half g_xp[(long)MAXT * G4H];            // gate-permuted, fp16
__device__ __half g_we0[HID * KP0];
__device__ __half g_we1[HID * HID];
__device__ __half g_wihp[G4H * HID];                 // row-permuted
__device__ __half g_whhp[G4H * HID];                 // row-permuted
__device__ float  g_bsum[G4H];                       // bih+bhh, permuted
__device__ __half g_hbuf[2][BATCH * HID];
__device__ float  g_hf32[BATCH * HID];
__device__ float  g_r0[BATCH * HID];
__device__ float  g_r1[BATCH * HID];
__device__ int    g_starts[BATCH];
__device__ unsigned g_barg[8];                       // per-mi-group barriers

// ===================== PTX helpers ==========================================
__device__ __forceinline__ uint32_t smem_u32(const void* p) {
    uint32_t a;
    asm("{ .reg .u64 t; cvta.to.shared.u64 t, %1; cvt.u32.u64 %0, t; }" : "=r"(a) : "l"(p));
    return a;
}
__device__ __forceinline__ void cp16(uint32_t dst, const void* src, int sz) {
    asm volatile("cp.async.cg.shared.global [%0], [%1], 16, %2;"
                 :: "r"(dst), "l"(src), "r"(sz));
}
__device__ __forceinline__ void cp_commit() {
    asm volatile("cp.async.commit_group;" ::: "memory");
}
#define CP_WAIT(n) asm volatile("cp.async.wait_group %0;" :: "n"(n) : "memory")

#define LDSM_X4(r, addr) \
    asm volatile("ldmatrix.sync.aligned.m8n8.x4.shared.b16 {%0,%1,%2,%3}, [%4];" \
        : "=r"((r)[0]), "=r"((r)[1]), "=r"((r)[2]), "=r"((r)[3]) : "r"(addr))

#define MMA16816(d, a, b0, b1) \
    asm volatile("mma.sync.aligned.m16n8k16.row.col.f32.f16.f16.f32 " \
        "{%0,%1,%2,%3}, {%4,%5,%6,%7}, {%8,%9}, {%0,%1,%2,%3};" \
        : "+f"((d)[0]), "+f"((d)[1]), "+f"((d)[2]), "+f"((d)[3]) \
        : "r"((a)[0]), "r"((a)[1]), "r"((a)[2]), "r"((a)[3]), "r"(b0), "r"(b1))

#define SWZ128(b) ((b) ^ (((b) >> 3) & 0x70))

// hardware tanh (MUFU.TANH) + sigmoid via tanh
__device__ __forceinline__ float tanha(float x) {
    float y;
    asm("tanh.approx.f32 %0, %1;" : "=f"(y) : "f"(x));
    return y;
}
__device__ __forceinline__ float siga(float x) {
    return fmaf(0.5f, tanha(0.5f * x), 0.5f);
}

// ===================== setup kernels ========================================
__global__ void scan_starts_kernel(const int* __restrict__ sizes, int* __restrict__ starts) {
    __shared__ int s[BATCH];
    int t = threadIdx.x;
    s[t] = sizes[t];
    __syncthreads();
    for (int off = 1; off < BATCH; off <<= 1) {
        int v = (t >= off) ? s[t - off] : 0;
        __syncthreads();
        s[t] += v;
        __syncthreads();
    }
    starts[t] = s[t] - sizes[t];
    if (t < 8) g_barg[t] = 0u;
}

__global__ void prep_bsum_kernel(const float* __restrict__ bih, const float* __restrict__ bhh,
                                 float* __restrict__ bsum) {
    int n = blockIdx.x * blockDim.x + threadIdx.x;
    if (n < G4H) {
        int orig = (n & 3) * HID + (n >> 2);
        bsum[n] = bih[orig] + bhh[orig];
    }
}

__global__ void cvt_kernel(const float* __restrict__ X, __half* __restrict__ out,
                           int M, int K, int Kp) {
    long i = (long)blockIdx.x * blockDim.x + threadIdx.x;
    if (i >= (long)M * Kp) return;
    int r = (int)(i / Kp), cidx = (int)(i % Kp);
    float v = (cidx < K) ? X[(long)r * K + cidx] : 0.f;
    out[i] = __float2half(v);
}

__global__ void cvt_wperm_kernel(const float* __restrict__ W, __half* __restrict__ out) {
    long i = (long)blockIdx.x * blockDim.x + threadIdx.x;
    if (i >= (long)G4H * HID) return;
    int n = (int)(i >> 9), k = (int)(i & 511);
    int orig = (n & 3) * HID + (n >> 2);
    out[i] = __float2half(W[(long)orig * HID + k]);
}

// ===================== fp16 tensor GEMM (parallel section) ==================
#define P_OFF_A  0
#define P_OFF_B  16384
#define P_STAGE  32768
#define P_SMEM   (2 * P_STAGE)

template<int EPI>
__global__ __launch_bounds__(256)
void mm2(const __half* __restrict__ A, const __half* __restrict__ B,
         const float* __restrict__ bias, __half* __restrict__ C,
         int M, int N, int K)
{
    extern __shared__ char smem[];
    const uint32_t sb = smem_u32(smem);
    const int tid  = threadIdx.x;
    const int wid  = tid >> 5;
    const int lane = tid & 31;
    const int warp_m = wid & 3;
    const int warp_n = wid >> 2;

    const int m0 = blockIdx.y * 128;
    const int n0 = blockIdx.x * 128;
    const int nk = K >> 6;

    const int lrow = tid >> 1;
    const int qb = (tid & 1) * 4;
    const int arow = m0 + lrow;
    const int asz = (arow < M) ? 16 : 0;
    const long abase = (long)((arow < M) ? arow : (M - 1)) * K;
    const long bbase = (long)(n0 + lrow) * K;

    uint32_t sw_dst[4];
    #pragma unroll
    for (int i = 0; i < 4; i++)
        sw_dst[i] = (uint32_t)SWZ128(lrow * 128 + (qb + i) * 16);

    {
        #pragma unroll
        for (int i = 0; i < 4; i++) {
            const int q = qb + i;
            const uint32_t d = sb + sw_dst[i];
            cp16(d + P_OFF_A, A + abase + q * 8, asz);
            cp16(d + P_OFF_B, B + bbase + q * 8, 16);
        }
        cp_commit();
    }

    float acc[2][8][4];
    #pragma unroll
    for (int a = 0; a < 2; a++)
        #pragma unroll
        for (int b = 0; b < 8; b++)
            #pragma unroll
            for (int v = 0; v < 4; v++) acc[a][b][v] = 0.f;

    const int a_row = warp_m * 32 + (lane & 15);
    const int a_kq  = (lane >> 4) * 16;
    const int b_row = warp_n * 64 + (lane & 7) + ((lane >> 4) << 3);
    const int b_kq  = ((lane >> 3) & 1) * 16;

    for (int it = 0; it < nk; ++it) {
        const uint32_t cur = sb + (uint32_t)((it & 1) * P_STAGE);
        if (it + 1 < nk) {
            const uint32_t nxt = sb + (uint32_t)(((it + 1) & 1) * P_STAGE);
            const long ka = abase + (long)(it + 1) * 64;
            const long kb = bbase + (long)(it + 1) * 64;
            #pragma unroll
            for (int i = 0; i < 4; i++) {
                const int q = qb + i;
                const uint32_t d = nxt + sw_dst[i];
                cp16(d + P_OFF_A, A + ka + q * 8, asz);
                cp16(d + P_OFF_B, B + kb + q * 8, 16);
            }
            cp_commit();
            CP_WAIT(1);
        } else {
            CP_WAIT(0);
        }
        __syncthreads();

        #pragma unroll
        for (int ks = 0; ks < 4; ks++) {
            const int kbyte = ks * 32;
            uint32_t ah[2][4], bh[4][4];
            #pragma unroll
            for (int mf = 0; mf < 2; mf++) {
                const uint32_t ab = (uint32_t)SWZ128((a_row + mf * 16) * 128 + kbyte + a_kq);
                LDSM_X4(ah[mf], cur + P_OFF_A + ab);
            }
            #pragma unroll
            for (int p = 0; p < 4; p++) {
                const uint32_t bb = (uint32_t)SWZ128((b_row + p * 16) * 128 + kbyte + b_kq);
                LDSM_X4(bh[p], cur + P_OFF_B + bb);
            }
            #pragma unroll
            for (int mf = 0; mf < 2; mf++) {
                #pragma unroll
                for (int p = 0; p < 4; p++) {
                    MMA16816(acc[mf][2 * p],     ah[mf], bh[p][0], bh[p][1]);
                    MMA16816(acc[mf][2 * p + 1], ah[mf], bh[p][2], bh[p][3]);
                }
            }
        }
        __syncthreads();
    }

    const int g  = lane >> 2;
    const int tg = lane & 3;
    #pragma unroll
    for (int mf = 0; mf < 2; mf++) {
        const int r_base = m0 + warp_m * 32 + mf * 16 + g;
        #pragma unroll
        for (int ng = 0; ng < 8; ng++) {
            const int col = n0 + warp_n * 64 + ng * 8 + tg * 2;
            float b0 = 0.f, b1 = 0.f;
            if (EPI == 1) { b0 = bias[col]; b1 = bias[col + 1]; }
            #pragma unroll
            for (int half_i = 0; half_i < 2; half_i++) {
                const int r = r_base + half_i * 8;
                if (r >= M) continue;
                float v0 = acc[mf][ng][2 * half_i]     + b0;
                float v1 = acc[mf][ng][2 * half_i + 1] + b1;
                if (EPI == 1) { v0 = fmaxf(v0, 0.f); v1 = fmaxf(v1, 0.f); }
                __half2 h2 = __floats2half2_rn(v0, v1);
                *(uint32_t*)(C + (long)r * N + col) = *(uint32_t*)&h2;
            }
        }
    }
}

// ===================== persistent fused LSTM recurrence =====================
// 128 CTAs: mi = bid/16 (128-row batch tile), ni = bid%16 (128-col gate tile).
// Whh slice resident in smem; 3-stage A pipeline; xp tile staged in smem via
// cp.async overlapped with MMA; MUFU.TANH gates; per-mi-group barrier.
#define R_SM_B   0
#define R_SM_A   131072
#define R_STAGE  16384
#define R_SM_XP  (R_SM_A + 3 * R_STAGE)      // 180224
#define XP_PITCH 272                          // 256B row + 16B pad (bank spread)
#define R_SM_H   (R_SM_XP + 128 * XP_PITCH)  // 215040
#define R_SMEM   (R_SM_H + 8192)             // 223232

__global__ __launch_bounds__(256, 1)
void lstm_persist(const __half* __restrict__ xp,
                  const int* __restrict__ sizes, const int* __restrict__ starts,
                  const float* __restrict__ bsum,
                  const __half* __restrict__ Whh,
                  __half* __restrict__ hbuf0, __half* __restrict__ hbuf1,
                  float* __restrict__ hf32)
{
    extern __shared__ char smem[];
    const uint32_t sb = smem_u32(smem);
    const int tid  = threadIdx.x;
    const int wid  = tid >> 5;
    const int lane = tid & 31;
    const int warp_m = wid & 3;
    const int warp_n = wid >> 2;
    const int mi = blockIdx.x >> 4;
    const int ni = blockIdx.x & 15;
    const int m0 = mi * 128;
    const int n0 = ni * 128;

    const int lrow = tid >> 1;
    const int qb = (tid & 1) * 4;
    const long abase = (long)(m0 + lrow) * HID;
    const long bbase = (long)(n0 + lrow) * HID;

    uint32_t sw_dst[4];
    #pragma unroll
    for (int i = 0; i < 4; i++)
        sw_dst[i] = (uint32_t)SWZ128(lrow * 128 + (qb + i) * 16);

    // ---- preload resident Whh slice: 8 K-chunks x 16KB (1 commit group) ----
    #pragma unroll
    for (int it = 0; it < 8; it++) {
        #pragma unroll
        for (int i = 0; i < 4; i++) {
            const int q = qb + i;
            cp16(sb + R_SM_B + it * 16384 + sw_dst[i], Whh + bbase + it * 64 + q * 8, 16);
        }
    }
    cp_commit();

    const int a_row = warp_m * 32 + (lane & 15);
    const int a_kq  = (lane >> 4) * 16;
    const int b_row = warp_n * 64 + (lane & 7) + ((lane >> 4) << 3);
    const int b_kq  = ((lane >> 3) & 1) * 16;

    const int g  = lane >> 2;
    const int tg = lane & 3;
    const int col_base = n0 + warp_n * 64 + tg * 2;

    // loader-row gather info (for xp prefetch): row m0 + tid/2
    const int st_row = starts[m0 + (tid >> 1)];
    const int sz_row = sizes[m0 + (tid >> 1)];
    const uint32_t xdst = sb + R_SM_XP + (uint32_t)((tid >> 1) * XP_PITCH + (tid & 1) * 128);

    // bias pairs preloaded to registers
    float bs0[8], bs1[8];
    #pragma unroll
    for (int ng = 0; ng < 8; ng++) {
        bs0[ng] = bsum[col_base + ng * 8];
        bs1[ng] = bsum[col_base + ng * 8 + 1];
    }

    float c_reg[2][8][2];
    #pragma unroll
    for (int mf = 0; mf < 2; mf++)
        #pragma unroll
        for (int ng = 0; ng < 8; ng++)
            #pragma unroll
            for (int hf = 0; hf < 2; hf++) c_reg[mf][ng][hf] = 0.f;

    __half* bufs[2] = { hbuf0, hbuf1 };
    __half* hstage = (__half*)(smem + R_SM_H);

    for (int t = 0; t < MAXLEN; t++) {
        // ---- issue xp prefetch for THIS step (consumed in epilogue) ----
        {
            const int xsz = (t < sz_row) ? 16 : 0;
            const __half* xg = xp + ((long)(st_row + t) * G4H + n0 + (tid & 1) * 64);
            #pragma unroll
            for (int q = 0; q < 8; q++)
                cp16(xdst + q * 16, xg + q * 8, xsz);
            cp_commit();
        }

        float acc[2][8][4];
        #pragma unroll
        for (int a = 0; a < 2; a++)
            #pragma unroll
            for (int b = 0; b < 8; b++)
                #pragma unroll
                for (int v = 0; v < 4; v++) acc[a][b][v] = 0.f;

        if (t > 0) {
            const __half* hr = bufs[(t + 1) & 1];   // written at step t-1
            // issue chunks 0,1 into stages 0,1
            #pragma unroll
            for (int c = 0; c < 2; c++) {
                const long ka = abase + (long)c * 64;
                #pragma unroll
                for (int i = 0; i < 4; i++) {
                    const int q = qb + i;
                    cp16(sb + R_SM_A + (uint32_t)(c * R_STAGE) + sw_dst[i], hr + ka + q * 8, 16);
                }
                cp_commit();
            }

            int s_cur = 0, s_pf = 2;
            for (int it = 0; it < 8; ++it) {
                if (it < 7) { CP_WAIT(1); } else { CP_WAIT(0); }
                __syncthreads();
                if (it + 2 < 8) {
                    const long ka = abase + (long)(it + 2) * 64;
                    const uint32_t dstb = sb + R_SM_A + (uint32_t)(s_pf * R_STAGE);
                    #pragma unroll
                    for (int i = 0; i < 4; i++) {
                        const int q = qb + i;
                        cp16(dstb + sw_dst[i], hr + ka + q * 8, 16);
                    }
                    cp_commit();
                    s_pf = (s_pf == 2) ? 0 : s_pf + 1;
                }

                const uint32_t curA = sb + R_SM_A + (uint32_t)(s_cur * R_STAGE);
                const uint32_t curB = sb + R_SM_B + (uint32_t)(it * 16384);
                #pragma unroll
                for (int ks = 0; ks < 4; ks++) {
                    const int kbyte = ks * 32;
                    uint32_t ah[2][4], bh[4][4];
                    #pragma unroll
                    for (int mf = 0; mf < 2; mf++) {
                        const uint32_t ab = (uint32_t)SWZ128((a_row + mf * 16) * 128 + kbyte + a_kq);
                        LDSM_X4(ah[mf], curA + ab);
                    }
                    #pragma unroll
                    for (int p = 0; p < 4; p++) {
                        const uint32_t bb = (uint32_t)SWZ128((b_row + p * 16) * 128 + kbyte + b_kq);
                        LDSM_X4(bh[p], curB + bb);
                    }
                    #pragma unroll
                    for (int mf = 0; mf < 2; mf++) {
                        #pragma unroll
                        for (int p = 0; p < 4; p++) {
                            MMA16816(acc[mf][2 * p],     ah[mf], bh[p][0], bh[p][1]);
                            MMA16816(acc[mf][2 * p + 1], ah[mf], bh[p][2], bh[p][3]);
                        }
                    }
                }
                s_cur = (s_cur == 2) ? 0 : s_cur + 1;
            }
        } else {
            // t == 0: no MMA; just drain xp (+ resident Whh group) and sync
            CP_WAIT(0);
            __syncthreads();
        }

        // ---- fused gate epilogue (xp from smem) -> smem stage ----
        #pragma unroll
        for (int mf = 0; mf < 2; mf++) {
            #pragma unroll
            for (int hf = 0; hf < 2; hf++) {
                const int rloc = warp_m * 32 + mf * 16 + g + 8 * hf;
                const char* xrow_s = smem + R_SM_XP + rloc * XP_PITCH
                                   + (warp_n * 64 + tg * 2) * 2;
                #pragma unroll
                for (int ng = 0; ng < 8; ng++) {
                    __half2 x2 = *(const __half2*)(xrow_s + ng * 16);
                    float2 xf = __half22float2(x2);
                    float p0 = acc[mf][ng][2 * hf]     + bs0[ng] + xf.x;
                    float p1 = acc[mf][ng][2 * hf + 1] + bs1[ng] + xf.y;
                    const float q0 = __shfl_xor_sync(0xffffffffu, p0, 1);
                    const float q1 = __shfl_xor_sync(0xffffffffu, p1, 1);
                    if ((tg & 1) == 0) {
                        // p0=i, p1=f, q0=g, q1=o
                        float cc = siga(p1) * c_reg[mf][ng][hf] + siga(p0) * tanha(q0);
                        c_reg[mf][ng][hf] = cc;
                        float hv = siga(q1) * tanha(cc);
                        const int jloc = warp_n * 16 + (tg >> 1) + ng * 2;
                        hstage[rloc * 32 + jloc] = __float2half(hv);
                    }
                }
            }
        }
        __syncthreads();

        // ---- coalesced h store from stage ----
        {
            __half* hw = bufs[t & 1];
            const int row = tid >> 1;
            const int off = (tid & 1) * 16;
            const __half* sp = hstage + row * 32 + off;
            uint4 v0 = *(const uint4*)(sp);
            uint4 v1 = *(const uint4*)(sp + 8);
            __half* dst = hw + (long)(m0 + row) * HID + ni * 32 + off;
            *(uint4*)dst = v0;
            *(uint4*)(dst + 8) = v1;
            if (t == MAXLEN - 1) {
                float* fd = hf32 + (long)(m0 + row) * HID + ni * 32 + off;
                #pragma unroll
                for (int k2 = 0; k2 < 16; k2++) fd[k2] = __half2float(sp[k2]);
            }
        }

        // ---- per-group barrier (16 CTAs sharing mi) ----
        if (t < MAXLEN - 1) {
            __syncthreads();
            if (tid == 0) {
                __threadfence();
                atomicAdd(&g_barg[mi], 1u);
                const unsigned target = 16u * (unsigned)(t + 1);
                while (*(volatile unsigned*)&g_barg[mi] < target) { __nanosleep(64); }
                __threadfence();
            }
            __syncthreads();
        }
    }
}

// ===================== fp32 SGEMM (tail) ====================================
template<bool RELU, bool RESID, bool BIAS>
__global__ __launch_bounds__(256)
void sgemm_nt(const float* __restrict__ A, const float* __restrict__ W,
              const float* __restrict__ bias, const float* __restrict__ R,
              float* __restrict__ C, int M, int N, int K)
{
    constexpr int BM = 64, BN = 64, BK = 16;
    __shared__ float As[BK][BM];
    __shared__ float Bs[BK][BN];
    const int tid = threadIdx.x;
    const int brow = blockIdx.y * BM;
    const int bcol = blockIdx.x * BN;
    const int tr = (tid / 16) * 4;
    const int tc = (tid % 16) * 4;
    const int lr = tid / 4;
    const int lc = (tid % 4) * 4;
    float acc[4][4] = {};
    for (int k0 = 0; k0 < K; k0 += BK) {
        {
            int ar = brow + lr;
            float4 v = *reinterpret_cast<const float4*>(&A[(long)ar * K + k0 + lc]);
            As[lc + 0][lr] = v.x; As[lc + 1][lr] = v.y; As[lc + 2][lr] = v.z; As[lc + 3][lr] = v.w;
        }
        {
            int wr = bcol + lr;
            float4 v = *reinterpret_cast<const float4*>(&W[(long)wr * K + k0 + lc]);
            Bs[lc + 0][lr] = v.x; Bs[lc + 1][lr] = v.y; Bs[lc + 2][lr] = v.z; Bs[lc + 3][lr] = v.w;
        }
        __syncthreads();
        #pragma unroll
        for (int kk = 0; kk < BK; kk++) {
            float a[4], b[4];
            #pragma unroll
            for (int i = 0; i < 4; i++) a[i] = As[kk][tr + i];
            #pragma unroll
            for (int j = 0; j < 4; j++) b[j] = Bs[kk][tc + j];
            #pragma unroll
            for (int i = 0; i < 4; i++)
                #pragma unroll
                for (int j = 0; j < 4; j++)
                    acc[i][j] = fmaf(a[i], b[j], acc[i][j]);
        }
        __syncthreads();
    }
    #pragma unroll
    for (int i = 0; i < 4; i++) {
        int r = brow + tr + i;
        #pragma unroll
        for (int j = 0; j < 4; j++) {
            int cidx = bcol + tc + j;
            float v = acc[i][j];
            if (BIAS)  v += bias[cidx];
            if (RELU)  v = fmaxf(v, 0.f);
            if (RESID) v += R[(long)r * N + cidx];
            C[(long)r * N + cidx] = v;
        }
    }
}

// ===================== decoder ==============================================
__global__ __launch_bounds__(128)
void decoder_kernel(const float* __restrict__ X, const float* __restrict__ Wd,
                    const float* __restrict__ bd, float* __restrict__ out)
{
    const int b = blockIdx.x;
    const int t = threadIdx.x;
    float s = 0.f;
    #pragma unroll
    for (int j = t; j < HID; j += 128) s += X[(long)b * HID + j] * Wd[j];
    s += __shfl_down_sync(0xffffffffu, s, 16);
    s += __shfl_down_sync(0xffffffffu, s, 8);
    s += __shfl_down_sync(0xffffffffu, s, 4);
    s += __shfl_down_sync(0xffffffffu, s, 2);
    s += __shfl_down_sync(0xffffffffu, s, 1);
    __shared__ float sh[4];
    if ((t & 31) == 0) sh[t >> 5] = s;
    __syncthreads();
    if (t == 0) out[b] = sh[0] + sh[1] + sh[2] + sh[3] + bd[0];
}

// ===================== host launcher ========================================
extern "C" void kernel_launch(void* const* d_in, const int* in_sizes, int n_in,
                              void* d_out, int out_size)
{
    const int*   sizes = (const int*)  d_in[0];
    const float* feat  = (const float*)d_in[1];
    const float* We0   = (const float*)d_in[2];
    const float* be0   = (const float*)d_in[3];
    const float* We1   = (const float*)d_in[4];
    const float* be1   = (const float*)d_in[5];
    const float* Wih   = (const float*)d_in[6];
    const float* bih   = (const float*)d_in[7];
    const float* Whh   = (const float*)d_in[8];
    const float* bhh   = (const float*)d_in[9];
    const float* Wl0   = (const float*)d_in[10];
    const float* bl0   = (const float*)d_in[11];
    const float* Wl1   = (const float*)d_in[12];
    const float* bl1   = (const float*)d_in[13];
    const float* Wd    = (const float*)d_in[14];
    const float* bd    = (const float*)d_in[15];
    float* out = (float*)d_out;

    const int T = in_sizes[1] / IN_DIM;
    const int mt = (T + 127) / 128;

    __half *fh, *x1, *x2, *xp, *we0, *we1, *wihp, *whhp, *hb0, *hb1;
    float *bsum, *hf32, *r0, *r1;
    int* starts;
    cudaGetSymbolAddress((void**)&fh, g_fh);
    cudaGetSymbolAddress((void**)&x1, g_x1);
    cudaGetSymbolAddress((void**)&x2, g_x2);
    cudaGetSymbolAddress((void**)&xp, g_xp);
    cudaGetSymbolAddress((void**)&we0, g_we0);
    cudaGetSymbolAddress((void**)&we1, g_we1);
    cudaGetSymbolAddress((void**)&wihp, g_wihp);
    cudaGetSymbolAddress((void**)&whhp, g_whhp);
    cudaGetSymbolAddress((void**)&bsum, g_bsum);
    {
        __half* hb;
        cudaGetSymbolAddress((void**)&hb, g_hbuf);
        hb0 = hb;
        hb1 = hb + (long)BATCH * HID;
    }
    cudaGetSymbolAddress((void**)&hf32, g_hf32);
    cudaGetSymbolAddress((void**)&r0, g_r0);
    cudaGetSymbolAddress((void**)&r1, g_r1);
    cudaGetSymbolAddress((void**)&starts, g_starts);

    cudaFuncSetAttribute(mm2<1>, cudaFuncAttributeMaxDynamicSharedMemorySize, P_SMEM);
    cudaFuncSetAttribute(mm2<2>, cudaFuncAttributeMaxDynamicSharedMemorySize, P_SMEM);
    cudaFuncSetAttribute(lstm_persist, cudaFuncAttributeMaxDynamicSharedMemorySize, R_SMEM);

    scan_starts_kernel<<<1, BATCH>>>(sizes, starts);
    prep_bsum_kernel<<<(G4H + 255) / 256, 256>>>(bih, bhh, bsum);

    // converts (fp16)
    {
        long n;
        n = (long)T * KP0;
        cvt_kernel<<<(int)((n + 255) / 256), 256>>>(feat, fh, T, IN_DIM, KP0);
        n = (long)HID * KP0;
        cvt_kernel<<<(int)((n + 255) / 256), 256>>>(We0, we0, HID, IN_DIM, KP0);
        n = (long)HID * HID;
        cvt_kernel<<<(int)((n + 255) / 256), 256>>>(We1, we1, HID, HID, HID);
        n = (long)G4H * HID;
        cvt_wperm_kernel<<<(int)((n + 255) / 256), 256>>>(Wih, wihp);
        cvt_wperm_kernel<<<(int)((n + 255) / 256), 256>>>(Whh, whhp);
    }

    // encoder MLP + input projection (gate-permuted)
    mm2<1><<<dim3(HID / 128, mt), 256, P_SMEM>>>(fh, we0, be0, x1, T, HID, KP0);
    mm2<1><<<dim3(HID / 128, mt), 256, P_SMEM>>>(x1, we1, be1, x2, T, HID, HID);
    mm2<2><<<dim3(G4H / 128, mt), 256, P_SMEM>>>(x2, wihp, nullptr, xp, T, G4H, HID);

    // persistent fused recurrence
    lstm_persist<<<RCTAS, 256, R_SMEM>>>(xp, sizes, starts, bsum, whhp, hb0, hb1, hf32);

    // tail
    sgemm_nt<true, true, true><<<dim3(HID / 64, BATCH / 64), 256>>>(hf32, Wl0, bl0, hf32, r0, BATCH, HID, HID);
    sgemm_nt<true, true, true><<<dim3(HID / 64, BATCH / 64), 256>>>(r0,   Wl1, bl1, r0,   r1, BATCH, HID, HID);
    decoder_kernel<<<BATCH, 128>>>(r1, Wd, bd, out);

    (void)n_in; (void)out_size;
}

// round 8
// speedup vs baseline: 7.6364x; 1.1124x over previous
#include <cuda_runtime.h>
#include <cuda_fp16.h>
#include <math.h>
#include <stdint.h>

#define IN_DIM 164
#define KP0    192
#define HID    512
#define G4H    2048
#define BATCH  1024
#define MAXLEN 128
#define MAXT   (BATCH * (MAXLEN - 1))
#define RCTAS  128

// Gate permutation (fragment-aligned): permuted row n holds original row
// g*512 + U with  s=n>>6, a=(n>>4)&3, b2=(n>>3)&1, tg=(n>>1)&3, b=n&1,
// U = s*16 + a*4 + tg,  g = b2*2 + b.
// => in the epilogue, thread tg owns ALL 4 gates of its units (no shuffles).

// ===================== scratch (static device globals) ======================
__device__ __half g_fh[(long)MAXT * KP0];
__device__ __half g_x1[(long)MAXT * HID];
__device__ __half g_x2[(long)MAXT * HID];
__device__ __half g_xp[(long)MAXT * G4H];            // gate-permuted, fp16
__device__ __half g_we0[HID * KP0];
__device__ __half g_we1[HID * HID];
__device__ __half g_wihp[G4H * HID];                 // row-permuted
__device__ __half g_whhp[G4H * HID];                 // row-permuted
__device__ float  g_bsum[G4H];                       // bih+bhh, permuted
__device__ __half g_hbuf[2][BATCH * HID];
__device__ float  g_hf32[BATCH * HID];
__device__ float  g_r0[BATCH * HID];
__device__ float  g_r1[BATCH * HID];
__device__ int    g_starts[BATCH];
__device__ unsigned g_barg[8];                       // per-mi-group barriers

// ===================== PTX helpers ==========================================
__device__ __forceinline__ uint32_t smem_u32(const void* p) {
    uint32_t a;
    asm("{ .reg .u64 t; cvta.to.shared.u64 t, %1; cvt.u32.u64 %0, t; }" : "=r"(a) : "l"(p));
    return a;
}
__device__ __forceinline__ void cp16(uint32_t dst, const void* src, int sz) {
    asm volatile("cp.async.cg.shared.global [%0], [%1], 16, %2;"
                 :: "r"(dst), "l"(src), "r"(sz));
}
__device__ __forceinline__ void cp_commit() {
    asm volatile("cp.async.commit_group;" ::: "memory");
}
#define CP_WAIT(n) asm volatile("cp.async.wait_group %0;" :: "n"(n) : "memory")

#define LDSM_X4(r, addr) \
    asm volatile("ldmatrix.sync.aligned.m8n8.x4.shared.b16 {%0,%1,%2,%3}, [%4];" \
        : "=r"((r)[0]), "=r"((r)[1]), "=r"((r)[2]), "=r"((r)[3]) : "r"(addr))

#define MMA16816(d, a, b0, b1) \
    asm volatile("mma.sync.aligned.m16n8k16.row.col.f32.f16.f16.f32 " \
        "{%0,%1,%2,%3}, {%4,%5,%6,%7}, {%8,%9}, {%0,%1,%2,%3};" \
        : "+f"((d)[0]), "+f"((d)[1]), "+f"((d)[2]), "+f"((d)[3]) \
        : "r"((a)[0]), "r"((a)[1]), "r"((a)[2]), "r"((a)[3]), "r"(b0), "r"(b1))

#define SWZ128(b) ((b) ^ (((b) >> 3) & 0x70))

// hardware tanh (MUFU.TANH) + sigmoid via tanh
__device__ __forceinline__ float tanha(float x) {
    float y;
    asm("tanh.approx.f32 %0, %1;" : "=f"(y) : "f"(x));
    return y;
}
__device__ __forceinline__ float siga(float x) {
    return fmaf(0.5f, tanha(0.5f * x), 0.5f);
}

// ===================== setup kernels ========================================
__global__ void scan_starts_kernel(const int* __restrict__ sizes, int* __restrict__ starts) {
    __shared__ int s[BATCH];
    int t = threadIdx.x;
    s[t] = sizes[t];
    __syncthreads();
    for (int off = 1; off < BATCH; off <<= 1) {
        int v = (t >= off) ? s[t - off] : 0;
        __syncthreads();
        s[t] += v;
        __syncthreads();
    }
    starts[t] = s[t] - sizes[t];
    if (t < 8) g_barg[t] = 0u;
}

__device__ __forceinline__ int perm_orig_row(int n) {
    int s  = n >> 6;
    int a  = (n >> 4) & 3;
    int b2 = (n >> 3) & 1;
    int tg = (n >> 1) & 3;
    int b  = n & 1;
    int U  = s * 16 + a * 4 + tg;
    int gg = b2 * 2 + b;
    return gg * 512 + U;
}

__global__ void prep_bsum_kernel(const float* __restrict__ bih, const float* __restrict__ bhh,
                                 float* __restrict__ bsum) {
    int n = blockIdx.x * blockDim.x + threadIdx.x;
    if (n < G4H) {
        int orig = perm_orig_row(n);
        bsum[n] = bih[orig] + bhh[orig];
    }
}

__global__ void cvt_kernel(const float* __restrict__ X, __half* __restrict__ out,
                           int M, int K, int Kp) {
    long i = (long)blockIdx.x * blockDim.x + threadIdx.x;
    if (i >= (long)M * Kp) return;
    int r = (int)(i / Kp), cidx = (int)(i % Kp);
    float v = (cidx < K) ? X[(long)r * K + cidx] : 0.f;
    out[i] = __float2half(v);
}

__global__ void cvt_wperm_kernel(const float* __restrict__ W, __half* __restrict__ out) {
    long i = (long)blockIdx.x * blockDim.x + threadIdx.x;
    if (i >= (long)G4H * HID) return;
    int n = (int)(i >> 9), k = (int)(i & 511);
    int orig = perm_orig_row(n);
    out[i] = __float2half(W[(long)orig * HID + k]);
}

// ===================== fp16 tensor GEMM (parallel section) ==================
#define P_OFF_A  0
#define P_OFF_B  16384
#define P_STAGE  32768
#define P_SMEM   (2 * P_STAGE)

template<int EPI>
__global__ __launch_bounds__(256, 2)
void mm2(const __half* __restrict__ A, const __half* __restrict__ B,
         const float* __restrict__ bias, __half* __restrict__ C,
         int M, int N, int K)
{
    extern __shared__ char smem[];
    const uint32_t sb = smem_u32(smem);
    const int tid  = threadIdx.x;
    const int wid  = tid >> 5;
    const int lane = tid & 31;
    const int warp_m = wid & 3;
    const int warp_n = wid >> 2;

    const int m0 = blockIdx.y * 128;
    const int n0 = blockIdx.x * 128;
    const int nk = K >> 6;

    const int lrow = tid >> 1;
    const int qb = (tid & 1) * 4;
    const int arow = m0 + lrow;
    const int asz = (arow < M) ? 16 : 0;
    const long abase = (long)((arow < M) ? arow : (M - 1)) * K;
    const long bbase = (long)(n0 + lrow) * K;

    uint32_t sw_dst[4];
    #pragma unroll
    for (int i = 0; i < 4; i++)
        sw_dst[i] = (uint32_t)SWZ128(lrow * 128 + (qb + i) * 16);

    {
        #pragma unroll
        for (int i = 0; i < 4; i++) {
            const int q = qb + i;
            const uint32_t d = sb + sw_dst[i];
            cp16(d + P_OFF_A, A + abase + q * 8, asz);
            cp16(d + P_OFF_B, B + bbase + q * 8, 16);
        }
        cp_commit();
    }

    float acc[2][8][4];
    #pragma unroll
    for (int a = 0; a < 2; a++)
        #pragma unroll
        for (int b = 0; b < 8; b++)
            #pragma unroll
            for (int v = 0; v < 4; v++) acc[a][b][v] = 0.f;

    const int a_row = warp_m * 32 + (lane & 15);
    const int a_kq  = (lane >> 4) * 16;
    const int b_row = warp_n * 64 + (lane & 7) + ((lane >> 4) << 3);
    const int b_kq  = ((lane >> 3) & 1) * 16;

    for (int it = 0; it < nk; ++it) {
        const uint32_t cur = sb + (uint32_t)((it & 1) * P_STAGE);
        if (it + 1 < nk) {
            const uint32_t nxt = sb + (uint32_t)(((it + 1) & 1) * P_STAGE);
            const long ka = abase + (long)(it + 1) * 64;
            const long kb = bbase + (long)(it + 1) * 64;
            #pragma unroll
            for (int i = 0; i < 4; i++) {
                const int q = qb + i;
                const uint32_t d = nxt + sw_dst[i];
                cp16(d + P_OFF_A, A + ka + q * 8, asz);
                cp16(d + P_OFF_B, B + kb + q * 8, 16);
            }
            cp_commit();
            CP_WAIT(1);
        } else {
            CP_WAIT(0);
        }
        __syncthreads();

        #pragma unroll
        for (int ks = 0; ks < 4; ks++) {
            const int kbyte = ks * 32;
            uint32_t ah[2][4], bh[4][4];
            #pragma unroll
            for (int mf = 0; mf < 2; mf++) {
                const uint32_t ab = (uint32_t)SWZ128((a_row + mf * 16) * 128 + kbyte + a_kq);
                LDSM_X4(ah[mf], cur + P_OFF_A + ab);
            }
            #pragma unroll
            for (int p = 0; p < 4; p++) {
                const uint32_t bb = (uint32_t)SWZ128((b_row + p * 16) * 128 + kbyte + b_kq);
                LDSM_X4(bh[p], cur + P_OFF_B + bb);
            }
            #pragma unroll
            for (int mf = 0; mf < 2; mf++) {
                #pragma unroll
                for (int p = 0; p < 4; p++) {
                    MMA16816(acc[mf][2 * p],     ah[mf], bh[p][0], bh[p][1]);
                    MMA16816(acc[mf][2 * p + 1], ah[mf], bh[p][2], bh[p][3]);
                }
            }
        }
        __syncthreads();
    }

    const int g  = lane >> 2;
    const int tg = lane & 3;
    #pragma unroll
    for (int mf = 0; mf < 2; mf++) {
        const int r_base = m0 + warp_m * 32 + mf * 16 + g;
        #pragma unroll
        for (int ng = 0; ng < 8; ng++) {
            const int col = n0 + warp_n * 64 + ng * 8 + tg * 2;
            float b0 = 0.f, b1 = 0.f;
            if (EPI == 1) { b0 = bias[col]; b1 = bias[col + 1]; }
            #pragma unroll
            for (int half_i = 0; half_i < 2; half_i++) {
                const int r = r_base + half_i * 8;
                if (r >= M) continue;
                float v0 = acc[mf][ng][2 * half_i]     + b0;
                float v1 = acc[mf][ng][2 * half_i + 1] + b1;
                if (EPI == 1) { v0 = fmaxf(v0, 0.f); v1 = fmaxf(v1, 0.f); }
                __half2 h2 = __floats2half2_rn(v0, v1);
                *(uint32_t*)(C + (long)r * N + col) = *(uint32_t*)&h2;
            }
        }
    }
}

// ===================== persistent fused LSTM recurrence =====================
#define R_SM_B   0
#define R_SM_A   131072
#define R_STAGE  16384
#define R_SM_XP  (R_SM_A + 3 * R_STAGE)      // 180224
#define XP_PITCH 272
#define R_SM_H   (R_SM_XP + 128 * XP_PITCH)  // 215040
#define R_SMEM   (R_SM_H + 8192)             // 223232

__global__ __launch_bounds__(256, 1)
void lstm_persist(const __half* __restrict__ xp,
                  const int* __restrict__ sizes, const int* __restrict__ starts,
                  const float* __restrict__ bsum,
                  const __half* __restrict__ Whh,
                  __half* __restrict__ hbuf0, __half* __restrict__ hbuf1,
                  float* __restrict__ hf32)
{
    extern __shared__ char smem[];
    const uint32_t sb = smem_u32(smem);
    const int tid  = threadIdx.x;
    const int wid  = tid >> 5;
    const int lane = tid & 31;
    const int warp_m = wid & 3;
    const int warp_n = wid >> 2;
    const int mi = blockIdx.x >> 4;
    const int ni = blockIdx.x & 15;
    const int m0 = mi * 128;
    const int n0 = ni * 128;

    const int lrow = tid >> 1;
    const int qb = (tid & 1) * 4;
    const long abase = (long)(m0 + lrow) * HID;
    const long bbase = (long)(n0 + lrow) * HID;

    uint32_t sw_dst[4];
    #pragma unroll
    for (int i = 0; i < 4; i++)
        sw_dst[i] = (uint32_t)SWZ128(lrow * 128 + (qb + i) * 16);

    // ---- preload resident Whh slice ----
    #pragma unroll
    for (int it = 0; it < 8; it++) {
        #pragma unroll
        for (int i = 0; i < 4; i++) {
            const int q = qb + i;
            cp16(sb + R_SM_B + it * 16384 + sw_dst[i], Whh + bbase + it * 64 + q * 8, 16);
        }
    }
    cp_commit();

    const int a_row = warp_m * 32 + (lane & 15);
    const int a_kq  = (lane >> 4) * 16;
    const int b_row = warp_n * 64 + (lane & 7) + ((lane >> 4) << 3);
    const int b_kq  = ((lane >> 3) & 1) * 16;

    const int g  = lane >> 2;
    const int tg = lane & 3;
    const int col_base = n0 + warp_n * 64 + tg * 2;

    const int st_row = starts[m0 + (tid >> 1)];
    const int sz_row = sizes[m0 + (tid >> 1)];
    const uint32_t xdst = sb + R_SM_XP + (uint32_t)((tid >> 1) * XP_PITCH + (tid & 1) * 128);

    float bs0[8], bs1[8];
    #pragma unroll
    for (int ng = 0; ng < 8; ng++) {
        bs0[ng] = bsum[col_base + ng * 8];
        bs1[ng] = bsum[col_base + ng * 8 + 1];
    }

    float c_reg[2][4][2];
    #pragma unroll
    for (int mf = 0; mf < 2; mf++)
        #pragma unroll
        for (int a = 0; a < 4; a++)
            #pragma unroll
            for (int hf = 0; hf < 2; hf++) c_reg[mf][a][hf] = 0.f;

    __half* bufs[2] = { hbuf0, hbuf1 };
    __half* hstage = (__half*)(smem + R_SM_H);

    for (int t = 0; t < MAXLEN; t++) {
        // ---- xp prefetch for THIS step ----
        {
            const int xsz = (t < sz_row) ? 16 : 0;
            const __half* xg = xp + ((long)(st_row + t) * G4H + n0 + (tid & 1) * 64);
            #pragma unroll
            for (int q = 0; q < 8; q++)
                cp16(xdst + q * 16, xg + q * 8, xsz);
            cp_commit();
        }

        float acc[2][8][4];
        #pragma unroll
        for (int a = 0; a < 2; a++)
            #pragma unroll
            for (int b = 0; b < 8; b++)
                #pragma unroll
                for (int v = 0; v < 4; v++) acc[a][b][v] = 0.f;

        if (t > 0) {
            const __half* hr = bufs[(t + 1) & 1];
            #pragma unroll
            for (int c = 0; c < 2; c++) {
                const long ka = abase + (long)c * 64;
                #pragma unroll
                for (int i = 0; i < 4; i++) {
                    const int q = qb + i;
                    cp16(sb + R_SM_A + (uint32_t)(c * R_STAGE) + sw_dst[i], hr + ka + q * 8, 16);
                }
                cp_commit();
            }

            int s_cur = 0, s_pf = 2;
            for (int it = 0; it < 8; ++it) {
                if (it < 7) { CP_WAIT(1); } else { CP_WAIT(0); }
                __syncthreads();
                if (it + 2 < 8) {
                    const long ka = abase + (long)(it + 2) * 64;
                    const uint32_t dstb = sb + R_SM_A + (uint32_t)(s_pf * R_STAGE);
                    #pragma unroll
                    for (int i = 0; i < 4; i++) {
                        const int q = qb + i;
                        cp16(dstb + sw_dst[i], hr + ka + q * 8, 16);
                    }
                    cp_commit();
                    s_pf = (s_pf == 2) ? 0 : s_pf + 1;
                }

                const uint32_t curA = sb + R_SM_A + (uint32_t)(s_cur * R_STAGE);
                const uint32_t curB = sb + R_SM_B + (uint32_t)(it * 16384);
                #pragma unroll
                for (int ks = 0; ks < 4; ks++) {
                    const int kbyte = ks * 32;
                    uint32_t ah[2][4], bh[4][4];
                    #pragma unroll
                    for (int mf = 0; mf < 2; mf++) {
                        const uint32_t ab = (uint32_t)SWZ128((a_row + mf * 16) * 128 + kbyte + a_kq);
                        LDSM_X4(ah[mf], curA + ab);
                    }
                    #pragma unroll
                    for (int p = 0; p < 4; p++) {
                        const uint32_t bb = (uint32_t)SWZ128((b_row + p * 16) * 128 + kbyte + b_kq);
                        LDSM_X4(bh[p], curB + bb);
                    }
                    #pragma unroll
                    for (int mf = 0; mf < 2; mf++) {
                        #pragma unroll
                        for (int p = 0; p < 4; p++) {
                            MMA16816(acc[mf][2 * p],     ah[mf], bh[p][0], bh[p][1]);
                            MMA16816(acc[mf][2 * p + 1], ah[mf], bh[p][2], bh[p][3]);
                        }
                    }
                }
                s_cur = (s_cur == 2) ? 0 : s_cur + 1;
            }
        } else {
            CP_WAIT(0);
            __syncthreads();
        }

        // ---- fused gate epilogue (all gates in-thread; no shuffles) ----
        #pragma unroll
        for (int mf = 0; mf < 2; mf++) {
            #pragma unroll
            for (int hf = 0; hf < 2; hf++) {
                const int rloc = warp_m * 32 + mf * 16 + g + 8 * hf;
                const char* xrow_s = smem + R_SM_XP + rloc * XP_PITCH
                                   + (warp_n * 64 + tg * 2) * 2;
                #pragma unroll
                for (int a = 0; a < 4; a++) {
                    __half2 xif = *(const __half2*)(xrow_s + (2 * a) * 16);
                    __half2 xgo = *(const __half2*)(xrow_s + (2 * a + 1) * 16);
                    float2 fif = __half22float2(xif);
                    float2 fgo = __half22float2(xgo);
                    float gi = acc[mf][2 * a][2 * hf]         + bs0[2 * a]     + fif.x;
                    float gf = acc[mf][2 * a][2 * hf + 1]     + bs1[2 * a]     + fif.y;
                    float gg = acc[mf][2 * a + 1][2 * hf]     + bs0[2 * a + 1] + fgo.x;
                    float go = acc[mf][2 * a + 1][2 * hf + 1] + bs1[2 * a + 1] + fgo.y;
                    float cc = siga(gf) * c_reg[mf][a][hf] + siga(gi) * tanha(gg);
                    c_reg[mf][a][hf] = cc;
                    float hv = siga(go) * tanha(cc);
                    hstage[rloc * 32 + warp_n * 16 + a * 4 + tg] = __float2half(hv);
                }
            }
        }
        __syncthreads();

        // ---- coalesced h store from stage ----
        {
            __half* hw = bufs[t & 1];
            const int row = tid >> 1;
            const int off = (tid & 1) * 16;
            const __half* sp = hstage + row * 32 + off;
            uint4 v0 = *(const uint4*)(sp);
            uint4 v1 = *(const uint4*)(sp + 8);
            __half* dst = hw + (long)(m0 + row) * HID + ni * 32 + off;
            *(uint4*)dst = v0;
            *(uint4*)(dst + 8) = v1;
            if (t == MAXLEN - 1) {
                float* fd = hf32 + (long)(m0 + row) * HID + ni * 32 + off;
                #pragma unroll
                for (int k2 = 0; k2 < 16; k2++) fd[k2] = __half2float(sp[k2]);
            }
        }

        // ---- per-group barrier (release/acquire, no full membar) ----
        if (t < MAXLEN - 1) {
            __syncthreads();
            if (tid == 0) {
                unsigned* bar = &g_barg[mi];
                asm volatile("red.release.gpu.add.u32 [%0], %1;" :: "l"(bar), "r"(1u) : "memory");
                const unsigned target = 16u * (unsigned)(t + 1);
                unsigned v;
                do {
                    asm volatile("ld.acquire.gpu.u32 %0, [%1];" : "=r"(v) : "l"(bar) : "memory");
                    if (v >= target) break;
                    __nanosleep(32);
                } while (1);
            }
            __syncthreads();
        }
    }
}

// ===================== fp32 SGEMM (tail) ====================================
template<bool RELU, bool RESID, bool BIAS>
__global__ __launch_bounds__(256)
void sgemm_nt(const float* __restrict__ A, const float* __restrict__ W,
              const float* __restrict__ bias, const float* __restrict__ R,
              float* __restrict__ C, int M, int N, int K)
{
    constexpr int BM = 64, BN = 64, BK = 16;
    __shared__ float As[BK][BM];
    __shared__ float Bs[BK][BN];
    const int tid = threadIdx.x;
    const int brow = blockIdx.y * BM;
    const int bcol = blockIdx.x * BN;
    const int tr = (tid / 16) * 4;
    const int tc = (tid % 16) * 4;
    const int lr = tid / 4;
    const int lc = (tid % 4) * 4;
    float acc[4][4] = {};
    for (int k0 = 0; k0 < K; k0 += BK) {
        {
            int ar = brow + lr;
            float4 v = *reinterpret_cast<const float4*>(&A[(long)ar * K + k0 + lc]);
            As[lc + 0][lr] = v.x; As[lc + 1][lr] = v.y; As[lc + 2][lr] = v.z; As[lc + 3][lr] = v.w;
        }
        {
            int wr = bcol + lr;
            float4 v = *reinterpret_cast<const float4*>(&W[(long)wr * K + k0 + lc]);
            Bs[lc + 0][lr] = v.x; Bs[lc + 1][lr] = v.y; Bs[lc + 2][lr] = v.z; Bs[lc + 3][lr] = v.w;
        }
        __syncthreads();
        #pragma unroll
        for (int kk = 0; kk < BK; kk++) {
            float a[4], b[4];
            #pragma unroll
            for (int i = 0; i < 4; i++) a[i] = As[kk][tr + i];
            #pragma unroll
            for (int j = 0; j < 4; j++) b[j] = Bs[kk][tc + j];
            #pragma unroll
            for (int i = 0; i < 4; i++)
                #pragma unroll
                for (int j = 0; j < 4; j++)
                    acc[i][j] = fmaf(a[i], b[j], acc[i][j]);
        }
        __syncthreads();
    }
    #pragma unroll
    for (int i = 0; i < 4; i++) {
        int r = brow + tr + i;
        #pragma unroll
        for (int j = 0; j < 4; j++) {
            int cidx = bcol + tc + j;
            float v = acc[i][j];
            if (BIAS)  v += bias[cidx];
            if (RELU)  v = fmaxf(v, 0.f);
            if (RESID) v += R[(long)r * N + cidx];
            C[(long)r * N + cidx] = v;
        }
    }
}

// ===================== decoder ==============================================
__global__ __launch_bounds__(128)
void decoder_kernel(const float* __restrict__ X, const float* __restrict__ Wd,
                    const float* __restrict__ bd, float* __restrict__ out)
{
    const int b = blockIdx.x;
    const int t = threadIdx.x;
    float s = 0.f;
    #pragma unroll
    for (int j = t; j < HID; j += 128) s += X[(long)b * HID + j] * Wd[j];
    s += __shfl_down_sync(0xffffffffu, s, 16);
    s += __shfl_down_sync(0xffffffffu, s, 8);
    s += __shfl_down_sync(0xffffffffu, s, 4);
    s += __shfl_down_sync(0xffffffffu, s, 2);
    s += __shfl_down_sync(0xffffffffu, s, 1);
    __shared__ float sh[4];
    if ((t & 31) == 0) sh[t >> 5] = s;
    __syncthreads();
    if (t == 0) out[b] = sh[0] + sh[1] + sh[2] + sh[3] + bd[0];
}

// ===================== host launcher ========================================
extern "C" void kernel_launch(void* const* d_in, const int* in_sizes, int n_in,
                              void* d_out, int out_size)
{
    const int*   sizes = (const int*)  d_in[0];
    const float* feat  = (const float*)d_in[1];
    const float* We0   = (const float*)d_in[2];
    const float* be0   = (const float*)d_in[3];
    const float* We1   = (const float*)d_in[4];
    const float* be1   = (const float*)d_in[5];
    const float* Wih   = (const float*)d_in[6];
    const float* bih   = (const float*)d_in[7];
    const float* Whh   = (const float*)d_in[8];
    const float* bhh   = (const float*)d_in[9];
    const float* Wl0   = (const float*)d_in[10];
    const float* bl0   = (const float*)d_in[11];
    const float* Wl1   = (const float*)d_in[12];
    const float* bl1   = (const float*)d_in[13];
    const float* Wd    = (const float*)d_in[14];
    const float* bd    = (const float*)d_in[15];
    float* out = (float*)d_out;

    const int T = in_sizes[1] / IN_DIM;
    const int mt = (T + 127) / 128;

    __half *fh, *x1, *x2, *xp, *we0, *we1, *wihp, *whhp, *hb0, *hb1;
    float *bsum, *hf32, *r0, *r1;
    int* starts;
    cudaGetSymbolAddress((void**)&fh, g_fh);
    cudaGetSymbolAddress((void**)&x1, g_x1);
    cudaGetSymbolAddress((void**)&x2, g_x2);
    cudaGetSymbolAddress((void**)&xp, g_xp);
    cudaGetSymbolAddress((void**)&we0, g_we0);
    cudaGetSymbolAddress((void**)&we1, g_we1);
    cudaGetSymbolAddress((void**)&wihp, g_wihp);
    cudaGetSymbolAddress((void**)&whhp, g_whhp);
    cudaGetSymbolAddress((void**)&bsum, g_bsum);
    {
        __half* hb;
        cudaGetSymbolAddress((void**)&hb, g_hbuf);
        hb0 = hb;
        hb1 = hb + (long)BATCH * HID;
    }
    cudaGetSymbolAddress((void**)&hf32, g_hf32);
    cudaGetSymbolAddress((void**)&r0, g_r0);
    cudaGetSymbolAddress((void**)&r1, g_r1);
    cudaGetSymbolAddress((void**)&starts, g_starts);

    cudaFuncSetAttribute(mm2<1>, cudaFuncAttributeMaxDynamicSharedMemorySize, P_SMEM);
    cudaFuncSetAttribute(mm2<2>, cudaFuncAttributeMaxDynamicSharedMemorySize, P_SMEM);
    cudaFuncSetAttribute(lstm_persist, cudaFuncAttributeMaxDynamicSharedMemorySize, R_SMEM);

    scan_starts_kernel<<<1, BATCH>>>(sizes, starts);
    prep_bsum_kernel<<<(G4H + 255) / 256, 256>>>(bih, bhh, bsum);

    // converts (fp16)
    {
        long n;
        n = (long)T * KP0;
        cvt_kernel<<<(int)((n + 255) / 256), 256>>>(feat, fh, T, IN_DIM, KP0);
        n = (long)HID * KP0;
        cvt_kernel<<<(int)((n + 255) / 256), 256>>>(We0, we0, HID, IN_DIM, KP0);
        n = (long)HID * HID;
        cvt_kernel<<<(int)((n + 255) / 256), 256>>>(We1, we1, HID, HID, HID);
        n = (long)G4H * HID;
        cvt_wperm_kernel<<<(int)((n + 255) / 256), 256>>>(Wih, wihp);
        cvt_wperm_kernel<<<(int)((n + 255) / 256), 256>>>(Whh, whhp);
    }

    // encoder MLP + input projection (gate-permuted)
    mm2<1><<<dim3(HID / 128, mt), 256, P_SMEM>>>(fh, we0, be0, x1, T, HID, KP0);
    mm2<1><<<dim3(HID / 128, mt), 256, P_SMEM>>>(x1, we1, be1, x2, T, HID, HID);
    mm2<2><<<dim3(G4H / 128, mt), 256, P_SMEM>>>(x2, wihp, nullptr, xp, T, G4H, HID);

    // persistent fused recurrence
    lstm_persist<<<RCTAS, 256, R_SMEM>>>(xp, sizes, starts, bsum, whhp, hb0, hb1, hf32);

    // tail
    sgemm_nt<true, true, true><<<dim3(HID / 64, BATCH / 64), 256>>>(hf32, Wl0, bl0, hf32, r0, BATCH, HID, HID);
    sgemm_nt<true, true, true><<<dim3(HID / 64, BATCH / 64), 256>>>(r0,   Wl1, bl1, r0,   r1, BATCH, HID, HID);
    decoder_kernel<<<BATCH, 128>>>(r1, Wd, bd, out);

    (void)n_in; (void)out_size;
}

// round 9
// speedup vs baseline: 8.3174x; 1.0892x over previous
#include <cuda_runtime.h>
#include <cuda_fp16.h>
#include <math.h>
#include <stdint.h>

#define IN_DIM 164
#define KP0    192
#define HID    512
#define G4H    2048
#define BATCH  1024
#define MAXLEN 128
#define MAXT   (BATCH * (MAXLEN - 1))
#define RCTAS  128

// Gate permutation (fragment-aligned): permuted row n holds original row
// g*512 + U with  s=n>>6, a=(n>>4)&3, b2=(n>>3)&1, tg=(n>>1)&3, b=n&1,
// U = s*16 + a*4 + tg,  g = b2*2 + b.

// ===================== scratch (static device globals) ======================
__device__ __half g_fh[(long)MAXT * KP0];
__device__ __half g_x1[(long)MAXT * HID];
__device__ __half g_x2[(long)MAXT * HID];
__device__ __half g_xp[(long)MAXT * G4H];            // gate-permuted, fp16
__device__ __half g_we0[HID * KP0];
__device__ __half g_we1[HID * HID];
__device__ __half g_wihp[G4H * HID];                 // row-permuted
__device__ __half g_whhp[G4H * HID];                 // row-permuted
__device__ float  g_bsum[G4H];                       // bih+bhh, permuted
__device__ __half g_hbuf[2][BATCH * HID];
__device__ float  g_hf32[BATCH * HID];
__device__ float  g_r0[BATCH * HID];
__device__ float  g_r1[BATCH * HID];
__device__ int    g_starts[BATCH];
__device__ unsigned g_barg[8];                       // per-mi-group barriers

// ===================== PTX helpers ==========================================
__device__ __forceinline__ uint32_t smem_u32(const void* p) {
    uint32_t a;
    asm("{ .reg .u64 t; cvta.to.shared.u64 t, %1; cvt.u32.u64 %0, t; }" : "=r"(a) : "l"(p));
    return a;
}
__device__ __forceinline__ void cp16(uint32_t dst, const void* src, int sz) {
    asm volatile("cp.async.cg.shared.global [%0], [%1], 16, %2;"
                 :: "r"(dst), "l"(src), "r"(sz));
}
__device__ __forceinline__ void cp_commit() {
    asm volatile("cp.async.commit_group;" ::: "memory");
}
#define CP_WAIT(n) asm volatile("cp.async.wait_group %0;" :: "n"(n) : "memory")

#define LDSM_X4(r, addr) \
    asm volatile("ldmatrix.sync.aligned.m8n8.x4.shared.b16 {%0,%1,%2,%3}, [%4];" \
        : "=r"((r)[0]), "=r"((r)[1]), "=r"((r)[2]), "=r"((r)[3]) : "r"(addr))

#define MMA16816(d, a, b0, b1) \
    asm volatile("mma.sync.aligned.m16n8k16.row.col.f32.f16.f16.f32 " \
        "{%0,%1,%2,%3}, {%4,%5,%6,%7}, {%8,%9}, {%0,%1,%2,%3};" \
        : "+f"((d)[0]), "+f"((d)[1]), "+f"((d)[2]), "+f"((d)[3]) \
        : "r"((a)[0]), "r"((a)[1]), "r"((a)[2]), "r"((a)[3]), "r"(b0), "r"(b1))

#define SWZ128(b) ((b) ^ (((b) >> 3) & 0x70))

// hardware tanh (MUFU.TANH) + sigmoid via tanh
__device__ __forceinline__ float tanha(float x) {
    float y;
    asm("tanh.approx.f32 %0, %1;" : "=f"(y) : "f"(x));
    return y;
}
__device__ __forceinline__ float siga(float x) {
    return fmaf(0.5f, tanha(0.5f * x), 0.5f);
}

// ===================== setup kernels ========================================
__global__ void scan_starts_kernel(const int* __restrict__ sizes, int* __restrict__ starts) {
    __shared__ int s[BATCH];
    int t = threadIdx.x;
    s[t] = sizes[t];
    __syncthreads();
    for (int off = 1; off < BATCH; off <<= 1) {
        int v = (t >= off) ? s[t - off] : 0;
        __syncthreads();
        s[t] += v;
        __syncthreads();
    }
    starts[t] = s[t] - sizes[t];
    if (t < 8) g_barg[t] = 0u;
}

__device__ __forceinline__ int perm_orig_row(int n) {
    int s  = n >> 6;
    int a  = (n >> 4) & 3;
    int b2 = (n >> 3) & 1;
    int tg = (n >> 1) & 3;
    int b  = n & 1;
    int U  = s * 16 + a * 4 + tg;
    int gg = b2 * 2 + b;
    return gg * 512 + U;
}

__global__ void prep_bsum_kernel(const float* __restrict__ bih, const float* __restrict__ bhh,
                                 float* __restrict__ bsum) {
    int n = blockIdx.x * blockDim.x + threadIdx.x;
    if (n < G4H) {
        int orig = perm_orig_row(n);
        bsum[n] = bih[orig] + bhh[orig];
    }
}

__global__ void cvt_kernel(const float* __restrict__ X, __half* __restrict__ out,
                           int M, int K, int Kp) {
    long i = (long)blockIdx.x * blockDim.x + threadIdx.x;
    if (i >= (long)M * Kp) return;
    int r = (int)(i / Kp), cidx = (int)(i % Kp);
    float v = (cidx < K) ? X[(long)r * K + cidx] : 0.f;
    out[i] = __float2half(v);
}

__global__ void cvt_wperm_kernel(const float* __restrict__ W, __half* __restrict__ out) {
    long i = (long)blockIdx.x * blockDim.x + threadIdx.x;
    if (i >= (long)G4H * HID) return;
    int n = (int)(i >> 9), k = (int)(i & 511);
    int orig = perm_orig_row(n);
    out[i] = __float2half(W[(long)orig * HID + k]);
}

// ===================== fp16 tensor GEMM (parallel section) ==================
#define P_OFF_A  0
#define P_OFF_B  16384
#define P_STAGE  32768
#define P_SMEM   (2 * P_STAGE)

template<int EPI>
__global__ __launch_bounds__(256, 2)
void mm2(const __half* __restrict__ A, const __half* __restrict__ B,
         const float* __restrict__ bias, __half* __restrict__ C,
         int M, int N, int K)
{
    extern __shared__ char smem[];
    const uint32_t sb = smem_u32(smem);
    const int tid  = threadIdx.x;
    const int wid  = tid >> 5;
    const int lane = tid & 31;
    const int warp_m = wid & 3;
    const int warp_n = wid >> 2;

    const int m0 = blockIdx.y * 128;
    const int n0 = blockIdx.x * 128;
    const int nk = K >> 6;

    const int lrow = tid >> 1;
    const int qb = (tid & 1) * 4;
    const int arow = m0 + lrow;
    const int asz = (arow < M) ? 16 : 0;
    const long abase = (long)((arow < M) ? arow : (M - 1)) * K;
    const long bbase = (long)(n0 + lrow) * K;

    uint32_t sw_dst[4];
    #pragma unroll
    for (int i = 0; i < 4; i++)
        sw_dst[i] = (uint32_t)SWZ128(lrow * 128 + (qb + i) * 16);

    {
        #pragma unroll
        for (int i = 0; i < 4; i++) {
            const int q = qb + i;
            const uint32_t d = sb + sw_dst[i];
            cp16(d + P_OFF_A, A + abase + q * 8, asz);
            cp16(d + P_OFF_B, B + bbase + q * 8, 16);
        }
        cp_commit();
    }

    float acc[2][8][4];
    #pragma unroll
    for (int a = 0; a < 2; a++)
        #pragma unroll
        for (int b = 0; b < 8; b++)
            #pragma unroll
            for (int v = 0; v < 4; v++) acc[a][b][v] = 0.f;

    const int a_row = warp_m * 32 + (lane & 15);
    const int a_kq  = (lane >> 4) * 16;
    const int b_row = warp_n * 64 + (lane & 7) + ((lane >> 4) << 3);
    const int b_kq  = ((lane >> 3) & 1) * 16;

    for (int it = 0; it < nk; ++it) {
        const uint32_t cur = sb + (uint32_t)((it & 1) * P_STAGE);
        if (it + 1 < nk) {
            const uint32_t nxt = sb + (uint32_t)(((it + 1) & 1) * P_STAGE);
            const long ka = abase + (long)(it + 1) * 64;
            const long kb = bbase + (long)(it + 1) * 64;
            #pragma unroll
            for (int i = 0; i < 4; i++) {
                const int q = qb + i;
                const uint32_t d = nxt + sw_dst[i];
                cp16(d + P_OFF_A, A + ka + q * 8, asz);
                cp16(d + P_OFF_B, B + kb + q * 8, 16);
            }
            cp_commit();
            CP_WAIT(1);
        } else {
            CP_WAIT(0);
        }
        __syncthreads();

        #pragma unroll
        for (int ks = 0; ks < 4; ks++) {
            const int kbyte = ks * 32;
            uint32_t ah[2][4], bh[4][4];
            #pragma unroll
            for (int mf = 0; mf < 2; mf++) {
                const uint32_t ab = (uint32_t)SWZ128((a_row + mf * 16) * 128 + kbyte + a_kq);
                LDSM_X4(ah[mf], cur + P_OFF_A + ab);
            }
            #pragma unroll
            for (int p = 0; p < 4; p++) {
                const uint32_t bb = (uint32_t)SWZ128((b_row + p * 16) * 128 + kbyte + b_kq);
                LDSM_X4(bh[p], cur + P_OFF_B + bb);
            }
            #pragma unroll
            for (int mf = 0; mf < 2; mf++) {
                #pragma unroll
                for (int p = 0; p < 4; p++) {
                    MMA16816(acc[mf][2 * p],     ah[mf], bh[p][0], bh[p][1]);
                    MMA16816(acc[mf][2 * p + 1], ah[mf], bh[p][2], bh[p][3]);
                }
            }
        }
        __syncthreads();
    }

    const int g  = lane >> 2;
    const int tg = lane & 3;
    #pragma unroll
    for (int mf = 0; mf < 2; mf++) {
        const int r_base = m0 + warp_m * 32 + mf * 16 + g;
        #pragma unroll
        for (int ng = 0; ng < 8; ng++) {
            const int col = n0 + warp_n * 64 + ng * 8 + tg * 2;
            float b0 = 0.f, b1 = 0.f;
            if (EPI == 1) { b0 = bias[col]; b1 = bias[col + 1]; }
            #pragma unroll
            for (int half_i = 0; half_i < 2; half_i++) {
                const int r = r_base + half_i * 8;
                if (r >= M) continue;
                float v0 = acc[mf][ng][2 * half_i]     + b0;
                float v1 = acc[mf][ng][2 * half_i + 1] + b1;
                if (EPI == 1) { v0 = fmaxf(v0, 0.f); v1 = fmaxf(v1, 0.f); }
                __half2 h2 = __floats2half2_rn(v0, v1);
                *(uint32_t*)(C + (long)r * N + col) = *(uint32_t*)&h2;
            }
        }
    }
}

// ===================== persistent fused LSTM recurrence =====================
// 128 CTAs x 512 threads (16 warps, warp tile 32x32): mi=bid/16, ni=bid%16.
// Whh slice resident in smem; 3-stage A pipeline; xp staged via cp.async;
// MUFU.TANH gates (all 4 gates in-thread); per-mi-group tight-poll barrier.
#define R_SM_B   0
#define R_SM_A   131072
#define R_STAGE  16384
#define R_SM_XP  (R_SM_A + 3 * R_STAGE)      // 180224
#define XP_PITCH 272
#define R_SM_H   (R_SM_XP + 128 * XP_PITCH)  // 215040
#define R_SMEM   (R_SM_H + 8192)             // 223232

__global__ __launch_bounds__(512, 1)
void lstm_persist(const __half* __restrict__ xp,
                  const int* __restrict__ sizes, const int* __restrict__ starts,
                  const float* __restrict__ bsum,
                  const __half* __restrict__ Whh,
                  __half* __restrict__ hbuf0, __half* __restrict__ hbuf1,
                  float* __restrict__ hf32)
{
    extern __shared__ char smem[];
    const uint32_t sb = smem_u32(smem);
    const int tid  = threadIdx.x;
    const int wid  = tid >> 5;
    const int lane = tid & 31;
    const int warp_m = wid & 3;      // 4 warps along M (32 rows)
    const int warp_n = wid >> 2;     // 4 warps along N (32 cols)
    const int mi = blockIdx.x >> 4;
    const int ni = blockIdx.x & 15;
    const int m0 = mi * 128;
    const int n0 = ni * 128;

    // loaders: 512 threads, thread -> row tid/4, 2 chunks of 16B
    const int lrow = tid >> 2;
    const int qb = (tid & 3) * 2;
    const long abase = (long)(m0 + lrow) * HID;
    const long bbase = (long)(n0 + lrow) * HID;

    uint32_t sw_dst[2];
    #pragma unroll
    for (int i = 0; i < 2; i++)
        sw_dst[i] = (uint32_t)SWZ128(lrow * 128 + (qb + i) * 16);

    // ---- preload resident Whh slice ----
    #pragma unroll
    for (int it = 0; it < 8; it++) {
        #pragma unroll
        for (int i = 0; i < 2; i++) {
            const int q = qb + i;
            cp16(sb + R_SM_B + it * 16384 + sw_dst[i], Whh + bbase + it * 64 + q * 8, 16);
        }
    }
    cp_commit();

    const int a_row = warp_m * 32 + (lane & 15);
    const int a_kq  = (lane >> 4) * 16;
    const int b_row = warp_n * 32 + (lane & 7) + ((lane >> 4) << 3);
    const int b_kq  = ((lane >> 3) & 1) * 16;

    const int g  = lane >> 2;
    const int tg = lane & 3;
    const int col_base = n0 + warp_n * 32 + tg * 2;

    // xp prefetch mapping: thread row tid/4, 4 chunks of 16B at (tid&3)*64
    const int st_row = starts[m0 + (tid >> 2)];
    const int sz_row = sizes[m0 + (tid >> 2)];
    const uint32_t xdst = sb + R_SM_XP + (uint32_t)((tid >> 2) * XP_PITCH + (tid & 3) * 64);

    float bs0[4], bs1[4];
    #pragma unroll
    for (int ng = 0; ng < 4; ng++) {
        bs0[ng] = bsum[col_base + ng * 8];
        bs1[ng] = bsum[col_base + ng * 8 + 1];
    }

    float c_reg[2][2][2];   // [mf][a][hf]
    #pragma unroll
    for (int mf = 0; mf < 2; mf++)
        #pragma unroll
        for (int a = 0; a < 2; a++)
            #pragma unroll
            for (int hf = 0; hf < 2; hf++) c_reg[mf][a][hf] = 0.f;

    __half* bufs[2] = { hbuf0, hbuf1 };
    __half* hstage = (__half*)(smem + R_SM_H);
    const int jbase = (warp_n >> 1) * 16 + (warp_n & 1) * 8 + tg;

    for (int t = 0; t < MAXLEN; t++) {
        // ---- xp prefetch for THIS step ----
        {
            const int xsz = (t < sz_row) ? 16 : 0;
            const __half* xg = xp + ((long)(st_row + t) * G4H + n0 + (tid & 3) * 32);
            #pragma unroll
            for (int q = 0; q < 4; q++)
                cp16(xdst + q * 16, xg + q * 8, xsz);
            cp_commit();
        }

        float acc[2][4][4];
        #pragma unroll
        for (int a = 0; a < 2; a++)
            #pragma unroll
            for (int b = 0; b < 4; b++)
                #pragma unroll
                for (int v = 0; v < 4; v++) acc[a][b][v] = 0.f;

        if (t > 0) {
            const __half* hr = bufs[(t + 1) & 1];
            #pragma unroll
            for (int c = 0; c < 2; c++) {
                const long ka = abase + (long)c * 64;
                #pragma unroll
                for (int i = 0; i < 2; i++) {
                    const int q = qb + i;
                    cp16(sb + R_SM_A + (uint32_t)(c * R_STAGE) + sw_dst[i], hr + ka + q * 8, 16);
                }
                cp_commit();
            }

            int s_cur = 0, s_pf = 2;
            for (int it = 0; it < 8; ++it) {
                if (it < 7) { CP_WAIT(1); } else { CP_WAIT(0); }
                __syncthreads();
                if (it + 2 < 8) {
                    const long ka = abase + (long)(it + 2) * 64;
                    const uint32_t dstb = sb + R_SM_A + (uint32_t)(s_pf * R_STAGE);
                    #pragma unroll
                    for (int i = 0; i < 2; i++) {
                        const int q = qb + i;
                        cp16(dstb + sw_dst[i], hr + ka + q * 8, 16);
                    }
                    cp_commit();
                    s_pf = (s_pf == 2) ? 0 : s_pf + 1;
                }

                const uint32_t curA = sb + R_SM_A + (uint32_t)(s_cur * R_STAGE);
                const uint32_t curB = sb + R_SM_B + (uint32_t)(it * 16384);
                #pragma unroll
                for (int ks = 0; ks < 4; ks++) {
                    const int kbyte = ks * 32;
                    uint32_t ah[2][4], bh[2][4];
                    #pragma unroll
                    for (int mf = 0; mf < 2; mf++) {
                        const uint32_t ab = (uint32_t)SWZ128((a_row + mf * 16) * 128 + kbyte + a_kq);
                        LDSM_X4(ah[mf], curA + ab);
                    }
                    #pragma unroll
                    for (int p = 0; p < 2; p++) {
                        const uint32_t bb = (uint32_t)SWZ128((b_row + p * 16) * 128 + kbyte + b_kq);
                        LDSM_X4(bh[p], curB + bb);
                    }
                    #pragma unroll
                    for (int mf = 0; mf < 2; mf++) {
                        #pragma unroll
                        for (int p = 0; p < 2; p++) {
                            MMA16816(acc[mf][2 * p],     ah[mf], bh[p][0], bh[p][1]);
                            MMA16816(acc[mf][2 * p + 1], ah[mf], bh[p][2], bh[p][3]);
                        }
                    }
                }
                s_cur = (s_cur == 2) ? 0 : s_cur + 1;
            }
        } else {
            CP_WAIT(0);
            __syncthreads();
        }

        // ---- fused gate epilogue (all gates in-thread) ----
        #pragma unroll
        for (int mf = 0; mf < 2; mf++) {
            #pragma unroll
            for (int hf = 0; hf < 2; hf++) {
                const int rloc = warp_m * 32 + mf * 16 + g + 8 * hf;
                const char* xrow_s = smem + R_SM_XP + rloc * XP_PITCH
                                   + (warp_n * 32 + tg * 2) * 2;
                #pragma unroll
                for (int a = 0; a < 2; a++) {
                    __half2 xif = *(const __half2*)(xrow_s + (2 * a) * 16);
                    __half2 xgo = *(const __half2*)(xrow_s + (2 * a + 1) * 16);
                    float2 fif = __half22float2(xif);
                    float2 fgo = __half22float2(xgo);
                    float gi = acc[mf][2 * a][2 * hf]         + bs0[2 * a]     + fif.x;
                    float gf = acc[mf][2 * a][2 * hf + 1]     + bs1[2 * a]     + fif.y;
                    float gg = acc[mf][2 * a + 1][2 * hf]     + bs0[2 * a + 1] + fgo.x;
                    float go = acc[mf][2 * a + 1][2 * hf + 1] + bs1[2 * a + 1] + fgo.y;
                    float cc = siga(gf) * c_reg[mf][a][hf] + siga(gi) * tanha(gg);
                    c_reg[mf][a][hf] = cc;
                    float hv = siga(go) * tanha(cc);
                    hstage[rloc * 32 + jbase + a * 4] = __float2half(hv);
                }
            }
        }
        __syncthreads();

        // ---- coalesced h store from stage (512 threads, 16B each) ----
        {
            __half* hw = bufs[t & 1];
            const int row = tid >> 2;
            const int off = (tid & 3) * 8;
            const __half* sp = hstage + row * 32 + off;
            uint4 v0 = *(const uint4*)(sp);
            __half* dst = hw + (long)(m0 + row) * HID + ni * 32 + off;
            *(uint4*)dst = v0;
            if (t == MAXLEN - 1) {
                float* fd = hf32 + (long)(m0 + row) * HID + ni * 32 + off;
                #pragma unroll
                for (int k2 = 0; k2 < 8; k2++) fd[k2] = __half2float(sp[k2]);
            }
        }

        // ---- per-group barrier (release/acquire, tight poll) ----
        if (t < MAXLEN - 1) {
            __syncthreads();
            if (tid == 0) {
                unsigned* bar = &g_barg[mi];
                asm volatile("red.release.gpu.add.u32 [%0], %1;" :: "l"(bar), "r"(1u) : "memory");
                const unsigned target = 16u * (unsigned)(t + 1);
                unsigned v;
                do {
                    asm volatile("ld.acquire.gpu.u32 %0, [%1];" : "=r"(v) : "l"(bar) : "memory");
                } while (v < target);
            }
            __syncthreads();
        }
    }
}

// ===================== fp32 SGEMM (tail) ====================================
template<bool RELU, bool RESID, bool BIAS>
__global__ __launch_bounds__(256)
void sgemm_nt(const float* __restrict__ A, const float* __restrict__ W,
              const float* __restrict__ bias, const float* __restrict__ R,
              float* __restrict__ C, int M, int N, int K)
{
    constexpr int BM = 64, BN = 64, BK = 16;
    __shared__ float As[BK][BM];
    __shared__ float Bs[BK][BN];
    const int tid = threadIdx.x;
    const int brow = blockIdx.y * BM;
    const int bcol = blockIdx.x * BN;
    const int tr = (tid / 16) * 4;
    const int tc = (tid % 16) * 4;
    const int lr = tid / 4;
    const int lc = (tid % 4) * 4;
    float acc[4][4] = {};
    for (int k0 = 0; k0 < K; k0 += BK) {
        {
            int ar = brow + lr;
            float4 v = *reinterpret_cast<const float4*>(&A[(long)ar * K + k0 + lc]);
            As[lc + 0][lr] = v.x; As[lc + 1][lr] = v.y; As[lc + 2][lr] = v.z; As[lc + 3][lr] = v.w;
        }
        {
            int wr = bcol + lr;
            float4 v = *reinterpret_cast<const float4*>(&W[(long)wr * K + k0 + lc]);
            Bs[lc + 0][lr] = v.x; Bs[lc + 1][lr] = v.y; Bs[lc + 2][lr] = v.z; Bs[lc + 3][lr] = v.w;
        }
        __syncthreads();
        #pragma unroll
        for (int kk = 0; kk < BK; kk++) {
            float a[4], b[4];
            #pragma unroll
            for (int i = 0; i < 4; i++) a[i] = As[kk][tr + i];
            #pragma unroll
            for (int j = 0; j < 4; j++) b[j] = Bs[kk][tc + j];
            #pragma unroll
            for (int i = 0; i < 4; i++)
                #pragma unroll
                for (int j = 0; j < 4; j++)
                    acc[i][j] = fmaf(a[i], b[j], acc[i][j]);
        }
        __syncthreads();
    }
    #pragma unroll
    for (int i = 0; i < 4; i++) {
        int r = brow + tr + i;
        #pragma unroll
        for (int j = 0; j < 4; j++) {
            int cidx = bcol + tc + j;
            float v = acc[i][j];
            if (BIAS)  v += bias[cidx];
            if (RELU)  v = fmaxf(v, 0.f);
            if (RESID) v += R[(long)r * N + cidx];
            C[(long)r * N + cidx] = v;
        }
    }
}

// ===================== decoder ==============================================
__global__ __launch_bounds__(128)
void decoder_kernel(const float* __restrict__ X, const float* __restrict__ Wd,
                    const float* __restrict__ bd, float* __restrict__ out)
{
    const int b = blockIdx.x;
    const int t = threadIdx.x;
    float s = 0.f;
    #pragma unroll
    for (int j = t; j < HID; j += 128) s += X[(long)b * HID + j] * Wd[j];
    s += __shfl_down_sync(0xffffffffu, s, 16);
    s += __shfl_down_sync(0xffffffffu, s, 8);
    s += __shfl_down_sync(0xffffffffu, s, 4);
    s += __shfl_down_sync(0xffffffffu, s, 2);
    s += __shfl_down_sync(0xffffffffu, s, 1);
    __shared__ float sh[4];
    if ((t & 31) == 0) sh[t >> 5] = s;
    __syncthreads();
    if (t == 0) out[b] = sh[0] + sh[1] + sh[2] + sh[3] + bd[0];
}

// ===================== host launcher ========================================
extern "C" void kernel_launch(void* const* d_in, const int* in_sizes, int n_in,
                              void* d_out, int out_size)
{
    const int*   sizes = (const int*)  d_in[0];
    const float* feat  = (const float*)d_in[1];
    const float* We0   = (const float*)d_in[2];
    const float* be0   = (const float*)d_in[3];
    const float* We1   = (const float*)d_in[4];
    const float* be1   = (const float*)d_in[5];
    const float* Wih   = (const float*)d_in[6];
    const float* bih   = (const float*)d_in[7];
    const float* Whh   = (const float*)d_in[8];
    const float* bhh   = (const float*)d_in[9];
    const float* Wl0   = (const float*)d_in[10];
    const float* bl0   = (const float*)d_in[11];
    const float* Wl1   = (const float*)d_in[12];
    const float* bl1   = (const float*)d_in[13];
    const float* Wd    = (const float*)d_in[14];
    const float* bd    = (const float*)d_in[15];
    float* out = (float*)d_out;

    const int T = in_sizes[1] / IN_DIM;
    const int mt = (T + 127) / 128;

    __half *fh, *x1, *x2, *xp, *we0, *we1, *wihp, *whhp, *hb0, *hb1;
    float *bsum, *hf32, *r0, *r1;
    int* starts;
    cudaGetSymbolAddress((void**)&fh, g_fh);
    cudaGetSymbolAddress((void**)&x1, g_x1);
    cudaGetSymbolAddress((void**)&x2, g_x2);
    cudaGetSymbolAddress((void**)&xp, g_xp);
    cudaGetSymbolAddress((void**)&we0, g_we0);
    cudaGetSymbolAddress((void**)&we1, g_we1);
    cudaGetSymbolAddress((void**)&wihp, g_wihp);
    cudaGetSymbolAddress((void**)&whhp, g_whhp);
    cudaGetSymbolAddress((void**)&bsum, g_bsum);
    {
        __half* hb;
        cudaGetSymbolAddress((void**)&hb, g_hbuf);
        hb0 = hb;
        hb1 = hb + (long)BATCH * HID;
    }
    cudaGetSymbolAddress((void**)&hf32, g_hf32);
    cudaGetSymbolAddress((void**)&r0, g_r0);
    cudaGetSymbolAddress((void**)&r1, g_r1);
    cudaGetSymbolAddress((void**)&starts, g_starts);

    cudaFuncSetAttribute(mm2<1>, cudaFuncAttributeMaxDynamicSharedMemorySize, P_SMEM);
    cudaFuncSetAttribute(mm2<2>, cudaFuncAttributeMaxDynamicSharedMemorySize, P_SMEM);
    cudaFuncSetAttribute(lstm_persist, cudaFuncAttributeMaxDynamicSharedMemorySize, R_SMEM);

    scan_starts_kernel<<<1, BATCH>>>(sizes, starts);
    prep_bsum_kernel<<<(G4H + 255) / 256, 256>>>(bih, bhh, bsum);

    // converts (fp16)
    {
        long n;
        n = (long)T * KP0;
        cvt_kernel<<<(int)((n + 255) / 256), 256>>>(feat, fh, T, IN_DIM, KP0);
        n = (long)HID * KP0;
        cvt_kernel<<<(int)((n + 255) / 256), 256>>>(We0, we0, HID, IN_DIM, KP0);
        n = (long)HID * HID;
        cvt_kernel<<<(int)((n + 255) / 256), 256>>>(We1, we1, HID, HID, HID);
        n = (long)G4H * HID;
        cvt_wperm_kernel<<<(int)((n + 255) / 256), 256>>>(Wih, wihp);
        cvt_wperm_kernel<<<(int)((n + 255) / 256), 256>>>(Whh, whhp);
    }

    // encoder MLP + input projection (gate-permuted)
    mm2<1><<<dim3(HID / 128, mt), 256, P_SMEM>>>(fh, we0, be0, x1, T, HID, KP0);
    mm2<1><<<dim3(HID / 128, mt), 256, P_SMEM>>>(x1, we1, be1, x2, T, HID, HID);
    mm2<2><<<dim3(G4H / 128, mt), 256, P_SMEM>>>(x2, wihp, nullptr, xp, T, G4H, HID);

    // persistent fused recurrence (512 threads, 16 warps)
    lstm_persist<<<RCTAS, 512, R_SMEM>>>(xp, sizes, starts, bsum, whhp, hb0, hb1, hf32);

    // tail
    sgemm_nt<true, true, true><<<dim3(HID / 64, BATCH / 64), 256>>>(hf32, Wl0, bl0, hf32, r0, BATCH, HID, HID);
    sgemm_nt<true, true, true><<<dim3(HID / 64, BATCH / 64), 256>>>(r0,   Wl1, bl1, r0,   r1, BATCH, HID, HID);
    decoder_kernel<<<BATCH, 128>>>(r1, Wd, bd, out);

    (void)n_in; (void)out_size;
}

// round 10
// speedup vs baseline: 8.3750x; 1.0069x over previous
#include <cuda_runtime.h>
#include <cuda_fp16.h>
#include <math.h>
#include <stdint.h>

#define IN_DIM 164
#define KP0    192
#define HID    512
#define G4H    2048
#define BATCH  1024
#define MAXLEN 128
#define MAXT   (BATCH * (MAXLEN - 1))
#define RCTAS  128

// Gate permutation (fragment-aligned): permuted row n holds original row
// g*512 + U with  s=n>>6, a=(n>>4)&3, b2=(n>>3)&1, tg=(n>>1)&3, b=n&1,
// U = s*16 + a*4 + tg,  g = b2*2 + b.

// ===================== scratch (static device globals) ======================
__device__ __half g_fh[(long)MAXT * KP0];
__device__ __half g_x1[(long)MAXT * HID];
__device__ __half g_x2[(long)MAXT * HID];
__device__ __half g_xp[(long)MAXT * G4H];            // gate-permuted, fp16
__device__ __half g_we0[HID * KP0];
__device__ __half g_we1[HID * HID];
__device__ __half g_wihp[G4H * HID];                 // row-permuted
__device__ __half g_whhp[G4H * HID];                 // row-permuted
__device__ float  g_bsum[G4H];                       // bih+bhh, permuted
__device__ __half g_hbuf[2][BATCH * HID];
__device__ float  g_hf32[BATCH * HID];
__device__ float  g_r0[BATCH * HID];
__device__ float  g_r1[BATCH * HID];
__device__ int    g_starts[BATCH];

// per-mi-group barriers, padded to 128B so each group's counter sits in its
// own L2 line (avoids same-line atomic serialization across all 128 CTAs)
struct BarPad { unsigned v; unsigned pad[31]; };
__device__ BarPad g_barg[8];

// ===================== PTX helpers ==========================================
__device__ __forceinline__ uint32_t smem_u32(const void* p) {
    uint32_t a;
    asm("{ .reg .u64 t; cvta.to.shared.u64 t, %1; cvt.u32.u64 %0, t; }" : "=r"(a) : "l"(p));
    return a;
}
__device__ __forceinline__ void cp16(uint32_t dst, const void* src, int sz) {
    asm volatile("cp.async.cg.shared.global [%0], [%1], 16, %2;"
                 :: "r"(dst), "l"(src), "r"(sz));
}
__device__ __forceinline__ void cp_commit() {
    asm volatile("cp.async.commit_group;" ::: "memory");
}
#define CP_WAIT(n) asm volatile("cp.async.wait_group %0;" :: "n"(n) : "memory")

#define LDSM_X4(r, addr) \
    asm volatile("ldmatrix.sync.aligned.m8n8.x4.shared.b16 {%0,%1,%2,%3}, [%4];" \
        : "=r"((r)[0]), "=r"((r)[1]), "=r"((r)[2]), "=r"((r)[3]) : "r"(addr))

#define MMA16816(d, a, b0, b1) \
    asm volatile("mma.sync.aligned.m16n8k16.row.col.f32.f16.f16.f32 " \
        "{%0,%1,%2,%3}, {%4,%5,%6,%7}, {%8,%9}, {%0,%1,%2,%3};" \
        : "+f"((d)[0]), "+f"((d)[1]), "+f"((d)[2]), "+f"((d)[3]) \
        : "r"((a)[0]), "r"((a)[1]), "r"((a)[2]), "r"((a)[3]), "r"(b0), "r"(b1))

#define SWZ128(b) ((b) ^ (((b) >> 3) & 0x70))

// hardware tanh (MUFU.TANH) + sigmoid via tanh
__device__ __forceinline__ float tanha(float x) {
    float y;
    asm("tanh.approx.f32 %0, %1;" : "=f"(y) : "f"(x));
    return y;
}
__device__ __forceinline__ float siga(float x) {
    return fmaf(0.5f, tanha(0.5f * x), 0.5f);
}

// ===================== setup kernels ========================================
__global__ void scan_starts_kernel(const int* __restrict__ sizes, int* __restrict__ starts) {
    __shared__ int s[BATCH];
    int t = threadIdx.x;
    s[t] = sizes[t];
    __syncthreads();
    for (int off = 1; off < BATCH; off <<= 1) {
        int v = (t >= off) ? s[t - off] : 0;
        __syncthreads();
        s[t] += v;
        __syncthreads();
    }
    starts[t] = s[t] - sizes[t];
    if (t < 8) g_barg[t].v = 0u;
}

__device__ __forceinline__ int perm_orig_row(int n) {
    int s  = n >> 6;
    int a  = (n >> 4) & 3;
    int b2 = (n >> 3) & 1;
    int tg = (n >> 1) & 3;
    int b  = n & 1;
    int U  = s * 16 + a * 4 + tg;
    int gg = b2 * 2 + b;
    return gg * 512 + U;
}

__global__ void prep_bsum_kernel(const float* __restrict__ bih, const float* __restrict__ bhh,
                                 float* __restrict__ bsum) {
    int n = blockIdx.x * blockDim.x + threadIdx.x;
    if (n < G4H) {
        int orig = perm_orig_row(n);
        bsum[n] = bih[orig] + bhh[orig];
    }
}

__global__ void cvt_kernel(const float* __restrict__ X, __half* __restrict__ out,
                           int M, int K, int Kp) {
    long i = (long)blockIdx.x * blockDim.x + threadIdx.x;
    if (i >= (long)M * Kp) return;
    int r = (int)(i / Kp), cidx = (int)(i % Kp);
    float v = (cidx < K) ? X[(long)r * K + cidx] : 0.f;
    out[i] = __float2half(v);
}

// both 2048x512 weights, gate-permuted, in one launch
__global__ void cvt_wperm2_kernel(const float* __restrict__ Wih, const float* __restrict__ Whh,
                                  __half* __restrict__ oih, __half* __restrict__ ohh) {
    const long tot = (long)G4H * HID;
    long i = (long)blockIdx.x * blockDim.x + threadIdx.x;
    if (i >= 2 * tot) return;
    const float* W = (i < tot) ? Wih : Whh;
    __half* o      = (i < tot) ? oih : ohh;
    long j = (i < tot) ? i : i - tot;
    int n = (int)(j >> 9), k = (int)(j & 511);
    int orig = perm_orig_row(n);
    o[j] = __float2half(W[(long)orig * HID + k]);
}

// ===================== fp16 tensor GEMM (parallel section) ==================
#define P_OFF_A  0
#define P_OFF_B  16384
#define P_STAGE  32768
#define P_SMEM   (2 * P_STAGE)

template<int EPI>
__global__ __launch_bounds__(256, 2)
void mm2(const __half* __restrict__ A, const __half* __restrict__ B,
         const float* __restrict__ bias, __half* __restrict__ C,
         int M, int N, int K)
{
    extern __shared__ char smem[];
    const uint32_t sb = smem_u32(smem);
    const int tid  = threadIdx.x;
    const int wid  = tid >> 5;
    const int lane = tid & 31;
    const int warp_m = wid & 3;
    const int warp_n = wid >> 2;

    const int m0 = blockIdx.y * 128;
    const int n0 = blockIdx.x * 128;
    const int nk = K >> 6;

    const int lrow = tid >> 1;
    const int qb = (tid & 1) * 4;
    const int arow = m0 + lrow;
    const int asz = (arow < M) ? 16 : 0;
    const long abase = (long)((arow < M) ? arow : (M - 1)) * K;
    const long bbase = (long)(n0 + lrow) * K;

    uint32_t sw_dst[4];
    #pragma unroll
    for (int i = 0; i < 4; i++)
        sw_dst[i] = (uint32_t)SWZ128(lrow * 128 + (qb + i) * 16);

    {
        #pragma unroll
        for (int i = 0; i < 4; i++) {
            const int q = qb + i;
            const uint32_t d = sb + sw_dst[i];
            cp16(d + P_OFF_A, A + abase + q * 8, asz);
            cp16(d + P_OFF_B, B + bbase + q * 8, 16);
        }
        cp_commit();
    }

    float acc[2][8][4];
    #pragma unroll
    for (int a = 0; a < 2; a++)
        #pragma unroll
        for (int b = 0; b < 8; b++)
            #pragma unroll
            for (int v = 0; v < 4; v++) acc[a][b][v] = 0.f;

    const int a_row = warp_m * 32 + (lane & 15);
    const int a_kq  = (lane >> 4) * 16;
    const int b_row = warp_n * 64 + (lane & 7) + ((lane >> 4) << 3);
    const int b_kq  = ((lane >> 3) & 1) * 16;

    for (int it = 0; it < nk; ++it) {
        const uint32_t cur = sb + (uint32_t)((it & 1) * P_STAGE);
        if (it + 1 < nk) {
            const uint32_t nxt = sb + (uint32_t)(((it + 1) & 1) * P_STAGE);
            const long ka = abase + (long)(it + 1) * 64;
            const long kb = bbase + (long)(it + 1) * 64;
            #pragma unroll
            for (int i = 0; i < 4; i++) {
                const int q = qb + i;
                const uint32_t d = nxt + sw_dst[i];
                cp16(d + P_OFF_A, A + ka + q * 8, asz);
                cp16(d + P_OFF_B, B + kb + q * 8, 16);
            }
            cp_commit();
            CP_WAIT(1);
        } else {
            CP_WAIT(0);
        }
        __syncthreads();

        #pragma unroll
        for (int ks = 0; ks < 4; ks++) {
            const int kbyte = ks * 32;
            uint32_t ah[2][4], bh[4][4];
            #pragma unroll
            for (int mf = 0; mf < 2; mf++) {
                const uint32_t ab = (uint32_t)SWZ128((a_row + mf * 16) * 128 + kbyte + a_kq);
                LDSM_X4(ah[mf], cur + P_OFF_A + ab);
            }
            #pragma unroll
            for (int p = 0; p < 4; p++) {
                const uint32_t bb = (uint32_t)SWZ128((b_row + p * 16) * 128 + kbyte + b_kq);
                LDSM_X4(bh[p], cur + P_OFF_B + bb);
            }
            #pragma unroll
            for (int mf = 0; mf < 2; mf++) {
                #pragma unroll
                for (int p = 0; p < 4; p++) {
                    MMA16816(acc[mf][2 * p],     ah[mf], bh[p][0], bh[p][1]);
                    MMA16816(acc[mf][2 * p + 1], ah[mf], bh[p][2], bh[p][3]);
                }
            }
        }
        __syncthreads();
    }

    const int g  = lane >> 2;
    const int tg = lane & 3;
    #pragma unroll
    for (int mf = 0; mf < 2; mf++) {
        const int r_base = m0 + warp_m * 32 + mf * 16 + g;
        #pragma unroll
        for (int ng = 0; ng < 8; ng++) {
            const int col = n0 + warp_n * 64 + ng * 8 + tg * 2;
            float b0 = 0.f, b1 = 0.f;
            if (EPI == 1) { b0 = bias[col]; b1 = bias[col + 1]; }
            #pragma unroll
            for (int half_i = 0; half_i < 2; half_i++) {
                const int r = r_base + half_i * 8;
                if (r >= M) continue;
                float v0 = acc[mf][ng][2 * half_i]     + b0;
                float v1 = acc[mf][ng][2 * half_i + 1] + b1;
                if (EPI == 1) { v0 = fmaxf(v0, 0.f); v1 = fmaxf(v1, 0.f); }
                __half2 h2 = __floats2half2_rn(v0, v1);
                *(uint32_t*)(C + (long)r * N + col) = *(uint32_t*)&h2;
            }
        }
    }
}

// ===================== persistent fused LSTM recurrence =====================
// 128 CTAs x 512 threads (16 warps, warp tile 32x32): mi=bid/16, ni=bid%16.
// Whh slice resident in smem; 3-stage A pipeline; xp for step t+1 prefetched
// BEFORE the step-t barrier (overlaps DRAM latency with barrier wait);
// MUFU.TANH gates; padded per-mi-group barrier.
#define R_SM_B   0
#define R_SM_A   131072
#define R_STAGE  16384
#define R_SM_XP  (R_SM_A + 3 * R_STAGE)      // 180224
#define XP_PITCH 272
#define R_SM_H   (R_SM_XP + 128 * XP_PITCH)  // 215040
#define R_SMEM   (R_SM_H + 8192)             // 223232

__global__ __launch_bounds__(512, 1)
void lstm_persist(const __half* __restrict__ xp,
                  const int* __restrict__ sizes, const int* __restrict__ starts,
                  const float* __restrict__ bsum,
                  const __half* __restrict__ Whh,
                  __half* __restrict__ hbuf0, __half* __restrict__ hbuf1,
                  float* __restrict__ hf32)
{
    extern __shared__ char smem[];
    const uint32_t sb = smem_u32(smem);
    const int tid  = threadIdx.x;
    const int wid  = tid >> 5;
    const int lane = tid & 31;
    const int warp_m = wid & 3;      // 4 warps along M (32 rows)
    const int warp_n = wid >> 2;     // 4 warps along N (32 cols)
    const int mi = blockIdx.x >> 4;
    const int ni = blockIdx.x & 15;
    const int m0 = mi * 128;
    const int n0 = ni * 128;

    // loaders: 512 threads, thread -> row tid/4, 2 chunks of 16B
    const int lrow = tid >> 2;
    const int qb = (tid & 3) * 2;
    const long abase = (long)(m0 + lrow) * HID;
    const long bbase = (long)(n0 + lrow) * HID;

    uint32_t sw_dst[2];
    #pragma unroll
    for (int i = 0; i < 2; i++)
        sw_dst[i] = (uint32_t)SWZ128(lrow * 128 + (qb + i) * 16);

    // ---- preload resident Whh slice ----
    #pragma unroll
    for (int it = 0; it < 8; it++) {
        #pragma unroll
        for (int i = 0; i < 2; i++) {
            const int q = qb + i;
            cp16(sb + R_SM_B + it * 16384 + sw_dst[i], Whh + bbase + it * 64 + q * 8, 16);
        }
    }
    cp_commit();

    const int a_row = warp_m * 32 + (lane & 15);
    const int a_kq  = (lane >> 4) * 16;
    const int b_row = warp_n * 32 + (lane & 7) + ((lane >> 4) << 3);
    const int b_kq  = ((lane >> 3) & 1) * 16;

    const int g  = lane >> 2;
    const int tg = lane & 3;
    const int col_base = n0 + warp_n * 32 + tg * 2;

    // xp prefetch mapping: thread row tid/4, 4 chunks of 16B at (tid&3)*64
    const int st_row = starts[m0 + (tid >> 2)];
    const int sz_row = sizes[m0 + (tid >> 2)];
    const uint32_t xdst = sb + R_SM_XP + (uint32_t)((tid >> 2) * XP_PITCH + (tid & 3) * 64);

    float bs0[4], bs1[4];
    #pragma unroll
    for (int ng = 0; ng < 4; ng++) {
        bs0[ng] = bsum[col_base + ng * 8];
        bs1[ng] = bsum[col_base + ng * 8 + 1];
    }

    float c_reg[2][2][2];   // [mf][a][hf]
    #pragma unroll
    for (int mf = 0; mf < 2; mf++)
        #pragma unroll
        for (int a = 0; a < 2; a++)
            #pragma unroll
            for (int hf = 0; hf < 2; hf++) c_reg[mf][a][hf] = 0.f;

    __half* bufs[2] = { hbuf0, hbuf1 };
    __half* hstage = (__half*)(smem + R_SM_H);
    const int jbase = (warp_n >> 1) * 16 + (warp_n & 1) * 8 + tg;

    // ---- xp prefetch for step 0 ----
    {
        const int xsz = (0 < sz_row) ? 16 : 0;
        const __half* xg = xp + ((long)(st_row + 0) * G4H + n0 + (tid & 3) * 32);
        #pragma unroll
        for (int q = 0; q < 4; q++)
            cp16(xdst + q * 16, xg + q * 8, xsz);
        cp_commit();
    }

    for (int t = 0; t < MAXLEN; t++) {
        float acc[2][4][4];
        #pragma unroll
        for (int a = 0; a < 2; a++)
            #pragma unroll
            for (int b = 0; b < 4; b++)
                #pragma unroll
                for (int v = 0; v < 4; v++) acc[a][b][v] = 0.f;

        if (t > 0) {
            const __half* hr = bufs[(t + 1) & 1];
            #pragma unroll
            for (int c = 0; c < 2; c++) {
                const long ka = abase + (long)c * 64;
                #pragma unroll
                for (int i = 0; i < 2; i++) {
                    const int q = qb + i;
                    cp16(sb + R_SM_A + (uint32_t)(c * R_STAGE) + sw_dst[i], hr + ka + q * 8, 16);
                }
                cp_commit();
            }

            int s_cur = 0, s_pf = 2;
            for (int it = 0; it < 8; ++it) {
                if (it < 7) { CP_WAIT(1); } else { CP_WAIT(0); }
                __syncthreads();
                if (it + 2 < 8) {
                    const long ka = abase + (long)(it + 2) * 64;
                    const uint32_t dstb = sb + R_SM_A + (uint32_t)(s_pf * R_STAGE);
                    #pragma unroll
                    for (int i = 0; i < 2; i++) {
                        const int q = qb + i;
                        cp16(dstb + sw_dst[i], hr + ka + q * 8, 16);
                    }
                    cp_commit();
                    s_pf = (s_pf == 2) ? 0 : s_pf + 1;
                }

                const uint32_t curA = sb + R_SM_A + (uint32_t)(s_cur * R_STAGE);
                const uint32_t curB = sb + R_SM_B + (uint32_t)(it * 16384);
                #pragma unroll
                for (int ks = 0; ks < 4; ks++) {
                    const int kbyte = ks * 32;
                    uint32_t ah[2][4], bh[2][4];
                    #pragma unroll
                    for (int mf = 0; mf < 2; mf++) {
                        const uint32_t ab = (uint32_t)SWZ128((a_row + mf * 16) * 128 + kbyte + a_kq);
                        LDSM_X4(ah[mf], curA + ab);
                    }
                    #pragma unroll
                    for (int p = 0; p < 2; p++) {
                        const uint32_t bb = (uint32_t)SWZ128((b_row + p * 16) * 128 + kbyte + b_kq);
                        LDSM_X4(bh[p], curB + bb);
                    }
                    #pragma unroll
                    for (int mf = 0; mf < 2; mf++) {
                        #pragma unroll
                        for (int p = 0; p < 2; p++) {
                            MMA16816(acc[mf][2 * p],     ah[mf], bh[p][0], bh[p][1]);
                            MMA16816(acc[mf][2 * p + 1], ah[mf], bh[p][2], bh[p][3]);
                        }
                    }
                }
                s_cur = (s_cur == 2) ? 0 : s_cur + 1;
            }
        } else {
            CP_WAIT(0);     // drain Whh preload + xp(0)
            __syncthreads();
        }

        // ---- fused gate epilogue (all gates in-thread) ----
        #pragma unroll
        for (int mf = 0; mf < 2; mf++) {
            #pragma unroll
            for (int hf = 0; hf < 2; hf++) {
                const int rloc = warp_m * 32 + mf * 16 + g + 8 * hf;
                const char* xrow_s = smem + R_SM_XP + rloc * XP_PITCH
                                   + (warp_n * 32 + tg * 2) * 2;
                #pragma unroll
                for (int a = 0; a < 2; a++) {
                    __half2 xif = *(const __half2*)(xrow_s + (2 * a) * 16);
                    __half2 xgo = *(const __half2*)(xrow_s + (2 * a + 1) * 16);
                    float2 fif = __half22float2(xif);
                    float2 fgo = __half22float2(xgo);
                    float gi = acc[mf][2 * a][2 * hf]         + bs0[2 * a]     + fif.x;
                    float gf = acc[mf][2 * a][2 * hf + 1]     + bs1[2 * a]     + fif.y;
                    float gg = acc[mf][2 * a + 1][2 * hf]     + bs0[2 * a + 1] + fgo.x;
                    float go = acc[mf][2 * a + 1][2 * hf + 1] + bs1[2 * a + 1] + fgo.y;
                    float cc = siga(gf) * c_reg[mf][a][hf] + siga(gi) * tanha(gg);
                    c_reg[mf][a][hf] = cc;
                    float hv = siga(go) * tanha(cc);
                    hstage[rloc * 32 + jbase + a * 4] = __float2half(hv);
                }
            }
        }
        __syncthreads();   // hstage ready; xp(t) fully consumed

        // ---- xp prefetch for NEXT step (overlaps with store + barrier) ----
        if (t < MAXLEN - 1) {
            const int tn = t + 1;
            const int xsz = (tn < sz_row) ? 16 : 0;
            const __half* xg = xp + ((long)(st_row + tn) * G4H + n0 + (tid & 3) * 32);
            #pragma unroll
            for (int q = 0; q < 4; q++)
                cp16(xdst + q * 16, xg + q * 8, xsz);
            cp_commit();
        }

        // ---- coalesced h store from stage (512 threads, 16B each) ----
        {
            __half* hw = bufs[t & 1];
            const int row = tid >> 2;
            const int off = (tid & 3) * 8;
            const __half* sp = hstage + row * 32 + off;
            uint4 v0 = *(const uint4*)(sp);
            __half* dst = hw + (long)(m0 + row) * HID + ni * 32 + off;
            *(uint4*)dst = v0;
            if (t == MAXLEN - 1) {
                float* fd = hf32 + (long)(m0 + row) * HID + ni * 32 + off;
                #pragma unroll
                for (int k2 = 0; k2 < 8; k2++) fd[k2] = __half2float(sp[k2]);
            }
        }

        // ---- per-group barrier (padded line; release/acquire, tight poll) ----
        if (t < MAXLEN - 1) {
            __syncthreads();
            if (tid == 0) {
                unsigned* bar = &g_barg[mi].v;
                asm volatile("red.release.gpu.add.u32 [%0], %1;" :: "l"(bar), "r"(1u) : "memory");
                const unsigned target = 16u * (unsigned)(t + 1);
                unsigned v;
                do {
                    asm volatile("ld.acquire.gpu.u32 %0, [%1];" : "=r"(v) : "l"(bar) : "memory");
                } while (v < target);
            }
            __syncthreads();
        }
    }
}

// ===================== fp32 SGEMM (tail) ====================================
template<bool RELU, bool RESID, bool BIAS>
__global__ __launch_bounds__(256)
void sgemm_nt(const float* __restrict__ A, const float* __restrict__ W,
              const float* __restrict__ bias, const float* __restrict__ R,
              float* __restrict__ C, int M, int N, int K)
{
    constexpr int BM = 64, BN = 64, BK = 16;
    __shared__ float As[BK][BM];
    __shared__ float Bs[BK][BN];
    const int tid = threadIdx.x;
    const int brow = blockIdx.y * BM;
    const int bcol = blockIdx.x * BN;
    const int tr = (tid / 16) * 4;
    const int tc = (tid % 16) * 4;
    const int lr = tid / 4;
    const int lc = (tid % 4) * 4;
    float acc[4][4] = {};
    for (int k0 = 0; k0 < K; k0 += BK) {
        {
            int ar = brow + lr;
            float4 v = *reinterpret_cast<const float4*>(&A[(long)ar * K + k0 + lc]);
            As[lc + 0][lr] = v.x; As[lc + 1][lr] = v.y; As[lc + 2][lr] = v.z; As[lc + 3][lr] = v.w;
        }
        {
            int wr = bcol + lr;
            float4 v = *reinterpret_cast<const float4*>(&W[(long)wr * K + k0 + lc]);
            Bs[lc + 0][lr] = v.x; Bs[lc + 1][lr] = v.y; Bs[lc + 2][lr] = v.z; Bs[lc + 3][lr] = v.w;
        }
        __syncthreads();
        #pragma unroll
        for (int kk = 0; kk < BK; kk++) {
            float a[4], b[4];
            #pragma unroll
            for (int i = 0; i < 4; i++) a[i] = As[kk][tr + i];
            #pragma unroll
            for (int j = 0; j < 4; j++) b[j] = Bs[kk][tc + j];
            #pragma unroll
            for (int i = 0; i < 4; i++)
                #pragma unroll
                for (int j = 0; j < 4; j++)
                    acc[i][j] = fmaf(a[i], b[j], acc[i][j]);
        }
        __syncthreads();
    }
    #pragma unroll
    for (int i = 0; i < 4; i++) {
        int r = brow + tr + i;
        #pragma unroll
        for (int j = 0; j < 4; j++) {
            int cidx = bcol + tc + j;
            float v = acc[i][j];
            if (BIAS)  v += bias[cidx];
            if (RELU)  v = fmaxf(v, 0.f);
            if (RESID) v += R[(long)r * N + cidx];
            C[(long)r * N + cidx] = v;
        }
    }
}

// ===================== decoder ==============================================
__global__ __launch_bounds__(128)
void decoder_kernel(const float* __restrict__ X, const float* __restrict__ Wd,
                    const float* __restrict__ bd, float* __restrict__ out)
{
    const int b = blockIdx.x;
    const int t = threadIdx.x;
    float s = 0.f;
    #pragma unroll
    for (int j = t; j < HID; j += 128) s += X[(long)b * HID + j] * Wd[j];
    s += __shfl_down_sync(0xffffffffu, s, 16);
    s += __shfl_down_sync(0xffffffffu, s, 8);
    s += __shfl_down_sync(0xffffffffu, s, 4);
    s += __shfl_down_sync(0xffffffffu, s, 2);
    s += __shfl_down_sync(0xffffffffu, s, 1);
    __shared__ float sh[4];
    if ((t & 31) == 0) sh[t >> 5] = s;
    __syncthreads();
    if (t == 0) out[b] = sh[0] + sh[1] + sh[2] + sh[3] + bd[0];
}

// ===================== host launcher ========================================
extern "C" void kernel_launch(void* const* d_in, const int* in_sizes, int n_in,
                              void* d_out, int out_size)
{
    const int*   sizes = (const int*)  d_in[0];
    const float* feat  = (const float*)d_in[1];
    const float* We0   = (const float*)d_in[2];
    const float* be0   = (const float*)d_in[3];
    const float* We1   = (const float*)d_in[4];
    const float* be1   = (const float*)d_in[5];
    const float* Wih   = (const float*)d_in[6];
    const float* bih   = (const float*)d_in[7];
    const float* Whh   = (const float*)d_in[8];
    const float* bhh   = (const float*)d_in[9];
    const float* Wl0   = (const float*)d_in[10];
    const float* bl0   = (const float*)d_in[11];
    const float* Wl1   = (const float*)d_in[12];
    const float* bl1   = (const float*)d_in[13];
    const float* Wd    = (const float*)d_in[14];
    const float* bd    = (const float*)d_in[15];
    float* out = (float*)d_out;

    const int T = in_sizes[1] / IN_DIM;
    const int mt = (T + 127) / 128;

    __half *fh, *x1, *x2, *xp, *we0, *we1, *wihp, *whhp, *hb0, *hb1;
    float *bsum, *hf32, *r0, *r1;
    int* starts;
    cudaGetSymbolAddress((void**)&fh, g_fh);
    cudaGetSymbolAddress((void**)&x1, g_x1);
    cudaGetSymbolAddress((void**)&x2, g_x2);
    cudaGetSymbolAddress((void**)&xp, g_xp);
    cudaGetSymbolAddress((void**)&we0, g_we0);
    cudaGetSymbolAddress((void**)&we1, g_we1);
    cudaGetSymbolAddress((void**)&wihp, g_wihp);
    cudaGetSymbolAddress((void**)&whhp, g_whhp);
    cudaGetSymbolAddress((void**)&bsum, g_bsum);
    {
        __half* hb;
        cudaGetSymbolAddress((void**)&hb, g_hbuf);
        hb0 = hb;
        hb1 = hb + (long)BATCH * HID;
    }
    cudaGetSymbolAddress((void**)&hf32, g_hf32);
    cudaGetSymbolAddress((void**)&r0, g_r0);
    cudaGetSymbolAddress((void**)&r1, g_r1);
    cudaGetSymbolAddress((void**)&starts, g_starts);

    cudaFuncSetAttribute(mm2<1>, cudaFuncAttributeMaxDynamicSharedMemorySize, P_SMEM);
    cudaFuncSetAttribute(mm2<2>, cudaFuncAttributeMaxDynamicSharedMemorySize, P_SMEM);
    cudaFuncSetAttribute(lstm_persist, cudaFuncAttributeMaxDynamicSharedMemorySize, R_SMEM);

    scan_starts_kernel<<<1, BATCH>>>(sizes, starts);
    prep_bsum_kernel<<<(G4H + 255) / 256, 256>>>(bih, bhh, bsum);

    // converts (fp16)
    {
        long n;
        n = (long)T * KP0;
        cvt_kernel<<<(int)((n + 255) / 256), 256>>>(feat, fh, T, IN_DIM, KP0);
        n = (long)HID * KP0;
        cvt_kernel<<<(int)((n + 255) / 256), 256>>>(We0, we0, HID, IN_DIM, KP0);
        n = (long)HID * HID;
        cvt_kernel<<<(int)((n + 255) / 256), 256>>>(We1, we1, HID, HID, HID);
        n = 2L * G4H * HID;
        cvt_wperm2_kernel<<<(int)((n + 255) / 256), 256>>>(Wih, Whh, wihp, whhp);
    }

    // encoder MLP + input projection (gate-permuted)
    mm2<1><<<dim3(HID / 128, mt), 256, P_SMEM>>>(fh, we0, be0, x1, T, HID, KP0);
    mm2<1><<<dim3(HID / 128, mt), 256, P_SMEM>>>(x1, we1, be1, x2, T, HID, HID);
    mm2<2><<<dim3(G4H / 128, mt), 256, P_SMEM>>>(x2, wihp, nullptr, xp, T, G4H, HID);

    // persistent fused recurrence (512 threads, 16 warps)
    lstm_persist<<<RCTAS, 512, R_SMEM>>>(xp, sizes, starts, bsum, whhp, hb0, hb1, hf32);

    // tail
    sgemm_nt<true, true, true><<<dim3(HID / 64, BATCH / 64), 256>>>(hf32, Wl0, bl0, hf32, r0, BATCH, HID, HID);
    sgemm_nt<true, true, true><<<dim3(HID / 64, BATCH / 64), 256>>>(r0,   Wl1, bl1, r0,   r1, BATCH, HID, HID);
    decoder_kernel<<<BATCH, 128>>>(r1, Wd, bd, out);

    (void)n_in; (void)out_size;
}